// round 6
// baseline (speedup 1.0000x reference)
#include <cuda_runtime.h>
#include <cuda_fp16.h>
#include <cstdint>

#define BATCH 2
#define SEQ   2048
#define CH    768
#define HEADS 12
#define HDIM  64
#define ATT_SCALE 0.125f    // HDIM^-0.5
#define OA_SCALE 4096.0f    // folded into attn fp16 scaling
#define OA_INV   (1.0f / 4096.0f)

// ---------------- scratch (static device arrays; no cudaMalloc) -------------
__device__ float g_xpart[BATCH * 64 * CH];
__device__ float g_xmean[BATCH * CH];
__device__ float g_u[BATCH * HEADS * CH];
__device__ float g_z[BATCH * HEADS * SEQ];
__device__ float g_attn[BATCH * HEADS * SEQ];   // softmax / SEQ (fp32)

__device__ __half g_xhi[BATCH * SEQ * CH];
__device__ __half g_xlo[BATCH * SEQ * CH];
__device__ __half g_wvhi[CH * CH];
__device__ __half g_wphi[CH * CH];
__device__ __half g_vhi[BATCH * SEQ * CH];      // V hi (from V-proj epilogue)
__device__ __half g_oahi[BATCH * SEQ * CH];     // oa * OA_SCALE hi/lo
__device__ __half g_oalo[BATCH * SEQ * CH];

// ---------------- fp32 -> fp16 hi/lo split (for x) ---------------------------
__global__ void split_kernel(const float* __restrict__ src,
                             __half* __restrict__ hi, __half* __restrict__ lo,
                             int n4) {
    int i = blockIdx.x * 256 + threadIdx.x;
    if (i >= n4) return;
    float4 v = ((const float4*)src)[i];
    __half hx = __float2half_rn(v.x), hy = __float2half_rn(v.y);
    __half hz = __float2half_rn(v.z), hw = __float2half_rn(v.w);
    __half lx = __float2half_rn(v.x - __half2float(hx));
    __half ly = __float2half_rn(v.y - __half2float(hy));
    __half lz = __float2half_rn(v.z - __half2float(hz));
    __half lw = __float2half_rn(v.w - __half2float(hw));
    ((__half2*)hi)[i * 2]     = __halves2half2(hx, hy);
    ((__half2*)hi)[i * 2 + 1] = __halves2half2(hz, hw);
    ((__half2*)lo)[i * 2]     = __halves2half2(lx, ly);
    ((__half2*)lo)[i * 2 + 1] = __halves2half2(lz, lw);
}

// ---------------- fp32 -> fp16 hi only (for weights) -------------------------
__global__ void hi_kernel(const float* __restrict__ src,
                          __half* __restrict__ hi, int n4) {
    int i = blockIdx.x * 256 + threadIdx.x;
    if (i >= n4) return;
    float4 v = ((const float4*)src)[i];
    ((__half2*)hi)[i * 2]     = __halves2half2(__float2half_rn(v.x), __float2half_rn(v.y));
    ((__half2*)hi)[i * 2 + 1] = __halves2half2(__float2half_rn(v.z), __float2half_rn(v.w));
}

// ---------------- 1a: partial sums of x over n (64 chunks of 32 rows) -------
__global__ void xpart_kernel(const float* __restrict__ x) {
    int b = blockIdx.y;
    int chunk = blockIdx.x;
    const float* xb = x + ((size_t)b * SEQ + (size_t)chunk * 32) * CH;
    for (int c = threadIdx.x; c < CH; c += 256) {
        float s = 0.f;
        #pragma unroll 8
        for (int n = 0; n < 32; n++) s += xb[(size_t)n * CH + c];
        g_xpart[(b * 64 + chunk) * CH + c] = s;
    }
}

// ---------------- 1b: reduce partials -> mean -------------------------------
__global__ void xmean_kernel() {
    int b = blockIdx.x;
    int c = threadIdx.x;
    float s = 0.f;
    #pragma unroll
    for (int k = 0; k < 64; k++) s += g_xpart[(b * 64 + k) * CH + c];
    g_xmean[b * CH + c] = s * (1.0f / SEQ);
}

// ---------------- 2: u[b,h,c] = SCALE * sum_d Wq[h*64+d,c] * K_avg[b,h,d] ---
__global__ void u_kernel(const float* __restrict__ Wq, const float* __restrict__ Wk) {
    int b = blockIdx.x / HEADS;
    int h = blockIdx.x % HEADS;
    __shared__ float xm[CH];
    __shared__ float kavg[HDIM];
    for (int c = threadIdx.x; c < CH; c += 256) xm[c] = g_xmean[b * CH + c];
    __syncthreads();
    if (threadIdx.x < HDIM) {
        const float* wk = Wk + (size_t)(h * HDIM + threadIdx.x) * CH;
        float s = 0.f;
        #pragma unroll 8
        for (int c = 0; c < CH; c++) s += xm[c] * wk[c];
        kavg[threadIdx.x] = s;
    }
    __syncthreads();
    for (int c = threadIdx.x; c < CH; c += 256) {
        float s = 0.f;
        #pragma unroll 8
        for (int d = 0; d < HDIM; d++)
            s += Wq[(size_t)(h * HDIM + d) * CH + c] * kavg[d];
        g_u[(b * HEADS + h) * CH + c] = s * ATT_SCALE;
    }
}

// ---------------- 3: z[b,h,n] = x[b,n,:] . u[b,h,:] --------------------------
__global__ void z_kernel(const float* __restrict__ x) {
    int bn = blockIdx.x;
    int b = bn / SEQ;
    int n = bn % SEQ;
    __shared__ float xs[CH];
    const float* xr = x + (size_t)bn * CH;
    for (int c = threadIdx.x; c < CH; c += 384) xs[c] = xr[c];
    __syncthreads();
    int w = threadIdx.x >> 5;
    int lane = threadIdx.x & 31;
    const float* u = g_u + (size_t)(b * HEADS + w) * CH;
    float s = 0.f;
    #pragma unroll
    for (int c = lane; c < CH; c += 32) s += xs[c] * u[c];
    #pragma unroll
    for (int off = 16; off > 0; off >>= 1)
        s += __shfl_down_sync(0xffffffffu, s, off);
    if (lane == 0) g_z[(b * HEADS + w) * SEQ + n] = s;
}

// ---------------- 4: softmax over n per (b,h), fold 1/SEQ --------------------
__global__ void softmax_kernel() {
    __shared__ float red[256];
    int base = blockIdx.x * SEQ;
    int tid = threadIdx.x;
    float v[8];
    float m = -1e30f;
    #pragma unroll
    for (int k = 0; k < 8; k++) {
        v[k] = g_z[base + tid + k * 256];
        m = fmaxf(m, v[k]);
    }
    red[tid] = m; __syncthreads();
    for (int s = 128; s > 0; s >>= 1) {
        if (tid < s) red[tid] = fmaxf(red[tid], red[tid + s]);
        __syncthreads();
    }
    m = red[0]; __syncthreads();
    float sum = 0.f;
    #pragma unroll
    for (int k = 0; k < 8; k++) { v[k] = __expf(v[k] - m); sum += v[k]; }
    red[tid] = sum; __syncthreads();
    for (int s = 128; s > 0; s >>= 1) {
        if (tid < s) red[tid] += red[tid + s];
        __syncthreads();
    }
    float inv = 1.0f / (red[0] * (float)SEQ);
    #pragma unroll
    for (int k = 0; k < 8; k++) g_attn[base + tid + k * 256] = v[k] * inv;
}

// ================= warp-MMA building blocks ==================================
__device__ __forceinline__ void mma16816(float* c, const uint32_t* a, const uint32_t* b) {
    asm volatile(
        "mma.sync.aligned.m16n8k16.row.col.f32.f16.f16.f32 "
        "{%0,%1,%2,%3}, {%4,%5,%6,%7}, {%8,%9}, {%0,%1,%2,%3};\n"
        : "+f"(c[0]), "+f"(c[1]), "+f"(c[2]), "+f"(c[3])
        : "r"(a[0]), "r"(a[1]), "r"(a[2]), "r"(a[3]), "r"(b[0]), "r"(b[1]));
}

__device__ __forceinline__ uint32_t smem_u32(const void* p) {
    uint32_t a;
    asm("{ .reg .u64 t; cvta.to.shared.u64 t, %1; cvt.u32.u64 %0, t; }"
        : "=r"(a) : "l"(p));
    return a;
}

__device__ __forceinline__ void ldmatrix_x4_trans(uint32_t* r, uint32_t addr) {
    asm volatile(
        "ldmatrix.sync.aligned.m8n8.x4.trans.shared.b16 {%0,%1,%2,%3}, [%4];"
        : "=r"(r[0]), "=r"(r[1]), "=r"(r[2]), "=r"(r[3]) : "r"(addr));
}

// ================= warp-MMA 2-product GEMM ===================================
// out = (Ahi+Alo)[M,768] @ (Bhi[768,768])^T, fp32 accum. 2 MMAs share B frag.
// MODE 1: fp32 out + bias (* outscale). MODE 2: fp16 hi out only.
template <int MODE>
__global__ void __launch_bounds__(256) gemm_mma_kernel(
    const __half* __restrict__ Ahi, const __half* __restrict__ Alo,
    const __half* __restrict__ Bhi,
    const float* __restrict__ bias, float* __restrict__ out,
    __half* __restrict__ outhi, float outscale)
{
    __shared__ uint32_t sAhi[128 * 20], sAlo[128 * 20];
    __shared__ uint32_t sBhi[128 * 20];

    int tid = threadIdx.x;
    int m0 = blockIdx.y * 128;
    int n0 = blockIdx.x * 128;
    int w = tid >> 5, lane = tid & 31;
    int wm = w >> 2, wn = w & 3;
    int g = lane >> 2, tig = lane & 3;

    float acc[4][4][4];
    #pragma unroll
    for (int mt = 0; mt < 4; mt++)
        #pragma unroll
        for (int nt = 0; nt < 4; nt++)
            #pragma unroll
            for (int r = 0; r < 4; r++) acc[mt][nt][r] = 0.f;

    int lrow = tid >> 1;
    int hs = tid & 1;
    size_t goffA = (size_t)(m0 + lrow) * CH + hs * 16;
    size_t goffB = (size_t)(n0 + lrow) * CH + hs * 16;
    int soff = lrow * 20 + hs * 8;

    const int NSTAGE = CH / 32;   // 24
    uint4 pa0, pa1, pb0, pb1, pc0, pc1;
    pa0 = *(const uint4*)(Ahi + goffA);  pa1 = *(const uint4*)(Ahi + goffA + 8);
    pb0 = *(const uint4*)(Alo + goffA);  pb1 = *(const uint4*)(Alo + goffA + 8);
    pc0 = *(const uint4*)(Bhi + goffB);  pc1 = *(const uint4*)(Bhi + goffB + 8);

    for (int s = 0; s < NSTAGE; s++) {
        *(uint4*)(sAhi + soff) = pa0;  *(uint4*)(sAhi + soff + 4) = pa1;
        *(uint4*)(sAlo + soff) = pb0;  *(uint4*)(sAlo + soff + 4) = pb1;
        *(uint4*)(sBhi + soff) = pc0;  *(uint4*)(sBhi + soff + 4) = pc1;
        __syncthreads();

        if (s + 1 < NSTAGE) {
            size_t ga = goffA + (size_t)(s + 1) * 32;
            size_t gb = goffB + (size_t)(s + 1) * 32;
            pa0 = *(const uint4*)(Ahi + ga);  pa1 = *(const uint4*)(Ahi + ga + 8);
            pb0 = *(const uint4*)(Alo + ga);  pb1 = *(const uint4*)(Alo + ga + 8);
            pc0 = *(const uint4*)(Bhi + gb);  pc1 = *(const uint4*)(Bhi + gb + 8);
        }

        #pragma unroll
        for (int kk = 0; kk < 2; kk++) {
            uint32_t bh[4][2];
            #pragma unroll
            for (int nt = 0; nt < 4; nt++) {
                int bi = (wn * 32 + nt * 8 + g) * 20 + kk * 8 + tig;
                bh[nt][0] = sBhi[bi];
                bh[nt][1] = sBhi[bi + 4];
            }
            #pragma unroll
            for (int mt = 0; mt < 4; mt++) {
                int ai = (wm * 64 + mt * 16 + g) * 20 + kk * 8 + tig;
                uint32_t ah[4], al[4];
                ah[0] = sAhi[ai];         ah[1] = sAhi[ai + 160];
                ah[2] = sAhi[ai + 4];     ah[3] = sAhi[ai + 164];
                al[0] = sAlo[ai];         al[1] = sAlo[ai + 160];
                al[2] = sAlo[ai + 4];     al[3] = sAlo[ai + 164];
                #pragma unroll
                for (int nt = 0; nt < 4; nt++) {
                    mma16816(acc[mt][nt], ah, bh[nt]);
                    mma16816(acc[mt][nt], al, bh[nt]);
                }
            }
        }
        __syncthreads();
    }

    #pragma unroll
    for (int mt = 0; mt < 4; mt++) {
        int r = m0 + wm * 64 + mt * 16 + g;
        #pragma unroll
        for (int nt = 0; nt < 4; nt++) {
            int c = n0 + wn * 32 + nt * 8 + tig * 2;
            if (MODE == 1) {
                float2 v0, v1;
                v0.x = acc[mt][nt][0] * outscale + bias[c];
                v0.y = acc[mt][nt][1] * outscale + bias[c + 1];
                v1.x = acc[mt][nt][2] * outscale + bias[c];
                v1.y = acc[mt][nt][3] * outscale + bias[c + 1];
                *(float2*)(out + (size_t)r * CH + c)       = v0;
                *(float2*)(out + (size_t)(r + 8) * CH + c) = v1;
            } else {
                #pragma unroll
                for (int hr = 0; hr < 2; hr++) {
                    __half hx = __float2half_rn(acc[mt][nt][hr * 2]);
                    __half hy = __float2half_rn(acc[mt][nt][hr * 2 + 1]);
                    size_t idx = (size_t)(r + hr * 8) * CH + c;
                    *(__half2*)(outhi + idx) = __halves2half2(hx, hy);
                }
            }
        }
    }
}

// ================= circulant attention on tensor cores =======================
// oa[b,i,c] = sum_j attn2[(j-i) mod N] * Vhi[j,c],  attn2 = attn/N * OA_SCALE
// attn kept hi/lo (A-side split, 2 MMAs/frag); V hi only (B-side).
// dyn smem (halves): A2hi @0, A2hiS @4096, A2lo @8192, A2loS @12288,
// V tiles @16384: buf*4608, tile = 64 rows x 72 halves.
#define CIRC_SMEM_BYTES ((16384 + 2 * 4608) * 2)

__global__ void __launch_bounds__(256) circ_mma_kernel() {
    extern __shared__ __half dsm[];
    __half* A2hi  = dsm;
    __half* A2hiS = dsm + 4096;
    __half* A2lo  = dsm + 8192;
    __half* A2loS = dsm + 12288;
    __half* Vbase = dsm + 16384;

    int tid = threadIdx.x;
    int i0 = blockIdx.x * 128;
    int h  = blockIdx.y;
    int b  = blockIdx.z;
    int c0 = h * HDIM;
    int w = tid >> 5, lane = tid & 31;
    int wm = w >> 2, wn = w & 3;
    int g = lane >> 2, tig = lane & 3;

    const float* arow = g_attn + (size_t)(b * HEADS + h) * SEQ;
    for (int t = tid; t < SEQ; t += 256) {
        float a = arow[t] * OA_SCALE;
        __half hi = __float2half_rn(a);
        __half lo = __float2half_rn(a - __half2float(hi));
        A2hi[t] = hi;  A2hi[t + SEQ] = hi;
        A2lo[t] = lo;  A2lo[t + SEQ] = lo;
    }
    __syncthreads();
    for (int t = tid; t < 2 * SEQ - 1; t += 256) {
        A2hiS[t] = A2hi[t + 1];
        A2loS[t] = A2lo[t + 1];
    }
    if (tid == 0) { A2hiS[2 * SEQ - 1] = __float2half_rn(0.f); A2loS[2 * SEQ - 1] = __float2half_rn(0.f); }

    int ob = SEQ + 2 * tig - (i0 + wm * 64 + g);
    int par = ob & 1;
    const uint32_t* PhiBase = (const uint32_t*)(par ? A2hiS : A2hi) + ((ob - par) >> 1);
    const uint32_t* PloBase = (const uint32_t*)(par ? A2loS : A2lo) + ((ob - par) >> 1);

    int vrow = tid >> 3, vcg = tid & 7;
    const __half* gvh = g_vhi + ((size_t)b * SEQ + vrow) * CH + c0 + vcg * 8;
    int svo_a = vrow * 72 + vcg * 8;
    int svo_b = (vrow + 32) * 72 + vcg * 8;

    int mrow = ((lane >> 3) & 1) * 8 + (lane & 7);
    int ncol = wn * 16 + (lane >> 4) * 8;
    uint32_t svAddrPart = (uint32_t)(mrow * 144 + ncol * 2);
    uint32_t sVu32 = smem_u32(Vbase);

    float acc[4][2][4];
    #pragma unroll
    for (int mt = 0; mt < 4; mt++)
        #pragma unroll
        for (int nt = 0; nt < 2; nt++)
            #pragma unroll
            for (int r = 0; r < 4; r++) acc[mt][nt][r] = 0.f;

    uint4 pfh0 = *(const uint4*)gvh;
    uint4 pfh1 = *(const uint4*)(gvh + 32 * CH);

    __syncthreads();

    const int NCHUNK = SEQ / 64;   // 32
    for (int c = 0; c < NCHUNK; c++) {
        int buf = c & 1;
        __half* sVhi = Vbase + buf * 4608;
        *(uint4*)(sVhi + svo_a) = pfh0;
        *(uint4*)(sVhi + svo_b) = pfh1;
        __syncthreads();

        if (c + 1 < NCHUNK) {
            size_t adv = (size_t)(c + 1) * 64 * CH;
            pfh0 = *(const uint4*)(gvh + adv);
            pfh1 = *(const uint4*)(gvh + adv + 32 * CH);
        }

        const uint32_t* Phi = PhiBase + 32 * c;
        const uint32_t* Plo = PloBase + 32 * c;
        uint32_t ehi[7], elo[7], fhi[8], flo[8];
        #pragma unroll
        for (int t = 0; t < 7; t++) { ehi[t] = Phi[8 * t - 24]; elo[t] = Plo[8 * t - 24]; }
        #pragma unroll
        for (int t = 0; t < 8; t++) { fhi[t] = Phi[8 * t - 28]; flo[t] = Plo[8 * t - 28]; }

        uint32_t sVhiAddr = sVu32 + (uint32_t)buf * 9216u + svAddrPart;

        #pragma unroll
        for (int kk = 0; kk < 4; kk++) {
            uint32_t bh[4];
            ldmatrix_x4_trans(bh, sVhiAddr + kk * 2304u);
            #pragma unroll
            for (int mt = 0; mt < 4; mt++) {
                int d3 = kk - mt + 3;
                uint32_t ah[4] = {ehi[d3], fhi[d3], fhi[d3 + 1], ehi[d3]};
                uint32_t al[4] = {elo[d3], flo[d3], flo[d3 + 1], elo[d3]};
                mma16816(acc[mt][0], ah, bh);
                mma16816(acc[mt][0], al, bh);
                uint32_t bh1[2] = {bh[2], bh[3]};
                mma16816(acc[mt][1], ah, bh1);
                mma16816(acc[mt][1], al, bh1);
            }
        }
        __syncthreads();
    }

    #pragma unroll
    for (int mt = 0; mt < 4; mt++) {
        int r = i0 + wm * 64 + mt * 16 + g;
        #pragma unroll
        for (int nt = 0; nt < 2; nt++) {
            int cc = c0 + wn * 16 + nt * 8 + tig * 2;
            #pragma unroll
            for (int hr = 0; hr < 2; hr++) {
                float vx = acc[mt][nt][hr * 2];
                float vy = acc[mt][nt][hr * 2 + 1];
                __half hx = __float2half_rn(vx);
                __half hy = __float2half_rn(vy);
                __half lx = __float2half_rn(vx - __half2float(hx));
                __half ly = __float2half_rn(vy - __half2float(hy));
                size_t idx = (size_t)(b * SEQ + r + hr * 8) * CH + cc;
                *(__half2*)(g_oahi + idx) = __halves2half2(hx, hy);
                *(__half2*)(g_oalo + idx) = __halves2half2(lx, ly);
            }
        }
    }
}

// ---------------- launch ------------------------------------------------------
extern "C" void kernel_launch(void* const* d_in, const int* in_sizes, int n_in,
                              void* d_out, int out_size) {
    const float* x  = (const float*)d_in[0];
    const float* Wq = (const float*)d_in[1];
    const float* Wk = (const float*)d_in[2];
    const float* Wv = (const float*)d_in[3];
    const float* Wp = (const float*)d_in[4];
    const float* bp = (const float*)d_in[5];
    float* out = (float*)d_out;

    __half* dxhi; cudaGetSymbolAddress((void**)&dxhi,  g_xhi);
    __half* dxlo; cudaGetSymbolAddress((void**)&dxlo,  g_xlo);
    __half* dvhi; cudaGetSymbolAddress((void**)&dvhi,  g_wvhi);
    __half* dphi; cudaGetSymbolAddress((void**)&dphi,  g_wphi);
    __half* dVhi; cudaGetSymbolAddress((void**)&dVhi,  g_vhi);
    __half* dohi; cudaGetSymbolAddress((void**)&dohi,  g_oahi);
    __half* dolo; cudaGetSymbolAddress((void**)&dolo,  g_oalo);

    cudaFuncSetAttribute(circ_mma_kernel,
                         cudaFuncAttributeMaxDynamicSharedMemorySize, CIRC_SMEM_BYTES);

    // 0) fp16 splits: x (hi/lo), Wv/Wp (hi only)
    {
        int n4x = BATCH * SEQ * CH / 4;
        int n4w = CH * CH / 4;
        split_kernel<<<(n4x + 255) / 256, 256>>>(x,  dxhi, dxlo, n4x);
        hi_kernel<<<(n4w + 255) / 256, 256>>>(Wv, dvhi, n4w);
        hi_kernel<<<(n4w + 255) / 256, 256>>>(Wp, dphi, n4w);
    }
    // 1) x mean over n
    xpart_kernel<<<dim3(64, BATCH), 256>>>(x);
    xmean_kernel<<<BATCH, CH>>>();
    // 2) u = SCALE * Wq(head-block)^T @ K_avg
    u_kernel<<<BATCH * HEADS, 256>>>(Wq, Wk);
    // 3) z = x . u
    z_kernel<<<BATCH * SEQ, 384>>>(x);
    // 4) softmax (+ 1/N fold)
    softmax_kernel<<<BATCH * HEADS, 256>>>();
    // 5) V = x @ Wv^T  (2-product warp MMA -> fp16 hi out)
    gemm_mma_kernel<2><<<dim3(CH / 128, (BATCH * SEQ) / 128), 256>>>(
        dxhi, dxlo, dvhi, nullptr, nullptr, dVhi, 1.0f);
    // 6) circulant attention (tensor cores) -> oa hi/lo (scaled)
    circ_mma_kernel<<<dim3(SEQ / 128, HEADS, BATCH), 256, CIRC_SMEM_BYTES>>>();
    // 7) out = oa @ Wp^T + bp (2-product warp MMA, unscale)
    gemm_mma_kernel<1><<<dim3(CH / 128, (BATCH * SEQ) / 128), 256>>>(
        dohi, dolo, dphi, bp, out, nullptr, OA_INV);
}

// round 7
// speedup vs baseline: 1.2856x; 1.2856x over previous
#include <cuda_runtime.h>
#include <cuda_fp16.h>
#include <cstdint>

#define BATCH 2
#define SEQ   2048
#define CH    768
#define HEADS 12
#define HDIM  64
#define ATT_SCALE 0.125f    // HDIM^-0.5
#define OA_SCALE 4096.0f
#define OA_INV   (1.0f / 4096.0f)

// ---------------- scratch (static device arrays; no cudaMalloc) -------------
__device__ float g_xpart[BATCH * 128 * CH];
__device__ float g_xmean[BATCH * CH];
__device__ float g_u[BATCH * HEADS * CH];
__device__ float g_z[BATCH * HEADS * SEQ];
__device__ float g_attn[BATCH * HEADS * SEQ];

__device__ __half g_xhi[BATCH * SEQ * CH];
__device__ __half g_xlo[BATCH * SEQ * CH];
__device__ __half g_wvhi[CH * CH];
__device__ __half g_wvlo[CH * CH];
__device__ __half g_wphi[CH * CH];
__device__ __half g_wplo[CH * CH];
__device__ __half g_vhi[BATCH * SEQ * CH];
__device__ __half g_vlo[BATCH * SEQ * CH];
__device__ __half g_oahi[BATCH * SEQ * CH];
__device__ __half g_oalo[BATCH * SEQ * CH];

// ---------------- fp32 -> fp16 hi/lo split ----------------------------------
__global__ void split_kernel(const float* __restrict__ src,
                             __half* __restrict__ hi, __half* __restrict__ lo,
                             int n4) {
    int i = blockIdx.x * 256 + threadIdx.x;
    if (i >= n4) return;
    float4 v = ((const float4*)src)[i];
    __half hx = __float2half_rn(v.x), hy = __float2half_rn(v.y);
    __half hz = __float2half_rn(v.z), hw = __float2half_rn(v.w);
    __half lx = __float2half_rn(v.x - __half2float(hx));
    __half ly = __float2half_rn(v.y - __half2float(hy));
    __half lz = __float2half_rn(v.z - __half2float(hz));
    __half lw = __float2half_rn(v.w - __half2float(hw));
    ((__half2*)hi)[i * 2]     = __halves2half2(hx, hy);
    ((__half2*)hi)[i * 2 + 1] = __halves2half2(hz, hw);
    ((__half2*)lo)[i * 2]     = __halves2half2(lx, ly);
    ((__half2*)lo)[i * 2 + 1] = __halves2half2(lz, lw);
}

// ---------------- 1a: partial sums of x over n (128 chunks of 16 rows) ------
__global__ void xpart_kernel(const float* __restrict__ x) {
    int b = blockIdx.y;
    int chunk = blockIdx.x;
    const float* xb = x + ((size_t)b * SEQ + (size_t)chunk * 16) * CH;
    for (int c = threadIdx.x; c < CH; c += 256) {
        float s = 0.f;
        #pragma unroll
        for (int n = 0; n < 16; n++) s += xb[(size_t)n * CH + c];
        g_xpart[(b * 128 + chunk) * CH + c] = s;
    }
}

// ---------------- 1b: reduce partials -> mean -------------------------------
__global__ void xmean_kernel() {
    int b = blockIdx.x;
    int c = threadIdx.x;
    float s = 0.f;
    #pragma unroll 16
    for (int k = 0; k < 128; k++) s += g_xpart[(b * 128 + k) * CH + c];
    g_xmean[b * CH + c] = s * (1.0f / SEQ);
}

// ---------------- 2: u[b,h,c] = SCALE * sum_d Wq[h*64+d,c] * K_avg[b,h,d] ---
__global__ void u_kernel(const float* __restrict__ Wq, const float* __restrict__ Wk) {
    int b = blockIdx.x / HEADS;
    int h = blockIdx.x % HEADS;
    __shared__ float xm[CH];
    __shared__ float kavg[HDIM];
    for (int c = threadIdx.x; c < CH; c += 256) xm[c] = g_xmean[b * CH + c];
    __syncthreads();
    if (threadIdx.x < HDIM) {
        const float* wk = Wk + (size_t)(h * HDIM + threadIdx.x) * CH;
        float s = 0.f;
        #pragma unroll 8
        for (int c = 0; c < CH; c++) s += xm[c] * wk[c];
        kavg[threadIdx.x] = s;
    }
    __syncthreads();
    for (int c = threadIdx.x; c < CH; c += 256) {
        float s = 0.f;
        #pragma unroll 8
        for (int d = 0; d < HDIM; d++)
            s += Wq[(size_t)(h * HDIM + d) * CH + c] * kavg[d];
        g_u[(b * HEADS + h) * CH + c] = s * ATT_SCALE;
    }
}

// ---------------- 3: z[b,h,n] = x[b,n,:] . u[b,h,:] --------------------------
__global__ void z_kernel(const float* __restrict__ x) {
    int bn = blockIdx.x;
    int b = bn / SEQ;
    int n = bn % SEQ;
    __shared__ float xs[CH];
    const float* xr = x + (size_t)bn * CH;
    for (int c = threadIdx.x; c < CH; c += 384) xs[c] = xr[c];
    __syncthreads();
    int w = threadIdx.x >> 5;
    int lane = threadIdx.x & 31;
    const float* u = g_u + (size_t)(b * HEADS + w) * CH;
    float s = 0.f;
    #pragma unroll
    for (int c = lane; c < CH; c += 32) s += xs[c] * u[c];
    #pragma unroll
    for (int off = 16; off > 0; off >>= 1)
        s += __shfl_down_sync(0xffffffffu, s, off);
    if (lane == 0) g_z[(b * HEADS + w) * SEQ + n] = s;
}

// ---------------- 4: softmax over n per (b,h), fold 1/SEQ --------------------
__global__ void softmax_kernel() {
    __shared__ float red[256];
    int base = blockIdx.x * SEQ;
    int tid = threadIdx.x;
    float v[8];
    float m = -1e30f;
    #pragma unroll
    for (int k = 0; k < 8; k++) {
        v[k] = g_z[base + tid + k * 256];
        m = fmaxf(m, v[k]);
    }
    red[tid] = m; __syncthreads();
    for (int s = 128; s > 0; s >>= 1) {
        if (tid < s) red[tid] = fmaxf(red[tid], red[tid + s]);
        __syncthreads();
    }
    m = red[0]; __syncthreads();
    float sum = 0.f;
    #pragma unroll
    for (int k = 0; k < 8; k++) { v[k] = __expf(v[k] - m); sum += v[k]; }
    red[tid] = sum; __syncthreads();
    for (int s = 128; s > 0; s >>= 1) {
        if (tid < s) red[tid] += red[tid + s];
        __syncthreads();
    }
    float inv = 1.0f / (red[0] * (float)SEQ);
    #pragma unroll
    for (int k = 0; k < 8; k++) g_attn[base + tid + k * 256] = v[k] * inv;
}

// ================= warp-MMA building blocks ==================================
__device__ __forceinline__ void mma16816(float* c, const uint32_t* a, const uint32_t* b) {
    asm volatile(
        "mma.sync.aligned.m16n8k16.row.col.f32.f16.f16.f32 "
        "{%0,%1,%2,%3}, {%4,%5,%6,%7}, {%8,%9}, {%0,%1,%2,%3};\n"
        : "+f"(c[0]), "+f"(c[1]), "+f"(c[2]), "+f"(c[3])
        : "r"(a[0]), "r"(a[1]), "r"(a[2]), "r"(a[3]), "r"(b[0]), "r"(b[1]));
}

__device__ __forceinline__ uint32_t smem_u32(const void* p) {
    uint32_t a;
    asm("{ .reg .u64 t; cvta.to.shared.u64 t, %1; cvt.u32.u64 %0, t; }"
        : "=r"(a) : "l"(p));
    return a;
}

__device__ __forceinline__ void ldmatrix_x4(uint32_t* r, uint32_t addr) {
    asm volatile(
        "ldmatrix.sync.aligned.m8n8.x4.shared.b16 {%0,%1,%2,%3}, [%4];"
        : "=r"(r[0]), "=r"(r[1]), "=r"(r[2]), "=r"(r[3]) : "r"(addr));
}

__device__ __forceinline__ void ldmatrix_x4_trans(uint32_t* r, uint32_t addr) {
    asm volatile(
        "ldmatrix.sync.aligned.m8n8.x4.trans.shared.b16 {%0,%1,%2,%3}, [%4];"
        : "=r"(r[0]), "=r"(r[1]), "=r"(r[2]), "=r"(r[3]) : "r"(addr));
}

// ================= warp-MMA fp16-split GEMM (ldmatrix fragments) =============
// out = (Ahi+Alo)[M,768] @ ((Bhi+Blo)[768,768])^T, fp32 accum, 3 products.
// MODE 1: fp32 out + bias (* outscale). MODE 2: fp16 hi/lo out.
// smem rows: 128 x 20 u32 (80B pad). A frags: ldmatrix.x4 (m16k16 block),
// B frags: ldmatrix.x4 covers two n8 blocks x k16.
template <int MODE>
__global__ void __launch_bounds__(256) gemm_mma_kernel(
    const __half* __restrict__ Ahi, const __half* __restrict__ Alo,
    const __half* __restrict__ Bhi, const __half* __restrict__ Blo,
    const float* __restrict__ bias, float* __restrict__ out,
    __half* __restrict__ outhi, __half* __restrict__ outlo, float outscale)
{
    __shared__ uint32_t sAhi[128 * 20], sAlo[128 * 20];
    __shared__ uint32_t sBhi[128 * 20], sBlo[128 * 20];

    int tid = threadIdx.x;
    int m0 = blockIdx.y * 128;
    int n0 = blockIdx.x * 128;
    int w = tid >> 5, lane = tid & 31;
    int wm = w >> 2, wn = w & 3;
    int g = lane >> 2, tig = lane & 3;

    float acc[4][4][4];
    #pragma unroll
    for (int mt = 0; mt < 4; mt++)
        #pragma unroll
        for (int nt = 0; nt < 4; nt++)
            #pragma unroll
            for (int r = 0; r < 4; r++) acc[mt][nt][r] = 0.f;

    int lrow = tid >> 1;
    int hs = tid & 1;
    size_t goffA = (size_t)(m0 + lrow) * CH + hs * 16;
    size_t goffB = (size_t)(n0 + lrow) * CH + hs * 16;
    int soff = lrow * 20 + hs * 8;

    // ldmatrix address bases (u32 units within row-padded arrays)
    int sub = lane >> 3, lr = lane & 7;
    // A: x4 blocks (m,k0),(m+8,k0),(m,k8),(m+8,k8)
    int aRow = wm * 64 + ((sub & 1) << 3) + lr;   // + mt*16
    int aKs  = sub >> 1;                           // k-section within k16
    uint32_t aOffBase = (uint32_t)((aRow * 20 + aKs * 4) << 2);
    // B: x4 blocks (n,k0),(n,k8),(n+8,k0),(n+8,k8)
    int bRow = wn * 32 + (((sub >> 1) & 1) << 3) + lr;   // + np*16
    int bKs  = sub & 1;
    uint32_t bOffBase = (uint32_t)((bRow * 20 + bKs * 4) << 2);

    uint32_t uAhi = smem_u32(sAhi), uAlo = smem_u32(sAlo);
    uint32_t uBhi = smem_u32(sBhi), uBlo = smem_u32(sBlo);

    const int NSTAGE = CH / 32;   // 24
    uint4 pa0, pa1, pb0, pb1, pc0, pc1, pd0, pd1;
    pa0 = *(const uint4*)(Ahi + goffA);  pa1 = *(const uint4*)(Ahi + goffA + 8);
    pb0 = *(const uint4*)(Alo + goffA);  pb1 = *(const uint4*)(Alo + goffA + 8);
    pc0 = *(const uint4*)(Bhi + goffB);  pc1 = *(const uint4*)(Bhi + goffB + 8);
    pd0 = *(const uint4*)(Blo + goffB);  pd1 = *(const uint4*)(Blo + goffB + 8);

    for (int s = 0; s < NSTAGE; s++) {
        *(uint4*)(sAhi + soff) = pa0;  *(uint4*)(sAhi + soff + 4) = pa1;
        *(uint4*)(sAlo + soff) = pb0;  *(uint4*)(sAlo + soff + 4) = pb1;
        *(uint4*)(sBhi + soff) = pc0;  *(uint4*)(sBhi + soff + 4) = pc1;
        *(uint4*)(sBlo + soff) = pd0;  *(uint4*)(sBlo + soff + 4) = pd1;
        __syncthreads();

        if (s + 1 < NSTAGE) {
            size_t ga = goffA + (size_t)(s + 1) * 32;
            size_t gb = goffB + (size_t)(s + 1) * 32;
            pa0 = *(const uint4*)(Ahi + ga);  pa1 = *(const uint4*)(Ahi + ga + 8);
            pb0 = *(const uint4*)(Alo + ga);  pb1 = *(const uint4*)(Alo + ga + 8);
            pc0 = *(const uint4*)(Bhi + gb);  pc1 = *(const uint4*)(Bhi + gb + 8);
            pd0 = *(const uint4*)(Blo + gb);  pd1 = *(const uint4*)(Blo + gb + 8);
        }

        #pragma unroll
        for (int kk = 0; kk < 2; kk++) {
            uint32_t kadd = (uint32_t)(kk * 8) << 2;
            // B fragments: two x4 loads per array cover nt = 0..3
            uint32_t bh[4][2], bl[4][2];
            #pragma unroll
            for (int np = 0; np < 2; np++) {
                uint32_t r4[4];
                uint32_t boff = bOffBase + kadd + (uint32_t)(np * 16 * 20) * 4u;
                ldmatrix_x4(r4, uBhi + boff);
                bh[np * 2][0] = r4[0];  bh[np * 2][1] = r4[1];
                bh[np * 2 + 1][0] = r4[2];  bh[np * 2 + 1][1] = r4[3];
                ldmatrix_x4(r4, uBlo + boff);
                bl[np * 2][0] = r4[0];  bl[np * 2][1] = r4[1];
                bl[np * 2 + 1][0] = r4[2];  bl[np * 2 + 1][1] = r4[3];
            }
            #pragma unroll
            for (int mt = 0; mt < 4; mt++) {
                uint32_t aoff = aOffBase + kadd + (uint32_t)(mt * 16 * 20) * 4u;
                uint32_t ah[4], al[4];
                ldmatrix_x4(ah, uAhi + aoff);
                ldmatrix_x4(al, uAlo + aoff);
                #pragma unroll
                for (int nt = 0; nt < 4; nt++) {
                    mma16816(acc[mt][nt], ah, bh[nt]);
                    mma16816(acc[mt][nt], ah, bl[nt]);
                    mma16816(acc[mt][nt], al, bh[nt]);
                }
            }
        }
        __syncthreads();
    }

    #pragma unroll
    for (int mt = 0; mt < 4; mt++) {
        int r = m0 + wm * 64 + mt * 16 + g;
        #pragma unroll
        for (int nt = 0; nt < 4; nt++) {
            int c = n0 + wn * 32 + nt * 8 + tig * 2;
            if (MODE == 1) {
                float2 v0, v1;
                v0.x = acc[mt][nt][0] * outscale + bias[c];
                v0.y = acc[mt][nt][1] * outscale + bias[c + 1];
                v1.x = acc[mt][nt][2] * outscale + bias[c];
                v1.y = acc[mt][nt][3] * outscale + bias[c + 1];
                *(float2*)(out + (size_t)r * CH + c)       = v0;
                *(float2*)(out + (size_t)(r + 8) * CH + c) = v1;
            } else {
                #pragma unroll
                for (int hr = 0; hr < 2; hr++) {
                    float vx = acc[mt][nt][hr * 2];
                    float vy = acc[mt][nt][hr * 2 + 1];
                    __half hx = __float2half_rn(vx);
                    __half hy = __float2half_rn(vy);
                    __half lx = __float2half_rn(vx - __half2float(hx));
                    __half ly = __float2half_rn(vy - __half2float(hy));
                    size_t idx = (size_t)(r + hr * 8) * CH + c;
                    *(__half2*)(outhi + idx) = __halves2half2(hx, hy);
                    *(__half2*)(outlo + idx) = __halves2half2(lx, ly);
                }
            }
        }
    }
}

// ================= circulant attention on tensor cores (R5 form) =============
#define CIRC_SMEM_BYTES ((16384 + 4 * 4608) * 2)

__global__ void __launch_bounds__(256) circ_mma_kernel() {
    extern __shared__ __half dsm[];
    __half* A2hi  = dsm;
    __half* A2hiS = dsm + 4096;
    __half* A2lo  = dsm + 8192;
    __half* A2loS = dsm + 12288;
    __half* Vbase = dsm + 16384;

    int tid = threadIdx.x;
    int i0 = blockIdx.x * 128;
    int h  = blockIdx.y;
    int b  = blockIdx.z;
    int c0 = h * HDIM;
    int w = tid >> 5, lane = tid & 31;
    int wm = w >> 2, wn = w & 3;
    int g = lane >> 2, tig = lane & 3;

    const float* arow = g_attn + (size_t)(b * HEADS + h) * SEQ;
    for (int t = tid; t < SEQ; t += 256) {
        float a = arow[t] * OA_SCALE;
        __half hi = __float2half_rn(a);
        __half lo = __float2half_rn(a - __half2float(hi));
        A2hi[t] = hi;  A2hi[t + SEQ] = hi;
        A2lo[t] = lo;  A2lo[t + SEQ] = lo;
    }
    __syncthreads();
    for (int t = tid; t < 2 * SEQ - 1; t += 256) {
        A2hiS[t] = A2hi[t + 1];
        A2loS[t] = A2lo[t + 1];
    }
    if (tid == 0) { A2hiS[2 * SEQ - 1] = __float2half_rn(0.f); A2loS[2 * SEQ - 1] = __float2half_rn(0.f); }

    int ob = SEQ + 2 * tig - (i0 + wm * 64 + g);
    int par = ob & 1;
    const uint32_t* PhiBase = (const uint32_t*)(par ? A2hiS : A2hi) + ((ob - par) >> 1);
    const uint32_t* PloBase = (const uint32_t*)(par ? A2loS : A2lo) + ((ob - par) >> 1);

    int vrow = tid >> 3, vcg = tid & 7;
    const __half* gvh = g_vhi + ((size_t)b * SEQ + vrow) * CH + c0 + vcg * 8;
    const __half* gvl = g_vlo + ((size_t)b * SEQ + vrow) * CH + c0 + vcg * 8;
    int svo_a = vrow * 72 + vcg * 8;
    int svo_b = (vrow + 32) * 72 + vcg * 8;

    int mrow = ((lane >> 3) & 1) * 8 + (lane & 7);
    int ncol = wn * 16 + (lane >> 4) * 8;
    uint32_t svAddrPart = (uint32_t)(mrow * 144 + ncol * 2);
    uint32_t sVu32 = smem_u32(Vbase);

    float acc[4][2][4];
    #pragma unroll
    for (int mt = 0; mt < 4; mt++)
        #pragma unroll
        for (int nt = 0; nt < 2; nt++)
            #pragma unroll
            for (int r = 0; r < 4; r++) acc[mt][nt][r] = 0.f;

    uint4 pfh0, pfh1, pfl0, pfl1;
    pfh0 = *(const uint4*)gvh;
    pfh1 = *(const uint4*)(gvh + 32 * CH);
    pfl0 = *(const uint4*)gvl;
    pfl1 = *(const uint4*)(gvl + 32 * CH);

    __syncthreads();

    const int NCHUNK = SEQ / 64;   // 32
    for (int c = 0; c < NCHUNK; c++) {
        int buf = c & 1;
        __half* sVhi = Vbase + (buf * 2 + 0) * 4608;
        __half* sVlo = Vbase + (buf * 2 + 1) * 4608;
        *(uint4*)(sVhi + svo_a) = pfh0;
        *(uint4*)(sVhi + svo_b) = pfh1;
        *(uint4*)(sVlo + svo_a) = pfl0;
        *(uint4*)(sVlo + svo_b) = pfl1;
        __syncthreads();

        if (c + 1 < NCHUNK) {
            size_t adv = (size_t)(c + 1) * 64 * CH;
            pfh0 = *(const uint4*)(gvh + adv);
            pfh1 = *(const uint4*)(gvh + adv + 32 * CH);
            pfl0 = *(const uint4*)(gvl + adv);
            pfl1 = *(const uint4*)(gvl + adv + 32 * CH);
        }

        const uint32_t* Phi = PhiBase + 32 * c;
        const uint32_t* Plo = PloBase + 32 * c;
        uint32_t ehi[7], elo[7], fhi[8], flo[8];
        #pragma unroll
        for (int t = 0; t < 7; t++) { ehi[t] = Phi[8 * t - 24]; elo[t] = Plo[8 * t - 24]; }
        #pragma unroll
        for (int t = 0; t < 8; t++) { fhi[t] = Phi[8 * t - 28]; flo[t] = Plo[8 * t - 28]; }

        uint32_t sVhiAddr = sVu32 + (uint32_t)(buf * 2 + 0) * 9216u + svAddrPart;
        uint32_t sVloAddr = sVu32 + (uint32_t)(buf * 2 + 1) * 9216u + svAddrPart;

        #pragma unroll
        for (int kk = 0; kk < 4; kk++) {
            uint32_t bh[4], bl[4];
            ldmatrix_x4_trans(bh, sVhiAddr + kk * 2304u);
            ldmatrix_x4_trans(bl, sVloAddr + kk * 2304u);
            #pragma unroll
            for (int mt = 0; mt < 4; mt++) {
                int d3 = kk - mt + 3;
                uint32_t ah[4] = {ehi[d3], fhi[d3], fhi[d3 + 1], ehi[d3]};
                uint32_t al[4] = {elo[d3], flo[d3], flo[d3 + 1], elo[d3]};
                mma16816(acc[mt][0], ah, bh);
                mma16816(acc[mt][0], ah, bl);
                mma16816(acc[mt][0], al, bh);
                uint32_t bh1[2] = {bh[2], bh[3]};
                uint32_t bl1[2] = {bl[2], bl[3]};
                mma16816(acc[mt][1], ah, bh1);
                mma16816(acc[mt][1], ah, bl1);
                mma16816(acc[mt][1], al, bh1);
            }
        }
        __syncthreads();
    }

    #pragma unroll
    for (int mt = 0; mt < 4; mt++) {
        int r = i0 + wm * 64 + mt * 16 + g;
        #pragma unroll
        for (int nt = 0; nt < 2; nt++) {
            int cc = c0 + wn * 16 + nt * 8 + tig * 2;
            #pragma unroll
            for (int hr = 0; hr < 2; hr++) {
                float vx = acc[mt][nt][hr * 2];
                float vy = acc[mt][nt][hr * 2 + 1];
                __half hx = __float2half_rn(vx);
                __half hy = __float2half_rn(vy);
                __half lx = __float2half_rn(vx - __half2float(hx));
                __half ly = __float2half_rn(vy - __half2float(hy));
                size_t idx = (size_t)(b * SEQ + r + hr * 8) * CH + cc;
                *(__half2*)(g_oahi + idx) = __halves2half2(hx, hy);
                *(__half2*)(g_oalo + idx) = __halves2half2(lx, ly);
            }
        }
    }
}

// ---------------- launch ------------------------------------------------------
extern "C" void kernel_launch(void* const* d_in, const int* in_sizes, int n_in,
                              void* d_out, int out_size) {
    const float* x  = (const float*)d_in[0];
    const float* Wq = (const float*)d_in[1];
    const float* Wk = (const float*)d_in[2];
    const float* Wv = (const float*)d_in[3];
    const float* Wp = (const float*)d_in[4];
    const float* bp = (const float*)d_in[5];
    float* out = (float*)d_out;

    __half* dxhi; cudaGetSymbolAddress((void**)&dxhi,  g_xhi);
    __half* dxlo; cudaGetSymbolAddress((void**)&dxlo,  g_xlo);
    __half* dvhi; cudaGetSymbolAddress((void**)&dvhi,  g_wvhi);
    __half* dvlo; cudaGetSymbolAddress((void**)&dvlo,  g_wvlo);
    __half* dphi; cudaGetSymbolAddress((void**)&dphi,  g_wphi);
    __half* dplo; cudaGetSymbolAddress((void**)&dplo,  g_wplo);
    __half* dVhi; cudaGetSymbolAddress((void**)&dVhi,  g_vhi);
    __half* dVlo; cudaGetSymbolAddress((void**)&dVlo,  g_vlo);
    __half* dohi; cudaGetSymbolAddress((void**)&dohi,  g_oahi);
    __half* dolo; cudaGetSymbolAddress((void**)&dolo,  g_oalo);

    cudaFuncSetAttribute(circ_mma_kernel,
                         cudaFuncAttributeMaxDynamicSharedMemorySize, CIRC_SMEM_BYTES);

    int n4x = BATCH * SEQ * CH / 4;
    int n4w = CH * CH / 4;
    // 1-3) splits (x, Wv, Wp)
    split_kernel<<<(n4x + 255) / 256, 256>>>(x,  dxhi, dxlo, n4x);
    split_kernel<<<(n4w + 255) / 256, 256>>>(Wv, dvhi, dvlo, n4w);
    split_kernel<<<(n4w + 255) / 256, 256>>>(Wp, dphi, dplo, n4w);
    // 4) V = x @ Wv^T  (4th launch -> ncu captures this one)
    gemm_mma_kernel<2><<<dim3(CH / 128, (BATCH * SEQ) / 128), 256>>>(
        dxhi, dxlo, dvhi, dvlo, nullptr, nullptr, dVhi, dVlo, 1.0f);
    // 5-6) x mean over n
    xpart_kernel<<<dim3(128, BATCH), 256>>>(x);
    xmean_kernel<<<BATCH, CH>>>();
    // 7) u = SCALE * Wq(head-block)^T @ K_avg
    u_kernel<<<BATCH * HEADS, 256>>>(Wq, Wk);
    // 8) z = x . u
    z_kernel<<<BATCH * SEQ, 384>>>(x);
    // 9) softmax (+ 1/N fold)
    softmax_kernel<<<BATCH * HEADS, 256>>>();
    // 10) circulant attention -> oa hi/lo (scaled)
    circ_mma_kernel<<<dim3(SEQ / 128, HEADS, BATCH), 256, CIRC_SMEM_BYTES>>>();
    // 11) out = oa @ Wp^T + bp
    gemm_mma_kernel<1><<<dim3(CH / 128, (BATCH * SEQ) / 128), 256>>>(
        dohi, dolo, dphi, dplo, bp, out, nullptr, nullptr, OA_INV);
}

// round 8
// speedup vs baseline: 1.3030x; 1.0135x over previous
#include <cuda_runtime.h>
#include <cuda_fp16.h>
#include <cstdint>

#define BATCH 2
#define SEQ   2048
#define CH    768
#define HEADS 12
#define HDIM  64
#define ATT_SCALE 0.125f    // HDIM^-0.5
#define OA_SCALE 4096.0f
#define OA_INV   (1.0f / 4096.0f)

// ---------------- scratch (static device arrays; no cudaMalloc) -------------
__device__ float g_xpart[BATCH * 128 * CH];
__device__ float g_xmean[BATCH * CH];
__device__ float g_u[BATCH * HEADS * CH];
__device__ float g_z[BATCH * HEADS * SEQ];
__device__ float g_attn[BATCH * HEADS * SEQ];

__device__ __half g_xhi[BATCH * SEQ * CH];
__device__ __half g_xlo[BATCH * SEQ * CH];
__device__ __half g_wvhi[CH * CH];
__device__ __half g_wvlo[CH * CH];
__device__ __half g_wphi[CH * CH];
__device__ __half g_wplo[CH * CH];
__device__ __half g_vhi[BATCH * SEQ * CH];
__device__ __half g_vlo[BATCH * SEQ * CH];
__device__ __half g_oahi[BATCH * SEQ * CH];
__device__ __half g_oalo[BATCH * SEQ * CH];

// ---------------- fp32 -> fp16 hi/lo split ----------------------------------
__global__ void split_kernel(const float* __restrict__ src,
                             __half* __restrict__ hi, __half* __restrict__ lo,
                             int n4) {
    int i = blockIdx.x * 256 + threadIdx.x;
    if (i >= n4) return;
    float4 v = ((const float4*)src)[i];
    __half hx = __float2half_rn(v.x), hy = __float2half_rn(v.y);
    __half hz = __float2half_rn(v.z), hw = __float2half_rn(v.w);
    __half lx = __float2half_rn(v.x - __half2float(hx));
    __half ly = __float2half_rn(v.y - __half2float(hy));
    __half lz = __float2half_rn(v.z - __half2float(hz));
    __half lw = __float2half_rn(v.w - __half2float(hw));
    ((__half2*)hi)[i * 2]     = __halves2half2(hx, hy);
    ((__half2*)hi)[i * 2 + 1] = __halves2half2(hz, hw);
    ((__half2*)lo)[i * 2]     = __halves2half2(lx, ly);
    ((__half2*)lo)[i * 2 + 1] = __halves2half2(lz, lw);
}

// ---------------- 1a: partial sums of x over n (128 chunks of 16 rows) ------
__global__ void xpart_kernel(const float* __restrict__ x) {
    int b = blockIdx.y;
    int chunk = blockIdx.x;
    const float* xb = x + ((size_t)b * SEQ + (size_t)chunk * 16) * CH;
    for (int c = threadIdx.x; c < CH; c += 256) {
        float s = 0.f;
        #pragma unroll
        for (int n = 0; n < 16; n++) s += xb[(size_t)n * CH + c];
        g_xpart[(b * 128 + chunk) * CH + c] = s;
    }
}

// ---------------- 1b: reduce partials -> mean -------------------------------
__global__ void xmean_kernel() {
    int b = blockIdx.x;
    int c = threadIdx.x;
    float s = 0.f;
    #pragma unroll 16
    for (int k = 0; k < 128; k++) s += g_xpart[(b * 128 + k) * CH + c];
    g_xmean[b * CH + c] = s * (1.0f / SEQ);
}

// ---------------- 2: u[b,h,c] = SCALE * sum_d Wq[h*64+d,c] * K_avg[b,h,d] ---
__global__ void u_kernel(const float* __restrict__ Wq, const float* __restrict__ Wk) {
    int b = blockIdx.x / HEADS;
    int h = blockIdx.x % HEADS;
    __shared__ float xm[CH];
    __shared__ float kavg[HDIM];
    for (int c = threadIdx.x; c < CH; c += 256) xm[c] = g_xmean[b * CH + c];
    __syncthreads();
    if (threadIdx.x < HDIM) {
        const float* wk = Wk + (size_t)(h * HDIM + threadIdx.x) * CH;
        float s = 0.f;
        #pragma unroll 8
        for (int c = 0; c < CH; c++) s += xm[c] * wk[c];
        kavg[threadIdx.x] = s;
    }
    __syncthreads();
    for (int c = threadIdx.x; c < CH; c += 256) {
        float s = 0.f;
        #pragma unroll 8
        for (int d = 0; d < HDIM; d++)
            s += Wq[(size_t)(h * HDIM + d) * CH + c] * kavg[d];
        g_u[(b * HEADS + h) * CH + c] = s * ATT_SCALE;
    }
}

// ---------------- 3: z[b,h,n] = x[b,n,:] . u[b,h,:] --------------------------
__global__ void z_kernel(const float* __restrict__ x) {
    int bn = blockIdx.x;
    int b = bn / SEQ;
    int n = bn % SEQ;
    __shared__ float xs[CH];
    const float* xr = x + (size_t)bn * CH;
    for (int c = threadIdx.x; c < CH; c += 384) xs[c] = xr[c];
    __syncthreads();
    int w = threadIdx.x >> 5;
    int lane = threadIdx.x & 31;
    const float* u = g_u + (size_t)(b * HEADS + w) * CH;
    float s = 0.f;
    #pragma unroll
    for (int c = lane; c < CH; c += 32) s += xs[c] * u[c];
    #pragma unroll
    for (int off = 16; off > 0; off >>= 1)
        s += __shfl_down_sync(0xffffffffu, s, off);
    if (lane == 0) g_z[(b * HEADS + w) * SEQ + n] = s;
}

// ---------------- 4: softmax over n per (b,h), fold 1/SEQ --------------------
__global__ void softmax_kernel() {
    __shared__ float red[256];
    int base = blockIdx.x * SEQ;
    int tid = threadIdx.x;
    float v[8];
    float m = -1e30f;
    #pragma unroll
    for (int k = 0; k < 8; k++) {
        v[k] = g_z[base + tid + k * 256];
        m = fmaxf(m, v[k]);
    }
    red[tid] = m; __syncthreads();
    for (int s = 128; s > 0; s >>= 1) {
        if (tid < s) red[tid] = fmaxf(red[tid], red[tid + s]);
        __syncthreads();
    }
    m = red[0]; __syncthreads();
    float sum = 0.f;
    #pragma unroll
    for (int k = 0; k < 8; k++) { v[k] = __expf(v[k] - m); sum += v[k]; }
    red[tid] = sum; __syncthreads();
    for (int s = 128; s > 0; s >>= 1) {
        if (tid < s) red[tid] += red[tid + s];
        __syncthreads();
    }
    float inv = 1.0f / (red[0] * (float)SEQ);
    #pragma unroll
    for (int k = 0; k < 8; k++) g_attn[base + tid + k * 256] = v[k] * inv;
}

// ================= warp-MMA building blocks ==================================
__device__ __forceinline__ void mma16816(float* c, const uint32_t* a, const uint32_t* b) {
    asm volatile(
        "mma.sync.aligned.m16n8k16.row.col.f32.f16.f16.f32 "
        "{%0,%1,%2,%3}, {%4,%5,%6,%7}, {%8,%9}, {%0,%1,%2,%3};\n"
        : "+f"(c[0]), "+f"(c[1]), "+f"(c[2]), "+f"(c[3])
        : "r"(a[0]), "r"(a[1]), "r"(a[2]), "r"(a[3]), "r"(b[0]), "r"(b[1]));
}

__device__ __forceinline__ uint32_t smem_u32(const void* p) {
    uint32_t a;
    asm("{ .reg .u64 t; cvta.to.shared.u64 t, %1; cvt.u32.u64 %0, t; }"
        : "=r"(a) : "l"(p));
    return a;
}

__device__ __forceinline__ void ldmatrix_x4(uint32_t* r, uint32_t addr) {
    asm volatile(
        "ldmatrix.sync.aligned.m8n8.x4.shared.b16 {%0,%1,%2,%3}, [%4];"
        : "=r"(r[0]), "=r"(r[1]), "=r"(r[2]), "=r"(r[3]) : "r"(addr));
}

__device__ __forceinline__ void ldmatrix_x4_trans(uint32_t* r, uint32_t addr) {
    asm volatile(
        "ldmatrix.sync.aligned.m8n8.x4.trans.shared.b16 {%0,%1,%2,%3}, [%4];"
        : "=r"(r[0]), "=r"(r[1]), "=r"(r[2]), "=r"(r[3]) : "r"(addr));
}

__device__ __forceinline__ void cp_async16(uint32_t smem_addr, const void* gptr) {
    asm volatile("cp.async.cg.shared.global [%0], [%1], 16;"
                 :: "r"(smem_addr), "l"(gptr) : "memory");
}
#define CP_COMMIT()  asm volatile("cp.async.commit_group;" ::: "memory")
#define CP_WAIT(N)   asm volatile("cp.async.wait_group %0;" :: "n"(N) : "memory")

// ================= warp-MMA fp16-split GEMM (cp.async 2-stage pipeline) ======
// out = (Ahi+Alo)[M,768] @ ((Bhi+Blo)[768,768])^T, fp32 accum, 3 products.
// MODE 1: fp32 out + bias (* outscale). MODE 2: fp16 hi/lo out.
// dyn smem: 2 stages x 4 arrays x (128 rows x 20 u32, 80B pad) = 81920 B.
#define GEMM_SMEM_BYTES (2 * 4 * 128 * 20 * 4)

template <int MODE>
__global__ void __launch_bounds__(256, 2) gemm_mma_kernel(
    const __half* __restrict__ Ahi, const __half* __restrict__ Alo,
    const __half* __restrict__ Bhi, const __half* __restrict__ Blo,
    const float* __restrict__ bias, float* __restrict__ out,
    __half* __restrict__ outhi, __half* __restrict__ outlo, float outscale)
{
    extern __shared__ uint32_t dsm[];
    uint32_t sbase = smem_u32(dsm);
    // array byte offsets within a stage: Ahi 0, Alo 10240, Bhi 20480, Blo 30720
    // stage stride: 40960 bytes

    int tid = threadIdx.x;
    int m0 = blockIdx.y * 128;
    int n0 = blockIdx.x * 128;
    int w = tid >> 5, lane = tid & 31;
    int wm = w >> 2, wn = w & 3;
    int g = lane >> 2, tig = lane & 3;

    float acc[4][4][4];
    #pragma unroll
    for (int mt = 0; mt < 4; mt++)
        #pragma unroll
        for (int nt = 0; nt < 4; nt++)
            #pragma unroll
            for (int r = 0; r < 4; r++) acc[mt][nt][r] = 0.f;

    // cp.async loader: thread t -> rows (t>>2, t>>2 + 64), 16B chunk q = t&3
    int lrow = tid >> 2;
    int q = tid & 3;
    uint32_t sdst0 = (uint32_t)(lrow * 80 + q * 16);
    uint32_t sdst1 = (uint32_t)((lrow + 64) * 80 + q * 16);
    size_t goffA0 = (size_t)(m0 + lrow) * CH + q * 8;
    size_t goffA1 = (size_t)(m0 + lrow + 64) * CH + q * 8;
    size_t goffB0 = (size_t)(n0 + lrow) * CH + q * 8;
    size_t goffB1 = (size_t)(n0 + lrow + 64) * CH + q * 8;

    // ldmatrix fragment address bases (bytes within an array)
    int sub = lane >> 3, lr = lane & 7;
    int aRow = wm * 64 + ((sub & 1) << 3) + lr;
    int aKs  = sub >> 1;
    uint32_t aOffBase = (uint32_t)(aRow * 80 + aKs * 16);
    int bRow = wn * 32 + (((sub >> 1) & 1) << 3) + lr;
    int bKs  = sub & 1;
    uint32_t bOffBase = (uint32_t)(bRow * 80 + bKs * 16);

    const int NSTAGE = CH / 32;   // 24

    // issue stage 0
    {
        uint32_t st = sbase;
        cp_async16(st + sdst0,          Ahi + goffA0);
        cp_async16(st + sdst1,          Ahi + goffA1);
        cp_async16(st + 10240 + sdst0,  Alo + goffA0);
        cp_async16(st + 10240 + sdst1,  Alo + goffA1);
        cp_async16(st + 20480 + sdst0,  Bhi + goffB0);
        cp_async16(st + 20480 + sdst1,  Bhi + goffB1);
        cp_async16(st + 30720 + sdst0,  Blo + goffB0);
        cp_async16(st + 30720 + sdst1,  Blo + goffB1);
        CP_COMMIT();
    }

    for (int s = 0; s < NSTAGE; s++) {
        // issue stage s+1 into the other buffer
        if (s + 1 < NSTAGE) {
            uint32_t st = sbase + ((s + 1) & 1) * 40960u;
            size_t ka = (size_t)(s + 1) * 32;
            cp_async16(st + sdst0,          Ahi + goffA0 + ka);
            cp_async16(st + sdst1,          Ahi + goffA1 + ka);
            cp_async16(st + 10240 + sdst0,  Alo + goffA0 + ka);
            cp_async16(st + 10240 + sdst1,  Alo + goffA1 + ka);
            cp_async16(st + 20480 + sdst0,  Bhi + goffB0 + ka);
            cp_async16(st + 20480 + sdst1,  Bhi + goffB1 + ka);
            cp_async16(st + 30720 + sdst0,  Blo + goffB0 + ka);
            cp_async16(st + 30720 + sdst1,  Blo + goffB1 + ka);
            CP_COMMIT();
            CP_WAIT(1);          // stage s resident, s+1 in flight
        } else {
            CP_WAIT(0);
        }
        __syncthreads();

        uint32_t st = sbase + (s & 1) * 40960u;
        uint32_t uAhi = st, uAlo = st + 10240u, uBhi = st + 20480u, uBlo = st + 30720u;

        #pragma unroll
        for (int kk = 0; kk < 2; kk++) {
            uint32_t kadd = (uint32_t)(kk * 32);
            uint32_t bh[4][2], bl[4][2];
            #pragma unroll
            for (int np = 0; np < 2; np++) {
                uint32_t r4[4];
                uint32_t boff = bOffBase + kadd + (uint32_t)(np * 16 * 80);
                ldmatrix_x4(r4, uBhi + boff);
                bh[np * 2][0] = r4[0];  bh[np * 2][1] = r4[1];
                bh[np * 2 + 1][0] = r4[2];  bh[np * 2 + 1][1] = r4[3];
                ldmatrix_x4(r4, uBlo + boff);
                bl[np * 2][0] = r4[0];  bl[np * 2][1] = r4[1];
                bl[np * 2 + 1][0] = r4[2];  bl[np * 2 + 1][1] = r4[3];
            }
            #pragma unroll
            for (int mt = 0; mt < 4; mt++) {
                uint32_t aoff = aOffBase + kadd + (uint32_t)(mt * 16 * 80);
                uint32_t ah[4], al[4];
                ldmatrix_x4(ah, uAhi + aoff);
                ldmatrix_x4(al, uAlo + aoff);
                #pragma unroll
                for (int nt = 0; nt < 4; nt++) {
                    mma16816(acc[mt][nt], ah, bh[nt]);
                    mma16816(acc[mt][nt], ah, bl[nt]);
                    mma16816(acc[mt][nt], al, bh[nt]);
                }
            }
        }
        __syncthreads();
    }

    #pragma unroll
    for (int mt = 0; mt < 4; mt++) {
        int r = m0 + wm * 64 + mt * 16 + g;
        #pragma unroll
        for (int nt = 0; nt < 4; nt++) {
            int c = n0 + wn * 32 + nt * 8 + tig * 2;
            if (MODE == 1) {
                float2 v0, v1;
                v0.x = acc[mt][nt][0] * outscale + bias[c];
                v0.y = acc[mt][nt][1] * outscale + bias[c + 1];
                v1.x = acc[mt][nt][2] * outscale + bias[c];
                v1.y = acc[mt][nt][3] * outscale + bias[c + 1];
                *(float2*)(out + (size_t)r * CH + c)       = v0;
                *(float2*)(out + (size_t)(r + 8) * CH + c) = v1;
            } else {
                #pragma unroll
                for (int hr = 0; hr < 2; hr++) {
                    float vx = acc[mt][nt][hr * 2];
                    float vy = acc[mt][nt][hr * 2 + 1];
                    __half hx = __float2half_rn(vx);
                    __half hy = __float2half_rn(vy);
                    __half lx = __float2half_rn(vx - __half2float(hx));
                    __half ly = __float2half_rn(vy - __half2float(hy));
                    size_t idx = (size_t)(r + hr * 8) * CH + c;
                    *(__half2*)(outhi + idx) = __halves2half2(hx, hy);
                    *(__half2*)(outlo + idx) = __halves2half2(lx, ly);
                }
            }
        }
    }
}

// ================= circulant attention on tensor cores (R5 form) =============
#define CIRC_SMEM_BYTES ((16384 + 4 * 4608) * 2)

__global__ void __launch_bounds__(256) circ_mma_kernel() {
    extern __shared__ __half dsmh[];
    __half* A2hi  = dsmh;
    __half* A2hiS = dsmh + 4096;
    __half* A2lo  = dsmh + 8192;
    __half* A2loS = dsmh + 12288;
    __half* Vbase = dsmh + 16384;

    int tid = threadIdx.x;
    int i0 = blockIdx.x * 128;
    int h  = blockIdx.y;
    int b  = blockIdx.z;
    int c0 = h * HDIM;
    int w = tid >> 5, lane = tid & 31;
    int wm = w >> 2, wn = w & 3;
    int g = lane >> 2, tig = lane & 3;

    const float* arow = g_attn + (size_t)(b * HEADS + h) * SEQ;
    for (int t = tid; t < SEQ; t += 256) {
        float a = arow[t] * OA_SCALE;
        __half hi = __float2half_rn(a);
        __half lo = __float2half_rn(a - __half2float(hi));
        A2hi[t] = hi;  A2hi[t + SEQ] = hi;
        A2lo[t] = lo;  A2lo[t + SEQ] = lo;
    }
    __syncthreads();
    for (int t = tid; t < 2 * SEQ - 1; t += 256) {
        A2hiS[t] = A2hi[t + 1];
        A2loS[t] = A2lo[t + 1];
    }
    if (tid == 0) { A2hiS[2 * SEQ - 1] = __float2half_rn(0.f); A2loS[2 * SEQ - 1] = __float2half_rn(0.f); }

    int ob = SEQ + 2 * tig - (i0 + wm * 64 + g);
    int par = ob & 1;
    const uint32_t* PhiBase = (const uint32_t*)(par ? A2hiS : A2hi) + ((ob - par) >> 1);
    const uint32_t* PloBase = (const uint32_t*)(par ? A2loS : A2lo) + ((ob - par) >> 1);

    int vrow = tid >> 3, vcg = tid & 7;
    const __half* gvh = g_vhi + ((size_t)b * SEQ + vrow) * CH + c0 + vcg * 8;
    const __half* gvl = g_vlo + ((size_t)b * SEQ + vrow) * CH + c0 + vcg * 8;
    int svo_a = vrow * 72 + vcg * 8;
    int svo_b = (vrow + 32) * 72 + vcg * 8;

    int mrow = ((lane >> 3) & 1) * 8 + (lane & 7);
    int ncol = wn * 16 + (lane >> 4) * 8;
    uint32_t svAddrPart = (uint32_t)(mrow * 144 + ncol * 2);
    uint32_t sVu32 = smem_u32(Vbase);

    float acc[4][2][4];
    #pragma unroll
    for (int mt = 0; mt < 4; mt++)
        #pragma unroll
        for (int nt = 0; nt < 2; nt++)
            #pragma unroll
            for (int r = 0; r < 4; r++) acc[mt][nt][r] = 0.f;

    uint4 pfh0, pfh1, pfl0, pfl1;
    pfh0 = *(const uint4*)gvh;
    pfh1 = *(const uint4*)(gvh + 32 * CH);
    pfl0 = *(const uint4*)gvl;
    pfl1 = *(const uint4*)(gvl + 32 * CH);

    __syncthreads();

    const int NCHUNK = SEQ / 64;   // 32
    for (int c = 0; c < NCHUNK; c++) {
        int buf = c & 1;
        __half* sVhi = Vbase + (buf * 2 + 0) * 4608;
        __half* sVlo = Vbase + (buf * 2 + 1) * 4608;
        *(uint4*)(sVhi + svo_a) = pfh0;
        *(uint4*)(sVhi + svo_b) = pfh1;
        *(uint4*)(sVlo + svo_a) = pfl0;
        *(uint4*)(sVlo + svo_b) = pfl1;
        __syncthreads();

        if (c + 1 < NCHUNK) {
            size_t adv = (size_t)(c + 1) * 64 * CH;
            pfh0 = *(const uint4*)(gvh + adv);
            pfh1 = *(const uint4*)(gvh + adv + 32 * CH);
            pfl0 = *(const uint4*)(gvl + adv);
            pfl1 = *(const uint4*)(gvl + adv + 32 * CH);
        }

        const uint32_t* Phi = PhiBase + 32 * c;
        const uint32_t* Plo = PloBase + 32 * c;
        uint32_t ehi[7], elo[7], fhi[8], flo[8];
        #pragma unroll
        for (int t = 0; t < 7; t++) { ehi[t] = Phi[8 * t - 24]; elo[t] = Plo[8 * t - 24]; }
        #pragma unroll
        for (int t = 0; t < 8; t++) { fhi[t] = Phi[8 * t - 28]; flo[t] = Plo[8 * t - 28]; }

        uint32_t sVhiAddr = sVu32 + (uint32_t)(buf * 2 + 0) * 9216u + svAddrPart;
        uint32_t sVloAddr = sVu32 + (uint32_t)(buf * 2 + 1) * 9216u + svAddrPart;

        #pragma unroll
        for (int kk = 0; kk < 4; kk++) {
            uint32_t bh[4], bl[4];
            ldmatrix_x4_trans(bh, sVhiAddr + kk * 2304u);
            ldmatrix_x4_trans(bl, sVloAddr + kk * 2304u);
            #pragma unroll
            for (int mt = 0; mt < 4; mt++) {
                int d3 = kk - mt + 3;
                uint32_t ah[4] = {ehi[d3], fhi[d3], fhi[d3 + 1], ehi[d3]};
                uint32_t al[4] = {elo[d3], flo[d3], flo[d3 + 1], elo[d3]};
                mma16816(acc[mt][0], ah, bh);
                mma16816(acc[mt][0], ah, bl);
                mma16816(acc[mt][0], al, bh);
                uint32_t bh1[2] = {bh[2], bh[3]};
                uint32_t bl1[2] = {bl[2], bl[3]};
                mma16816(acc[mt][1], ah, bh1);
                mma16816(acc[mt][1], ah, bl1);
                mma16816(acc[mt][1], al, bh1);
            }
        }
        __syncthreads();
    }

    #pragma unroll
    for (int mt = 0; mt < 4; mt++) {
        int r = i0 + wm * 64 + mt * 16 + g;
        #pragma unroll
        for (int nt = 0; nt < 2; nt++) {
            int cc = c0 + wn * 16 + nt * 8 + tig * 2;
            #pragma unroll
            for (int hr = 0; hr < 2; hr++) {
                float vx = acc[mt][nt][hr * 2];
                float vy = acc[mt][nt][hr * 2 + 1];
                __half hx = __float2half_rn(vx);
                __half hy = __float2half_rn(vy);
                __half lx = __float2half_rn(vx - __half2float(hx));
                __half ly = __float2half_rn(vy - __half2float(hy));
                size_t idx = (size_t)(b * SEQ + r + hr * 8) * CH + cc;
                *(__half2*)(g_oahi + idx) = __halves2half2(hx, hy);
                *(__half2*)(g_oalo + idx) = __halves2half2(lx, ly);
            }
        }
    }
}

// ---------------- launch ------------------------------------------------------
extern "C" void kernel_launch(void* const* d_in, const int* in_sizes, int n_in,
                              void* d_out, int out_size) {
    const float* x  = (const float*)d_in[0];
    const float* Wq = (const float*)d_in[1];
    const float* Wk = (const float*)d_in[2];
    const float* Wv = (const float*)d_in[3];
    const float* Wp = (const float*)d_in[4];
    const float* bp = (const float*)d_in[5];
    float* out = (float*)d_out;

    __half* dxhi; cudaGetSymbolAddress((void**)&dxhi,  g_xhi);
    __half* dxlo; cudaGetSymbolAddress((void**)&dxlo,  g_xlo);
    __half* dvhi; cudaGetSymbolAddress((void**)&dvhi,  g_wvhi);
    __half* dvlo; cudaGetSymbolAddress((void**)&dvlo,  g_wvlo);
    __half* dphi; cudaGetSymbolAddress((void**)&dphi,  g_wphi);
    __half* dplo; cudaGetSymbolAddress((void**)&dplo,  g_wplo);
    __half* dVhi; cudaGetSymbolAddress((void**)&dVhi,  g_vhi);
    __half* dVlo; cudaGetSymbolAddress((void**)&dVlo,  g_vlo);
    __half* dohi; cudaGetSymbolAddress((void**)&dohi,  g_oahi);
    __half* dolo; cudaGetSymbolAddress((void**)&dolo,  g_oalo);

    cudaFuncSetAttribute(circ_mma_kernel,
                         cudaFuncAttributeMaxDynamicSharedMemorySize, CIRC_SMEM_BYTES);
    cudaFuncSetAttribute(gemm_mma_kernel<1>,
                         cudaFuncAttributeMaxDynamicSharedMemorySize, GEMM_SMEM_BYTES);
    cudaFuncSetAttribute(gemm_mma_kernel<2>,
                         cudaFuncAttributeMaxDynamicSharedMemorySize, GEMM_SMEM_BYTES);

    int n4x = BATCH * SEQ * CH / 4;
    int n4w = CH * CH / 4;
    // 1-3) splits (x, Wv, Wp)
    split_kernel<<<(n4x + 255) / 256, 256>>>(x,  dxhi, dxlo, n4x);
    split_kernel<<<(n4w + 255) / 256, 256>>>(Wv, dvhi, dvlo, n4w);
    split_kernel<<<(n4w + 255) / 256, 256>>>(Wp, dphi, dplo, n4w);
    // 4) V = x @ Wv^T  (4th launch -> ncu captures this one)
    gemm_mma_kernel<2><<<dim3(CH / 128, (BATCH * SEQ) / 128), 256, GEMM_SMEM_BYTES>>>(
        dxhi, dxlo, dvhi, dvlo, nullptr, nullptr, dVhi, dVlo, 1.0f);
    // 5-6) x mean over n
    xpart_kernel<<<dim3(128, BATCH), 256>>>(x);
    xmean_kernel<<<BATCH, CH>>>();
    // 7) u = SCALE * Wq(head-block)^T @ K_avg
    u_kernel<<<BATCH * HEADS, 256>>>(Wq, Wk);
    // 8) z = x . u
    z_kernel<<<BATCH * SEQ, 384>>>(x);
    // 9) softmax (+ 1/N fold)
    softmax_kernel<<<BATCH * HEADS, 256>>>();
    // 10) circulant attention -> oa hi/lo (scaled)
    circ_mma_kernel<<<dim3(SEQ / 128, HEADS, BATCH), 256, CIRC_SMEM_BYTES>>>();
    // 11) out = oa @ Wp^T + bp
    gemm_mma_kernel<1><<<dim3(CH / 128, (BATCH * SEQ) / 128), 256, GEMM_SMEM_BYTES>>>(
        dohi, dolo, dphi, dplo, bp, out, nullptr, nullptr, OA_INV);
}

// round 9
// speedup vs baseline: 1.4702x; 1.1283x over previous
#include <cuda_runtime.h>
#include <cuda_fp16.h>
#include <cstdint>

#define BATCH 2
#define SEQ   2048
#define CH    768
#define HEADS 12
#define HDIM  64
#define ATT_SCALE 0.125f    // HDIM^-0.5
#define OA_SCALE 4096.0f
#define OA_INV   (1.0f / 4096.0f)

// ---------------- scratch (static device arrays; no cudaMalloc) -------------
__device__ float g_xpart[BATCH * 128 * CH];
__device__ float g_xmean[BATCH * CH];
__device__ float g_u[BATCH * HEADS * CH];
__device__ float g_z[BATCH * HEADS * SEQ];
__device__ float g_attn[BATCH * HEADS * SEQ];

__device__ __half g_xhi[BATCH * SEQ * CH];
__device__ __half g_xlo[BATCH * SEQ * CH];
__device__ __half g_wvhi[CH * CH];
__device__ __half g_wphi[CH * CH];
__device__ __half g_vhi[BATCH * SEQ * CH];
__device__ __half g_vlo[BATCH * SEQ * CH];
__device__ __half g_oahi[BATCH * SEQ * CH];
__device__ __half g_oalo[BATCH * SEQ * CH];

// ---------------- fp32 -> fp16 hi/lo split ----------------------------------
__global__ void split_kernel(const float* __restrict__ src,
                             __half* __restrict__ hi, __half* __restrict__ lo,
                             int n4) {
    int i = blockIdx.x * 256 + threadIdx.x;
    if (i >= n4) return;
    float4 v = ((const float4*)src)[i];
    __half hx = __float2half_rn(v.x), hy = __float2half_rn(v.y);
    __half hz = __float2half_rn(v.z), hw = __float2half_rn(v.w);
    __half lx = __float2half_rn(v.x - __half2float(hx));
    __half ly = __float2half_rn(v.y - __half2float(hy));
    __half lz = __float2half_rn(v.z - __half2float(hz));
    __half lw = __float2half_rn(v.w - __half2float(hw));
    ((__half2*)hi)[i * 2]     = __halves2half2(hx, hy);
    ((__half2*)hi)[i * 2 + 1] = __halves2half2(hz, hw);
    ((__half2*)lo)[i * 2]     = __halves2half2(lx, ly);
    ((__half2*)lo)[i * 2 + 1] = __halves2half2(lz, lw);
}

// ---------------- fp32 -> fp16 hi only (weights) -----------------------------
__global__ void hi_kernel(const float* __restrict__ src,
                          __half* __restrict__ hi, int n4) {
    int i = blockIdx.x * 256 + threadIdx.x;
    if (i >= n4) return;
    float4 v = ((const float4*)src)[i];
    ((__half2*)hi)[i * 2]     = __halves2half2(__float2half_rn(v.x), __float2half_rn(v.y));
    ((__half2*)hi)[i * 2 + 1] = __halves2half2(__float2half_rn(v.z), __float2half_rn(v.w));
}

// ---------------- 1a: partial sums of x over n -------------------------------
__global__ void xpart_kernel(const float* __restrict__ x) {
    int b = blockIdx.y;
    int chunk = blockIdx.x;
    const float* xb = x + ((size_t)b * SEQ + (size_t)chunk * 16) * CH;
    for (int c = threadIdx.x; c < CH; c += 256) {
        float s = 0.f;
        #pragma unroll
        for (int n = 0; n < 16; n++) s += xb[(size_t)n * CH + c];
        g_xpart[(b * 128 + chunk) * CH + c] = s;
    }
}

// ---------------- 1b: reduce partials -> mean -------------------------------
__global__ void xmean_kernel() {
    int b = blockIdx.x;
    int c = threadIdx.x;
    float s = 0.f;
    #pragma unroll 16
    for (int k = 0; k < 128; k++) s += g_xpart[(b * 128 + k) * CH + c];
    g_xmean[b * CH + c] = s * (1.0f / SEQ);
}

// ---------------- 2: u[b,h,c] = SCALE * sum_d Wq[h*64+d,c] * K_avg[b,h,d] ---
__global__ void u_kernel(const float* __restrict__ Wq, const float* __restrict__ Wk) {
    int b = blockIdx.x / HEADS;
    int h = blockIdx.x % HEADS;
    __shared__ float xm[CH];
    __shared__ float kavg[HDIM];
    for (int c = threadIdx.x; c < CH; c += 256) xm[c] = g_xmean[b * CH + c];
    __syncthreads();
    if (threadIdx.x < HDIM) {
        const float* wk = Wk + (size_t)(h * HDIM + threadIdx.x) * CH;
        float s = 0.f;
        #pragma unroll 8
        for (int c = 0; c < CH; c++) s += xm[c] * wk[c];
        kavg[threadIdx.x] = s;
    }
    __syncthreads();
    for (int c = threadIdx.x; c < CH; c += 256) {
        float s = 0.f;
        #pragma unroll 8
        for (int d = 0; d < HDIM; d++)
            s += Wq[(size_t)(h * HDIM + d) * CH + c] * kavg[d];
        g_u[(b * HEADS + h) * CH + c] = s * ATT_SCALE;
    }
}

// ---------------- 3: z[b,h,n] = x[b,n,:] . u[b,h,:] --------------------------
__global__ void z_kernel(const float* __restrict__ x) {
    int bn = blockIdx.x;
    int b = bn / SEQ;
    int n = bn % SEQ;
    __shared__ float xs[CH];
    const float* xr = x + (size_t)bn * CH;
    for (int c = threadIdx.x; c < CH; c += 384) xs[c] = xr[c];
    __syncthreads();
    int w = threadIdx.x >> 5;
    int lane = threadIdx.x & 31;
    const float* u = g_u + (size_t)(b * HEADS + w) * CH;
    float s = 0.f;
    #pragma unroll
    for (int c = lane; c < CH; c += 32) s += xs[c] * u[c];
    #pragma unroll
    for (int off = 16; off > 0; off >>= 1)
        s += __shfl_down_sync(0xffffffffu, s, off);
    if (lane == 0) g_z[(b * HEADS + w) * SEQ + n] = s;
}

// ---------------- 4: softmax over n per (b,h), fold 1/SEQ --------------------
__global__ void softmax_kernel() {
    __shared__ float red[256];
    int base = blockIdx.x * SEQ;
    int tid = threadIdx.x;
    float v[8];
    float m = -1e30f;
    #pragma unroll
    for (int k = 0; k < 8; k++) {
        v[k] = g_z[base + tid + k * 256];
        m = fmaxf(m, v[k]);
    }
    red[tid] = m; __syncthreads();
    for (int s = 128; s > 0; s >>= 1) {
        if (tid < s) red[tid] = fmaxf(red[tid], red[tid + s]);
        __syncthreads();
    }
    m = red[0]; __syncthreads();
    float sum = 0.f;
    #pragma unroll
    for (int k = 0; k < 8; k++) { v[k] = __expf(v[k] - m); sum += v[k]; }
    red[tid] = sum; __syncthreads();
    for (int s = 128; s > 0; s >>= 1) {
        if (tid < s) red[tid] += red[tid + s];
        __syncthreads();
    }
    float inv = 1.0f / (red[0] * (float)SEQ);
    #pragma unroll
    for (int k = 0; k < 8; k++) g_attn[base + tid + k * 256] = v[k] * inv;
}

// ================= warp-MMA building blocks ==================================
__device__ __forceinline__ void mma16816(float* c, const uint32_t* a, const uint32_t* b) {
    asm volatile(
        "mma.sync.aligned.m16n8k16.row.col.f32.f16.f16.f32 "
        "{%0,%1,%2,%3}, {%4,%5,%6,%7}, {%8,%9}, {%0,%1,%2,%3};\n"
        : "+f"(c[0]), "+f"(c[1]), "+f"(c[2]), "+f"(c[3])
        : "r"(a[0]), "r"(a[1]), "r"(a[2]), "r"(a[3]), "r"(b[0]), "r"(b[1]));
}

__device__ __forceinline__ uint32_t smem_u32(const void* p) {
    uint32_t a;
    asm("{ .reg .u64 t; cvta.to.shared.u64 t, %1; cvt.u32.u64 %0, t; }"
        : "=r"(a) : "l"(p));
    return a;
}

__device__ __forceinline__ void ldmatrix_x4(uint32_t* r, uint32_t addr) {
    asm volatile(
        "ldmatrix.sync.aligned.m8n8.x4.shared.b16 {%0,%1,%2,%3}, [%4];"
        : "=r"(r[0]), "=r"(r[1]), "=r"(r[2]), "=r"(r[3]) : "r"(addr));
}

__device__ __forceinline__ void ldmatrix_x4_trans(uint32_t* r, uint32_t addr) {
    asm volatile(
        "ldmatrix.sync.aligned.m8n8.x4.trans.shared.b16 {%0,%1,%2,%3}, [%4];"
        : "=r"(r[0]), "=r"(r[1]), "=r"(r[2]), "=r"(r[3]) : "r"(addr));
}

__device__ __forceinline__ void cp_async16(uint32_t smem_addr, const void* gptr) {
    asm volatile("cp.async.cg.shared.global [%0], [%1], 16;"
                 :: "r"(smem_addr), "l"(gptr) : "memory");
}
#define CP_COMMIT()  asm volatile("cp.async.commit_group;" ::: "memory")
#define CP_WAIT(N)   asm volatile("cp.async.wait_group %0;" :: "n"(N) : "memory")

// ================= warp-MMA 2-product GEMM (cp.async 3-stage) ================
// out = (Ahi+Alo)[M,768] @ (Bhi[768,768])^T, fp32 accum.
// MODE 1: fp32 out + bias (* outscale). MODE 2: fp16 hi/lo out.
// dyn smem: 3 stages x 3 arrays x 10240 B = 92160 B. 2 CTAs/SM.
#define GEMM_STAGE_BYTES 30720
#define GEMM_SMEM_BYTES  (3 * GEMM_STAGE_BYTES)

template <int MODE>
__global__ void __launch_bounds__(256, 2) gemm_mma_kernel(
    const __half* __restrict__ Ahi, const __half* __restrict__ Alo,
    const __half* __restrict__ Bhi,
    const float* __restrict__ bias, float* __restrict__ out,
    __half* __restrict__ outhi, __half* __restrict__ outlo, float outscale)
{
    extern __shared__ uint32_t dsm[];
    uint32_t sbase = smem_u32(dsm);
    // within a stage: Ahi @0, Alo @10240, Bhi @20480

    int tid = threadIdx.x;
    int m0 = blockIdx.y * 128;
    int n0 = blockIdx.x * 128;
    int w = tid >> 5, lane = tid & 31;
    int wm = w >> 2, wn = w & 3;
    int g = lane >> 2, tig = lane & 3;

    float acc[4][4][4];
    #pragma unroll
    for (int mt = 0; mt < 4; mt++)
        #pragma unroll
        for (int nt = 0; nt < 4; nt++)
            #pragma unroll
            for (int r = 0; r < 4; r++) acc[mt][nt][r] = 0.f;

    int lrow = tid >> 2;
    int q = tid & 3;
    uint32_t sdst0 = (uint32_t)(lrow * 80 + q * 16);
    uint32_t sdst1 = (uint32_t)((lrow + 64) * 80 + q * 16);
    size_t goffA0 = (size_t)(m0 + lrow) * CH + q * 8;
    size_t goffA1 = (size_t)(m0 + lrow + 64) * CH + q * 8;
    size_t goffB0 = (size_t)(n0 + lrow) * CH + q * 8;
    size_t goffB1 = (size_t)(n0 + lrow + 64) * CH + q * 8;

    int sub = lane >> 3, lr = lane & 7;
    int aRow = wm * 64 + ((sub & 1) << 3) + lr;
    int aKs  = sub >> 1;
    uint32_t aOffBase = (uint32_t)(aRow * 80 + aKs * 16);
    int bRow = wn * 32 + (((sub >> 1) & 1) << 3) + lr;
    int bKs  = sub & 1;
    uint32_t bOffBase = (uint32_t)(bRow * 80 + bKs * 16);

    const int NSTAGE = CH / 32;   // 24

    // prologue: issue stages 0 and 1
    #pragma unroll
    for (int p = 0; p < 2; p++) {
        uint32_t st = sbase + (uint32_t)p * GEMM_STAGE_BYTES;
        size_t ka = (size_t)p * 32;
        cp_async16(st + sdst0,          Ahi + goffA0 + ka);
        cp_async16(st + sdst1,          Ahi + goffA1 + ka);
        cp_async16(st + 10240 + sdst0,  Alo + goffA0 + ka);
        cp_async16(st + 10240 + sdst1,  Alo + goffA1 + ka);
        cp_async16(st + 20480 + sdst0,  Bhi + goffB0 + ka);
        cp_async16(st + 20480 + sdst1,  Bhi + goffB1 + ka);
        CP_COMMIT();
    }

    int sslot = 0;
    for (int s = 0; s < NSTAGE; s++) {
        CP_WAIT(1);           // stage s resident (s+1 may be in flight)
        __syncthreads();

        uint32_t st = sbase + (uint32_t)sslot * GEMM_STAGE_BYTES;
        uint32_t uAhi = st, uAlo = st + 10240u, uBhi = st + 20480u;

        #pragma unroll
        for (int kk = 0; kk < 2; kk++) {
            uint32_t kadd = (uint32_t)(kk * 32);
            uint32_t bh[4][2];
            #pragma unroll
            for (int np = 0; np < 2; np++) {
                uint32_t r4[4];
                uint32_t boff = bOffBase + kadd + (uint32_t)(np * 16 * 80);
                ldmatrix_x4(r4, uBhi + boff);
                bh[np * 2][0] = r4[0];      bh[np * 2][1] = r4[1];
                bh[np * 2 + 1][0] = r4[2];  bh[np * 2 + 1][1] = r4[3];
            }
            #pragma unroll
            for (int mt = 0; mt < 4; mt++) {
                uint32_t aoff = aOffBase + kadd + (uint32_t)(mt * 16 * 80);
                uint32_t ah[4], al[4];
                ldmatrix_x4(ah, uAhi + aoff);
                ldmatrix_x4(al, uAlo + aoff);
                #pragma unroll
                for (int nt = 0; nt < 4; nt++) {
                    mma16816(acc[mt][nt], ah, bh[nt]);
                    mma16816(acc[mt][nt], al, bh[nt]);
                }
            }
        }
        __syncthreads();      // stage slot sslot now reusable

        if (s + 2 < NSTAGE) {
            int tgt = (sslot + 2) % 3;
            uint32_t st2 = sbase + (uint32_t)tgt * GEMM_STAGE_BYTES;
            size_t ka = (size_t)(s + 2) * 32;
            cp_async16(st2 + sdst0,          Ahi + goffA0 + ka);
            cp_async16(st2 + sdst1,          Ahi + goffA1 + ka);
            cp_async16(st2 + 10240 + sdst0,  Alo + goffA0 + ka);
            cp_async16(st2 + 10240 + sdst1,  Alo + goffA1 + ka);
            cp_async16(st2 + 20480 + sdst0,  Bhi + goffB0 + ka);
            cp_async16(st2 + 20480 + sdst1,  Bhi + goffB1 + ka);
            CP_COMMIT();
        }
        sslot = (sslot + 1) % 3;
    }

    #pragma unroll
    for (int mt = 0; mt < 4; mt++) {
        int r = m0 + wm * 64 + mt * 16 + g;
        #pragma unroll
        for (int nt = 0; nt < 4; nt++) {
            int c = n0 + wn * 32 + nt * 8 + tig * 2;
            if (MODE == 1) {
                float2 v0, v1;
                v0.x = acc[mt][nt][0] * outscale + bias[c];
                v0.y = acc[mt][nt][1] * outscale + bias[c + 1];
                v1.x = acc[mt][nt][2] * outscale + bias[c];
                v1.y = acc[mt][nt][3] * outscale + bias[c + 1];
                *(float2*)(out + (size_t)r * CH + c)       = v0;
                *(float2*)(out + (size_t)(r + 8) * CH + c) = v1;
            } else {
                #pragma unroll
                for (int hr = 0; hr < 2; hr++) {
                    float vx = acc[mt][nt][hr * 2];
                    float vy = acc[mt][nt][hr * 2 + 1];
                    __half hx = __float2half_rn(vx);
                    __half hy = __float2half_rn(vy);
                    __half lx = __float2half_rn(vx - __half2float(hx));
                    __half ly = __float2half_rn(vy - __half2float(hy));
                    size_t idx = (size_t)(r + hr * 8) * CH + c;
                    *(__half2*)(outhi + idx) = __halves2half2(hx, hy);
                    *(__half2*)(outlo + idx) = __halves2half2(lx, ly);
                }
            }
        }
    }
}

// ================= circulant attention on tensor cores (unchanged R5) ========
#define CIRC_SMEM_BYTES ((16384 + 4 * 4608) * 2)

__global__ void __launch_bounds__(256) circ_mma_kernel() {
    extern __shared__ __half dsmh[];
    __half* A2hi  = dsmh;
    __half* A2hiS = dsmh + 4096;
    __half* A2lo  = dsmh + 8192;
    __half* A2loS = dsmh + 12288;
    __half* Vbase = dsmh + 16384;

    int tid = threadIdx.x;
    int i0 = blockIdx.x * 128;
    int h  = blockIdx.y;
    int b  = blockIdx.z;
    int c0 = h * HDIM;
    int w = tid >> 5, lane = tid & 31;
    int wm = w >> 2, wn = w & 3;
    int g = lane >> 2, tig = lane & 3;

    const float* arow = g_attn + (size_t)(b * HEADS + h) * SEQ;
    for (int t = tid; t < SEQ; t += 256) {
        float a = arow[t] * OA_SCALE;
        __half hi = __float2half_rn(a);
        __half lo = __float2half_rn(a - __half2float(hi));
        A2hi[t] = hi;  A2hi[t + SEQ] = hi;
        A2lo[t] = lo;  A2lo[t + SEQ] = lo;
    }
    __syncthreads();
    for (int t = tid; t < 2 * SEQ - 1; t += 256) {
        A2hiS[t] = A2hi[t + 1];
        A2loS[t] = A2lo[t + 1];
    }
    if (tid == 0) { A2hiS[2 * SEQ - 1] = __float2half_rn(0.f); A2loS[2 * SEQ - 1] = __float2half_rn(0.f); }

    int ob = SEQ + 2 * tig - (i0 + wm * 64 + g);
    int par = ob & 1;
    const uint32_t* PhiBase = (const uint32_t*)(par ? A2hiS : A2hi) + ((ob - par) >> 1);
    const uint32_t* PloBase = (const uint32_t*)(par ? A2loS : A2lo) + ((ob - par) >> 1);

    int vrow = tid >> 3, vcg = tid & 7;
    const __half* gvh = g_vhi + ((size_t)b * SEQ + vrow) * CH + c0 + vcg * 8;
    const __half* gvl = g_vlo + ((size_t)b * SEQ + vrow) * CH + c0 + vcg * 8;
    int svo_a = vrow * 72 + vcg * 8;
    int svo_b = (vrow + 32) * 72 + vcg * 8;

    int mrow = ((lane >> 3) & 1) * 8 + (lane & 7);
    int ncol = wn * 16 + (lane >> 4) * 8;
    uint32_t svAddrPart = (uint32_t)(mrow * 144 + ncol * 2);
    uint32_t sVu32 = smem_u32(Vbase);

    float acc[4][2][4];
    #pragma unroll
    for (int mt = 0; mt < 4; mt++)
        #pragma unroll
        for (int nt = 0; nt < 2; nt++)
            #pragma unroll
            for (int r = 0; r < 4; r++) acc[mt][nt][r] = 0.f;

    uint4 pfh0, pfh1, pfl0, pfl1;
    pfh0 = *(const uint4*)gvh;
    pfh1 = *(const uint4*)(gvh + 32 * CH);
    pfl0 = *(const uint4*)gvl;
    pfl1 = *(const uint4*)(gvl + 32 * CH);

    __syncthreads();

    const int NCHUNK = SEQ / 64;   // 32
    for (int c = 0; c < NCHUNK; c++) {
        int buf = c & 1;
        __half* sVhi = Vbase + (buf * 2 + 0) * 4608;
        __half* sVlo = Vbase + (buf * 2 + 1) * 4608;
        *(uint4*)(sVhi + svo_a) = pfh0;
        *(uint4*)(sVhi + svo_b) = pfh1;
        *(uint4*)(sVlo + svo_a) = pfl0;
        *(uint4*)(sVlo + svo_b) = pfl1;
        __syncthreads();

        if (c + 1 < NCHUNK) {
            size_t adv = (size_t)(c + 1) * 64 * CH;
            pfh0 = *(const uint4*)(gvh + adv);
            pfh1 = *(const uint4*)(gvh + adv + 32 * CH);
            pfl0 = *(const uint4*)(gvl + adv);
            pfl1 = *(const uint4*)(gvl + adv + 32 * CH);
        }

        const uint32_t* Phi = PhiBase + 32 * c;
        const uint32_t* Plo = PloBase + 32 * c;
        uint32_t ehi[7], elo[7], fhi[8], flo[8];
        #pragma unroll
        for (int t = 0; t < 7; t++) { ehi[t] = Phi[8 * t - 24]; elo[t] = Plo[8 * t - 24]; }
        #pragma unroll
        for (int t = 0; t < 8; t++) { fhi[t] = Phi[8 * t - 28]; flo[t] = Plo[8 * t - 28]; }

        uint32_t sVhiAddr = sVu32 + (uint32_t)(buf * 2 + 0) * 9216u + svAddrPart;
        uint32_t sVloAddr = sVu32 + (uint32_t)(buf * 2 + 1) * 9216u + svAddrPart;

        #pragma unroll
        for (int kk = 0; kk < 4; kk++) {
            uint32_t bh[4], bl[4];
            ldmatrix_x4_trans(bh, sVhiAddr + kk * 2304u);
            ldmatrix_x4_trans(bl, sVloAddr + kk * 2304u);
            #pragma unroll
            for (int mt = 0; mt < 4; mt++) {
                int d3 = kk - mt + 3;
                uint32_t ah[4] = {ehi[d3], fhi[d3], fhi[d3 + 1], ehi[d3]};
                uint32_t al[4] = {elo[d3], flo[d3], flo[d3 + 1], elo[d3]};
                mma16816(acc[mt][0], ah, bh);
                mma16816(acc[mt][0], ah, bl);
                mma16816(acc[mt][0], al, bh);
                uint32_t bh1[2] = {bh[2], bh[3]};
                uint32_t bl1[2] = {bl[2], bl[3]};
                mma16816(acc[mt][1], ah, bh1);
                mma16816(acc[mt][1], ah, bl1);
                mma16816(acc[mt][1], al, bh1);
            }
        }
        __syncthreads();
    }

    #pragma unroll
    for (int mt = 0; mt < 4; mt++) {
        int r = i0 + wm * 64 + mt * 16 + g;
        #pragma unroll
        for (int nt = 0; nt < 2; nt++) {
            int cc = c0 + wn * 16 + nt * 8 + tig * 2;
            #pragma unroll
            for (int hr = 0; hr < 2; hr++) {
                float vx = acc[mt][nt][hr * 2];
                float vy = acc[mt][nt][hr * 2 + 1];
                __half hx = __float2half_rn(vx);
                __half hy = __float2half_rn(vy);
                __half lx = __float2half_rn(vx - __half2float(hx));
                __half ly = __float2half_rn(vy - __half2float(hy));
                size_t idx = (size_t)(b * SEQ + r + hr * 8) * CH + cc;
                *(__half2*)(g_oahi + idx) = __halves2half2(hx, hy);
                *(__half2*)(g_oalo + idx) = __halves2half2(lx, ly);
            }
        }
    }
}

// ---------------- launch ------------------------------------------------------
extern "C" void kernel_launch(void* const* d_in, const int* in_sizes, int n_in,
                              void* d_out, int out_size) {
    const float* x  = (const float*)d_in[0];
    const float* Wq = (const float*)d_in[1];
    const float* Wk = (const float*)d_in[2];
    const float* Wv = (const float*)d_in[3];
    const float* Wp = (const float*)d_in[4];
    const float* bp = (const float*)d_in[5];
    float* out = (float*)d_out;

    __half* dxhi; cudaGetSymbolAddress((void**)&dxhi,  g_xhi);
    __half* dxlo; cudaGetSymbolAddress((void**)&dxlo,  g_xlo);
    __half* dvhi; cudaGetSymbolAddress((void**)&dvhi,  g_wvhi);
    __half* dphi; cudaGetSymbolAddress((void**)&dphi,  g_wphi);
    __half* dVhi; cudaGetSymbolAddress((void**)&dVhi,  g_vhi);
    __half* dVlo; cudaGetSymbolAddress((void**)&dVlo,  g_vlo);
    __half* dohi; cudaGetSymbolAddress((void**)&dohi,  g_oahi);
    __half* dolo; cudaGetSymbolAddress((void**)&dolo,  g_oalo);

    cudaFuncSetAttribute(circ_mma_kernel,
                         cudaFuncAttributeMaxDynamicSharedMemorySize, CIRC_SMEM_BYTES);
    cudaFuncSetAttribute(gemm_mma_kernel<1>,
                         cudaFuncAttributeMaxDynamicSharedMemorySize, GEMM_SMEM_BYTES);
    cudaFuncSetAttribute(gemm_mma_kernel<2>,
                         cudaFuncAttributeMaxDynamicSharedMemorySize, GEMM_SMEM_BYTES);

    int n4x = BATCH * SEQ * CH / 4;
    int n4w = CH * CH / 4;
    // 1-3) splits (x hi/lo, Wv hi, Wp hi)
    split_kernel<<<(n4x + 255) / 256, 256>>>(x,  dxhi, dxlo, n4x);
    hi_kernel<<<(n4w + 255) / 256, 256>>>(Wv, dvhi, n4w);
    hi_kernel<<<(n4w + 255) / 256, 256>>>(Wp, dphi, n4w);
    // 4) V = x @ Wv^T  (4th launch -> ncu captures this one)
    gemm_mma_kernel<2><<<dim3(CH / 128, (BATCH * SEQ) / 128), 256, GEMM_SMEM_BYTES>>>(
        dxhi, dxlo, dvhi, nullptr, nullptr, dVhi, dVlo, 1.0f);
    // 5-6) x mean over n
    xpart_kernel<<<dim3(128, BATCH), 256>>>(x);
    xmean_kernel<<<BATCH, CH>>>();
    // 7) u = SCALE * Wq(head-block)^T @ K_avg
    u_kernel<<<BATCH * HEADS, 256>>>(Wq, Wk);
    // 8) z = x . u
    z_kernel<<<BATCH * SEQ, 384>>>(x);
    // 9) softmax (+ 1/N fold)
    softmax_kernel<<<BATCH * HEADS, 256>>>();
    // 10) circulant attention -> oa hi/lo (scaled)
    circ_mma_kernel<<<dim3(SEQ / 128, HEADS, BATCH), 256, CIRC_SMEM_BYTES>>>();
    // 11) out = oa @ Wp^T + bp
    gemm_mma_kernel<1><<<dim3(CH / 128, (BATCH * SEQ) / 128), 256, GEMM_SMEM_BYTES>>>(
        dohi, dolo, dphi, bp, out, nullptr, nullptr, OA_INV);
}

// round 10
// speedup vs baseline: 1.7169x; 1.1678x over previous
#include <cuda_runtime.h>
#include <cuda_fp16.h>
#include <cstdint>

#define BATCH 2
#define SEQ   2048
#define CH    768
#define HEADS 12
#define HDIM  64
#define ATT_SCALE 0.125f    // HDIM^-0.5
#define OA_SCALE 4096.0f
#define OA_INV   (1.0f / 4096.0f)

// ---------------- scratch (static device arrays; no cudaMalloc) -------------
__device__ float g_xpart[BATCH * 128 * CH];
__device__ float g_xmean[BATCH * CH];
__device__ float g_u[BATCH * HEADS * CH];
__device__ float g_z[BATCH * HEADS * SEQ];
__device__ float g_attn[BATCH * HEADS * SEQ];

__device__ __half g_xhi[BATCH * SEQ * CH];
__device__ __half g_xlo[BATCH * SEQ * CH];
__device__ __half g_wvhi[CH * CH];
__device__ __half g_wphi[CH * CH];
__device__ __half g_vhi[BATCH * SEQ * CH];
__device__ __half g_oahi[BATCH * SEQ * CH];
__device__ __half g_oalo[BATCH * SEQ * CH];

// ---------------- fp32 -> fp16 hi/lo split ----------------------------------
__global__ void split_kernel(const float* __restrict__ src,
                             __half* __restrict__ hi, __half* __restrict__ lo,
                             int n4) {
    int i = blockIdx.x * 256 + threadIdx.x;
    if (i >= n4) return;
    float4 v = ((const float4*)src)[i];
    __half hx = __float2half_rn(v.x), hy = __float2half_rn(v.y);
    __half hz = __float2half_rn(v.z), hw = __float2half_rn(v.w);
    __half lx = __float2half_rn(v.x - __half2float(hx));
    __half ly = __float2half_rn(v.y - __half2float(hy));
    __half lz = __float2half_rn(v.z - __half2float(hz));
    __half lw = __float2half_rn(v.w - __half2float(hw));
    ((__half2*)hi)[i * 2]     = __halves2half2(hx, hy);
    ((__half2*)hi)[i * 2 + 1] = __halves2half2(hz, hw);
    ((__half2*)lo)[i * 2]     = __halves2half2(lx, ly);
    ((__half2*)lo)[i * 2 + 1] = __halves2half2(lz, lw);
}

// ---------------- fp32 -> fp16 hi only (weights) -----------------------------
__global__ void hi_kernel(const float* __restrict__ src,
                          __half* __restrict__ hi, int n4) {
    int i = blockIdx.x * 256 + threadIdx.x;
    if (i >= n4) return;
    float4 v = ((const float4*)src)[i];
    ((__half2*)hi)[i * 2]     = __halves2half2(__float2half_rn(v.x), __float2half_rn(v.y));
    ((__half2*)hi)[i * 2 + 1] = __halves2half2(__float2half_rn(v.z), __float2half_rn(v.w));
}

// ---------------- 1a: partial sums of x over n -------------------------------
__global__ void xpart_kernel(const float* __restrict__ x) {
    int b = blockIdx.y;
    int chunk = blockIdx.x;
    const float* xb = x + ((size_t)b * SEQ + (size_t)chunk * 16) * CH;
    for (int c = threadIdx.x; c < CH; c += 256) {
        float s = 0.f;
        #pragma unroll
        for (int n = 0; n < 16; n++) s += xb[(size_t)n * CH + c];
        g_xpart[(b * 128 + chunk) * CH + c] = s;
    }
}

// ---------------- 1b: reduce partials -> mean -------------------------------
__global__ void xmean_kernel() {
    int b = blockIdx.x;
    int c = threadIdx.x;
    float s = 0.f;
    #pragma unroll 16
    for (int k = 0; k < 128; k++) s += g_xpart[(b * 128 + k) * CH + c];
    g_xmean[b * CH + c] = s * (1.0f / SEQ);
}

// ---------------- 2: u[b,h,c] = SCALE * sum_d Wq[h*64+d,c] * K_avg[b,h,d] ---
__global__ void u_kernel(const float* __restrict__ Wq, const float* __restrict__ Wk) {
    int b = blockIdx.x / HEADS;
    int h = blockIdx.x % HEADS;
    __shared__ float xm[CH];
    __shared__ float kavg[HDIM];
    for (int c = threadIdx.x; c < CH; c += 256) xm[c] = g_xmean[b * CH + c];
    __syncthreads();
    if (threadIdx.x < HDIM) {
        const float* wk = Wk + (size_t)(h * HDIM + threadIdx.x) * CH;
        float s = 0.f;
        #pragma unroll 8
        for (int c = 0; c < CH; c++) s += xm[c] * wk[c];
        kavg[threadIdx.x] = s;
    }
    __syncthreads();
    for (int c = threadIdx.x; c < CH; c += 256) {
        float s = 0.f;
        #pragma unroll 8
        for (int d = 0; d < HDIM; d++)
            s += Wq[(size_t)(h * HDIM + d) * CH + c] * kavg[d];
        g_u[(b * HEADS + h) * CH + c] = s * ATT_SCALE;
    }
}

// ---------------- 3: z[b,h,n] = x[b,n,:] . u[b,h,:] --------------------------
__global__ void z_kernel(const float* __restrict__ x) {
    int bn = blockIdx.x;
    int b = bn / SEQ;
    int n = bn % SEQ;
    __shared__ float xs[CH];
    const float* xr = x + (size_t)bn * CH;
    for (int c = threadIdx.x; c < CH; c += 384) xs[c] = xr[c];
    __syncthreads();
    int w = threadIdx.x >> 5;
    int lane = threadIdx.x & 31;
    const float* u = g_u + (size_t)(b * HEADS + w) * CH;
    float s = 0.f;
    #pragma unroll
    for (int c = lane; c < CH; c += 32) s += xs[c] * u[c];
    #pragma unroll
    for (int off = 16; off > 0; off >>= 1)
        s += __shfl_down_sync(0xffffffffu, s, off);
    if (lane == 0) g_z[(b * HEADS + w) * SEQ + n] = s;
}

// ---------------- 4: softmax over n per (b,h), fold 1/SEQ --------------------
__global__ void softmax_kernel() {
    __shared__ float red[256];
    int base = blockIdx.x * SEQ;
    int tid = threadIdx.x;
    float v[8];
    float m = -1e30f;
    #pragma unroll
    for (int k = 0; k < 8; k++) {
        v[k] = g_z[base + tid + k * 256];
        m = fmaxf(m, v[k]);
    }
    red[tid] = m; __syncthreads();
    for (int s = 128; s > 0; s >>= 1) {
        if (tid < s) red[tid] = fmaxf(red[tid], red[tid + s]);
        __syncthreads();
    }
    m = red[0]; __syncthreads();
    float sum = 0.f;
    #pragma unroll
    for (int k = 0; k < 8; k++) { v[k] = __expf(v[k] - m); sum += v[k]; }
    red[tid] = sum; __syncthreads();
    for (int s = 128; s > 0; s >>= 1) {
        if (tid < s) red[tid] += red[tid + s];
        __syncthreads();
    }
    float inv = 1.0f / (red[0] * (float)SEQ);
    #pragma unroll
    for (int k = 0; k < 8; k++) g_attn[base + tid + k * 256] = v[k] * inv;
}

// ================= warp-MMA building blocks ==================================
__device__ __forceinline__ void mma16816(float* c, const uint32_t* a, const uint32_t* b) {
    asm volatile(
        "mma.sync.aligned.m16n8k16.row.col.f32.f16.f16.f32 "
        "{%0,%1,%2,%3}, {%4,%5,%6,%7}, {%8,%9}, {%0,%1,%2,%3};\n"
        : "+f"(c[0]), "+f"(c[1]), "+f"(c[2]), "+f"(c[3])
        : "r"(a[0]), "r"(a[1]), "r"(a[2]), "r"(a[3]), "r"(b[0]), "r"(b[1]));
}

__device__ __forceinline__ uint32_t smem_u32(const void* p) {
    uint32_t a;
    asm("{ .reg .u64 t; cvta.to.shared.u64 t, %1; cvt.u32.u64 %0, t; }"
        : "=r"(a) : "l"(p));
    return a;
}

__device__ __forceinline__ void ldmatrix_x4(uint32_t* r, uint32_t addr) {
    asm volatile(
        "ldmatrix.sync.aligned.m8n8.x4.shared.b16 {%0,%1,%2,%3}, [%4];"
        : "=r"(r[0]), "=r"(r[1]), "=r"(r[2]), "=r"(r[3]) : "r"(addr));
}

__device__ __forceinline__ void ldmatrix_x4_trans(uint32_t* r, uint32_t addr) {
    asm volatile(
        "ldmatrix.sync.aligned.m8n8.x4.trans.shared.b16 {%0,%1,%2,%3}, [%4];"
        : "=r"(r[0]), "=r"(r[1]), "=r"(r[2]), "=r"(r[3]) : "r"(addr));
}

__device__ __forceinline__ void cp_async16(uint32_t smem_addr, const void* gptr) {
    asm volatile("cp.async.cg.shared.global [%0], [%1], 16;"
                 :: "r"(smem_addr), "l"(gptr) : "memory");
}
#define CP_COMMIT()  asm volatile("cp.async.commit_group;" ::: "memory")
#define CP_WAIT(N)   asm volatile("cp.async.wait_group %0;" :: "n"(N) : "memory")

// ================= warp-MMA 2-product GEMM (cp.async 3-stage) ================
// out = (Ahi+Alo)[M,768] @ (Bhi[768,768])^T, fp32 accum.
// MODE 1: fp32 out + bias (* outscale). MODE 2: fp16 hi out.
#define GEMM_STAGE_BYTES 30720
#define GEMM_SMEM_BYTES  (3 * GEMM_STAGE_BYTES)

template <int MODE>
__global__ void __launch_bounds__(256, 2) gemm_mma_kernel(
    const __half* __restrict__ Ahi, const __half* __restrict__ Alo,
    const __half* __restrict__ Bhi,
    const float* __restrict__ bias, float* __restrict__ out,
    __half* __restrict__ outhi, __half* __restrict__ outlo, float outscale)
{
    extern __shared__ uint32_t dsm[];
    uint32_t sbase = smem_u32(dsm);

    int tid = threadIdx.x;
    int m0 = blockIdx.y * 128;
    int n0 = blockIdx.x * 128;
    int w = tid >> 5, lane = tid & 31;
    int wm = w >> 2, wn = w & 3;
    int g = lane >> 2, tig = lane & 3;

    float acc[4][4][4];
    #pragma unroll
    for (int mt = 0; mt < 4; mt++)
        #pragma unroll
        for (int nt = 0; nt < 4; nt++)
            #pragma unroll
            for (int r = 0; r < 4; r++) acc[mt][nt][r] = 0.f;

    int lrow = tid >> 2;
    int q = tid & 3;
    uint32_t sdst0 = (uint32_t)(lrow * 80 + q * 16);
    uint32_t sdst1 = (uint32_t)((lrow + 64) * 80 + q * 16);
    size_t goffA0 = (size_t)(m0 + lrow) * CH + q * 8;
    size_t goffA1 = (size_t)(m0 + lrow + 64) * CH + q * 8;
    size_t goffB0 = (size_t)(n0 + lrow) * CH + q * 8;
    size_t goffB1 = (size_t)(n0 + lrow + 64) * CH + q * 8;

    int sub = lane >> 3, lr = lane & 7;
    int aRow = wm * 64 + ((sub & 1) << 3) + lr;
    int aKs  = sub >> 1;
    uint32_t aOffBase = (uint32_t)(aRow * 80 + aKs * 16);
    int bRow = wn * 32 + (((sub >> 1) & 1) << 3) + lr;
    int bKs  = sub & 1;
    uint32_t bOffBase = (uint32_t)(bRow * 80 + bKs * 16);

    const int NSTAGE = CH / 32;   // 24

    #pragma unroll
    for (int p = 0; p < 2; p++) {
        uint32_t st = sbase + (uint32_t)p * GEMM_STAGE_BYTES;
        size_t ka = (size_t)p * 32;
        cp_async16(st + sdst0,          Ahi + goffA0 + ka);
        cp_async16(st + sdst1,          Ahi + goffA1 + ka);
        cp_async16(st + 10240 + sdst0,  Alo + goffA0 + ka);
        cp_async16(st + 10240 + sdst1,  Alo + goffA1 + ka);
        cp_async16(st + 20480 + sdst0,  Bhi + goffB0 + ka);
        cp_async16(st + 20480 + sdst1,  Bhi + goffB1 + ka);
        CP_COMMIT();
    }

    int sslot = 0;
    for (int s = 0; s < NSTAGE; s++) {
        // tail-correct wait: when no group besides stage s is in flight,
        // wait for ALL groups (WAIT(1) would be a no-op with 1 pending).
        if (s + 1 < NSTAGE) { CP_WAIT(1); } else { CP_WAIT(0); }
        __syncthreads();

        // issue stage s+2 (slot reuse safe: all threads are past compute s-1)
        if (s + 2 < NSTAGE) {
            int tgt = (sslot + 2) % 3;
            uint32_t st2 = sbase + (uint32_t)tgt * GEMM_STAGE_BYTES;
            size_t ka = (size_t)(s + 2) * 32;
            cp_async16(st2 + sdst0,          Ahi + goffA0 + ka);
            cp_async16(st2 + sdst1,          Ahi + goffA1 + ka);
            cp_async16(st2 + 10240 + sdst0,  Alo + goffA0 + ka);
            cp_async16(st2 + 10240 + sdst1,  Alo + goffA1 + ka);
            cp_async16(st2 + 20480 + sdst0,  Bhi + goffB0 + ka);
            cp_async16(st2 + 20480 + sdst1,  Bhi + goffB1 + ka);
            CP_COMMIT();
        }

        uint32_t st = sbase + (uint32_t)sslot * GEMM_STAGE_BYTES;
        uint32_t uAhi = st, uAlo = st + 10240u, uBhi = st + 20480u;

        #pragma unroll
        for (int kk = 0; kk < 2; kk++) {
            uint32_t kadd = (uint32_t)(kk * 32);
            uint32_t bh[4][2];
            #pragma unroll
            for (int np = 0; np < 2; np++) {
                uint32_t r4[4];
                uint32_t boff = bOffBase + kadd + (uint32_t)(np * 16 * 80);
                ldmatrix_x4(r4, uBhi + boff);
                bh[np * 2][0] = r4[0];      bh[np * 2][1] = r4[1];
                bh[np * 2 + 1][0] = r4[2];  bh[np * 2 + 1][1] = r4[3];
            }
            #pragma unroll
            for (int mt = 0; mt < 4; mt++) {
                uint32_t aoff = aOffBase + kadd + (uint32_t)(mt * 16 * 80);
                uint32_t ah[4], al[4];
                ldmatrix_x4(ah, uAhi + aoff);
                ldmatrix_x4(al, uAlo + aoff);
                #pragma unroll
                for (int nt = 0; nt < 4; nt++) {
                    mma16816(acc[mt][nt], ah, bh[nt]);
                    mma16816(acc[mt][nt], al, bh[nt]);
                }
            }
        }
        __syncthreads();
        sslot = (sslot + 1) % 3;
    }

    #pragma unroll
    for (int mt = 0; mt < 4; mt++) {
        int r = m0 + wm * 64 + mt * 16 + g;
        #pragma unroll
        for (int nt = 0; nt < 4; nt++) {
            int c = n0 + wn * 32 + nt * 8 + tig * 2;
            if (MODE == 1) {
                float2 v0, v1;
                v0.x = acc[mt][nt][0] * outscale + bias[c];
                v0.y = acc[mt][nt][1] * outscale + bias[c + 1];
                v1.x = acc[mt][nt][2] * outscale + bias[c];
                v1.y = acc[mt][nt][3] * outscale + bias[c + 1];
                *(float2*)(out + (size_t)r * CH + c)       = v0;
                *(float2*)(out + (size_t)(r + 8) * CH + c) = v1;
            } else {
                #pragma unroll
                for (int hr = 0; hr < 2; hr++) {
                    __half hx = __float2half_rn(acc[mt][nt][hr * 2]);
                    __half hy = __float2half_rn(acc[mt][nt][hr * 2 + 1]);
                    size_t idx = (size_t)(r + hr * 8) * CH + c;
                    *(__half2*)(outhi + idx) = __halves2half2(hx, hy);
                }
            }
        }
    }
}

// ================= circulant attention (2-product, cp.async 3-stage V) =======
// oa[b,i,c] = sum_j attn2[(j-i) mod N] * Vhi[j,c],  attn2 = attn/N * OA_SCALE
// attn hi/lo (A-side split), V hi only (B-side).
// dyn smem: A arrays 32768 B + 3 V stages x 9216 B = 60416 B.
#define CIRC_STAGE_BYTES 9216
#define CIRC_SMEM_BYTES (32768 + 3 * CIRC_STAGE_BYTES)

__global__ void __launch_bounds__(256, 2) circ_mma_kernel() {
    extern __shared__ __half dsmh[];
    __half* A2hi  = dsmh;
    __half* A2hiS = dsmh + 4096;
    __half* A2lo  = dsmh + 8192;
    __half* A2loS = dsmh + 12288;
    uint32_t sVu32 = smem_u32(dsmh + 16384);

    int tid = threadIdx.x;
    int i0 = blockIdx.x * 128;
    int h  = blockIdx.y;
    int b  = blockIdx.z;
    int c0 = h * HDIM;
    int w = tid >> 5, lane = tid & 31;
    int wm = w >> 2, wn = w & 3;
    int g = lane >> 2, tig = lane & 3;

    const float* arow = g_attn + (size_t)(b * HEADS + h) * SEQ;
    for (int t = tid; t < SEQ; t += 256) {
        float a = arow[t] * OA_SCALE;
        __half hi = __float2half_rn(a);
        __half lo = __float2half_rn(a - __half2float(hi));
        A2hi[t] = hi;  A2hi[t + SEQ] = hi;
        A2lo[t] = lo;  A2lo[t + SEQ] = lo;
    }
    __syncthreads();
    for (int t = tid; t < 2 * SEQ - 1; t += 256) {
        A2hiS[t] = A2hi[t + 1];
        A2loS[t] = A2lo[t + 1];
    }
    if (tid == 0) { A2hiS[2 * SEQ - 1] = __float2half_rn(0.f); A2loS[2 * SEQ - 1] = __float2half_rn(0.f); }

    int ob = SEQ + 2 * tig - (i0 + wm * 64 + g);
    int par = ob & 1;
    const uint32_t* PhiBase = (const uint32_t*)(par ? A2hiS : A2hi) + ((ob - par) >> 1);
    const uint32_t* PloBase = (const uint32_t*)(par ? A2loS : A2lo) + ((ob - par) >> 1);

    // V loader: thread t -> rows (t>>3, t>>3 + 32), 16B group vcg = t&7
    int vrow = tid >> 3, vcg = tid & 7;
    const __half* gvh = g_vhi + ((size_t)b * SEQ + vrow) * CH + c0 + vcg * 8;
    uint32_t svoA = (uint32_t)((vrow * 72 + vcg * 8) * 2);
    uint32_t svoB = (uint32_t)(((vrow + 32) * 72 + vcg * 8) * 2);

    int mrow = ((lane >> 3) & 1) * 8 + (lane & 7);
    int ncol = wn * 16 + (lane >> 4) * 8;
    uint32_t svAddrPart = (uint32_t)(mrow * 144 + ncol * 2);

    float acc[4][2][4];
    #pragma unroll
    for (int mt = 0; mt < 4; mt++)
        #pragma unroll
        for (int nt = 0; nt < 2; nt++)
            #pragma unroll
            for (int r = 0; r < 4; r++) acc[mt][nt][r] = 0.f;

    // prologue: issue chunks 0,1 into slots 0,1
    #pragma unroll
    for (int p = 0; p < 2; p++) {
        uint32_t st = sVu32 + (uint32_t)p * CIRC_STAGE_BYTES;
        size_t adv = (size_t)p * 64 * CH;
        cp_async16(st + svoA, gvh + adv);
        cp_async16(st + svoB, gvh + adv + 32 * CH);
        CP_COMMIT();
    }
    __syncthreads();   // attn arrays ready (also orders smem fill)

    const int NCHUNK = SEQ / 64;   // 32
    for (int c = 0; c < NCHUNK; c++) {
        if (c + 1 < NCHUNK) { CP_WAIT(1); } else { CP_WAIT(0); }
        __syncthreads();

        // issue chunk c+2 into slot (c+2)%3 (safe: compute c-1 done everywhere)
        if (c + 2 < NCHUNK) {
            uint32_t st = sVu32 + (uint32_t)((c + 2) % 3) * CIRC_STAGE_BYTES;
            size_t adv = (size_t)(c + 2) * 64 * CH;
            cp_async16(st + svoA, gvh + adv);
            cp_async16(st + svoB, gvh + adv + 32 * CH);
            CP_COMMIT();
        }

        const uint32_t* Phi = PhiBase + 32 * c;
        const uint32_t* Plo = PloBase + 32 * c;
        uint32_t ehi[7], elo[7], fhi[8], flo[8];
        #pragma unroll
        for (int t = 0; t < 7; t++) { ehi[t] = Phi[8 * t - 24]; elo[t] = Plo[8 * t - 24]; }
        #pragma unroll
        for (int t = 0; t < 8; t++) { fhi[t] = Phi[8 * t - 28]; flo[t] = Plo[8 * t - 28]; }

        uint32_t sVAddr = sVu32 + (uint32_t)(c % 3) * CIRC_STAGE_BYTES + svAddrPart;

        #pragma unroll
        for (int kk = 0; kk < 4; kk++) {
            uint32_t bh[4];
            ldmatrix_x4_trans(bh, sVAddr + kk * 2304u);
            #pragma unroll
            for (int mt = 0; mt < 4; mt++) {
                int d3 = kk - mt + 3;
                uint32_t ah[4] = {ehi[d3], fhi[d3], fhi[d3 + 1], ehi[d3]};
                uint32_t al[4] = {elo[d3], flo[d3], flo[d3 + 1], elo[d3]};
                mma16816(acc[mt][0], ah, bh);
                mma16816(acc[mt][0], al, bh);
                uint32_t bh1[2] = {bh[2], bh[3]};
                mma16816(acc[mt][1], ah, bh1);
                mma16816(acc[mt][1], al, bh1);
            }
        }
        // no trailing barrier: next iteration's post-wait barrier protects
        // slot reuse (writes target slot (c+3)%3, read last at iter c+... )
    }

    #pragma unroll
    for (int mt = 0; mt < 4; mt++) {
        int r = i0 + wm * 64 + mt * 16 + g;
        #pragma unroll
        for (int nt = 0; nt < 2; nt++) {
            int cc = c0 + wn * 16 + nt * 8 + tig * 2;
            #pragma unroll
            for (int hr = 0; hr < 2; hr++) {
                float vx = acc[mt][nt][hr * 2];
                float vy = acc[mt][nt][hr * 2 + 1];
                __half hx = __float2half_rn(vx);
                __half hy = __float2half_rn(vy);
                __half lx = __float2half_rn(vx - __half2float(hx));
                __half ly = __float2half_rn(vy - __half2float(hy));
                size_t idx = (size_t)(b * SEQ + r + hr * 8) * CH + cc;
                *(__half2*)(g_oahi + idx) = __halves2half2(hx, hy);
                *(__half2*)(g_oalo + idx) = __halves2half2(lx, ly);
            }
        }
    }
}

// ---------------- launch ------------------------------------------------------
extern "C" void kernel_launch(void* const* d_in, const int* in_sizes, int n_in,
                              void* d_out, int out_size) {
    const float* x  = (const float*)d_in[0];
    const float* Wq = (const float*)d_in[1];
    const float* Wk = (const float*)d_in[2];
    const float* Wv = (const float*)d_in[3];
    const float* Wp = (const float*)d_in[4];
    const float* bp = (const float*)d_in[5];
    float* out = (float*)d_out;

    __half* dxhi; cudaGetSymbolAddress((void**)&dxhi,  g_xhi);
    __half* dxlo; cudaGetSymbolAddress((void**)&dxlo,  g_xlo);
    __half* dvhi; cudaGetSymbolAddress((void**)&dvhi,  g_wvhi);
    __half* dphi; cudaGetSymbolAddress((void**)&dphi,  g_wphi);
    __half* dVhi; cudaGetSymbolAddress((void**)&dVhi,  g_vhi);
    __half* dohi; cudaGetSymbolAddress((void**)&dohi,  g_oahi);
    __half* dolo; cudaGetSymbolAddress((void**)&dolo,  g_oalo);

    cudaFuncSetAttribute(circ_mma_kernel,
                         cudaFuncAttributeMaxDynamicSharedMemorySize, CIRC_SMEM_BYTES);
    cudaFuncSetAttribute(gemm_mma_kernel<1>,
                         cudaFuncAttributeMaxDynamicSharedMemorySize, GEMM_SMEM_BYTES);
    cudaFuncSetAttribute(gemm_mma_kernel<2>,
                         cudaFuncAttributeMaxDynamicSharedMemorySize, GEMM_SMEM_BYTES);

    int n4x = BATCH * SEQ * CH / 4;
    int n4w = CH * CH / 4;
    // 1-3) splits (x hi/lo, Wv hi, Wp hi)
    split_kernel<<<(n4x + 255) / 256, 256>>>(x,  dxhi, dxlo, n4x);
    hi_kernel<<<(n4w + 255) / 256, 256>>>(Wv, dvhi, n4w);
    hi_kernel<<<(n4w + 255) / 256, 256>>>(Wp, dphi, n4w);
    // 4) V = x @ Wv^T  (4th launch -> ncu captures this one)
    gemm_mma_kernel<2><<<dim3(CH / 128, (BATCH * SEQ) / 128), 256, GEMM_SMEM_BYTES>>>(
        dxhi, dxlo, dvhi, nullptr, nullptr, dVhi, nullptr, 1.0f);
    // 5-6) x mean over n
    xpart_kernel<<<dim3(128, BATCH), 256>>>(x);
    xmean_kernel<<<BATCH, CH>>>();
    // 7) u = SCALE * Wq(head-block)^T @ K_avg
    u_kernel<<<BATCH * HEADS, 256>>>(Wq, Wk);
    // 8) z = x . u
    z_kernel<<<BATCH * SEQ, 384>>>(x);
    // 9) softmax (+ 1/N fold)
    softmax_kernel<<<BATCH * HEADS, 256>>>();
    // 10) circulant attention -> oa hi/lo (scaled)
    circ_mma_kernel<<<dim3(SEQ / 128, HEADS, BATCH), 256, CIRC_SMEM_BYTES>>>();
    // 11) out = oa @ Wp^T + bp
    gemm_mma_kernel<1><<<dim3(CH / 128, (BATCH * SEQ) / 128), 256, GEMM_SMEM_BYTES>>>(
        dohi, dolo, dphi, bp, out, nullptr, nullptr, OA_INV);
}

// round 11
// speedup vs baseline: 1.9659x; 1.1450x over previous
#include <cuda_runtime.h>
#include <cuda_fp16.h>
#include <cstdint>

#define BATCH 2
#define SEQ   2048
#define CH    768
#define HEADS 12
#define HDIM  64
#define ATT_SCALE 0.125f    // HDIM^-0.5
#define OA_SCALE 4096.0f
#define OA_INV   (1.0f / 4096.0f)

// ---------------- scratch (static device arrays; no cudaMalloc) -------------
__device__ float g_xpart[BATCH * 64 * CH];
__device__ float g_xmean[BATCH * CH];
__device__ float g_u[BATCH * HEADS * CH];
__device__ float g_z[BATCH * HEADS * SEQ];
__device__ float g_attn[BATCH * HEADS * SEQ];

__device__ __half g_xhi[BATCH * SEQ * CH];
__device__ __half g_xlo[BATCH * SEQ * CH];
__device__ __half g_wvhi[CH * CH];
__device__ __half g_wphi[CH * CH];
__device__ __half g_vhi[BATCH * SEQ * CH];
__device__ __half g_oahi[BATCH * SEQ * CH];
__device__ __half g_oalo[BATCH * SEQ * CH];

// ---------------- fp32 -> fp16 hi/lo split ----------------------------------
__global__ void split_kernel(const float* __restrict__ src,
                             __half* __restrict__ hi, __half* __restrict__ lo,
                             int n4) {
    int i = blockIdx.x * 256 + threadIdx.x;
    if (i >= n4) return;
    float4 v = ((const float4*)src)[i];
    __half hx = __float2half_rn(v.x), hy = __float2half_rn(v.y);
    __half hz = __float2half_rn(v.z), hw = __float2half_rn(v.w);
    __half lx = __float2half_rn(v.x - __half2float(hx));
    __half ly = __float2half_rn(v.y - __half2float(hy));
    __half lz = __float2half_rn(v.z - __half2float(hz));
    __half lw = __float2half_rn(v.w - __half2float(hw));
    ((__half2*)hi)[i * 2]     = __halves2half2(hx, hy);
    ((__half2*)hi)[i * 2 + 1] = __halves2half2(hz, hw);
    ((__half2*)lo)[i * 2]     = __halves2half2(lx, ly);
    ((__half2*)lo)[i * 2 + 1] = __halves2half2(lz, lw);
}

// ---------------- fp32 -> fp16 hi only (weights) -----------------------------
__global__ void hi_kernel(const float* __restrict__ src,
                          __half* __restrict__ hi, int n4) {
    int i = blockIdx.x * 256 + threadIdx.x;
    if (i >= n4) return;
    float4 v = ((const float4*)src)[i];
    ((__half2*)hi)[i * 2]     = __halves2half2(__float2half_rn(v.x), __float2half_rn(v.y));
    ((__half2*)hi)[i * 2 + 1] = __halves2half2(__float2half_rn(v.z), __float2half_rn(v.w));
}

// ---------------- 1a: partial sums of x over n (64 chunks of 32 rows) -------
__global__ void xpart_kernel(const float* __restrict__ x) {
    int b = blockIdx.y;
    int chunk = blockIdx.x;           // 0..63
    int c = threadIdx.x;              // 768 threads
    const float* xb = x + ((size_t)b * SEQ + (size_t)chunk * 32) * CH + c;
    float s = 0.f;
    #pragma unroll 8
    for (int n = 0; n < 32; n++) s += xb[(size_t)n * CH];
    g_xpart[(b * 64 + chunk) * CH + c] = s;
}

// ---------------- 1b: reduce partials -> mean -------------------------------
__global__ void xmean_kernel() {
    int b = blockIdx.x;
    int c = threadIdx.x;
    float s = 0.f;
    #pragma unroll 16
    for (int k = 0; k < 64; k++) s += g_xpart[(b * 64 + k) * CH + c];
    g_xmean[b * CH + c] = s * (1.0f / SEQ);
}

// ---------------- 2: u[b,h,c] = SCALE * sum_d Wq[h*64+d,c] * K_avg[b,h,d] ---
__global__ void u_kernel(const float* __restrict__ Wq, const float* __restrict__ Wk) {
    int b = blockIdx.x / HEADS;
    int h = blockIdx.x % HEADS;
    __shared__ float xm[CH];
    __shared__ float kavg[HDIM];
    for (int c = threadIdx.x; c < CH; c += 256) xm[c] = g_xmean[b * CH + c];
    __syncthreads();
    if (threadIdx.x < HDIM) {
        const float* wk = Wk + (size_t)(h * HDIM + threadIdx.x) * CH;
        float s = 0.f;
        #pragma unroll 8
        for (int c = 0; c < CH; c++) s += xm[c] * wk[c];
        kavg[threadIdx.x] = s;
    }
    __syncthreads();
    for (int c = threadIdx.x; c < CH; c += 256) {
        float s = 0.f;
        #pragma unroll 8
        for (int d = 0; d < HDIM; d++)
            s += Wq[(size_t)(h * HDIM + d) * CH + c] * kavg[d];
        g_u[(b * HEADS + h) * CH + c] = s * ATT_SCALE;
    }
}

// ---------------- 3: z[b,h,n] = x[b,n,:] . u[b,h,:]  (8 rows/block) ----------
__global__ void __launch_bounds__(256) z_kernel(const float* __restrict__ x) {
    __shared__ float us[HEADS * CH];     // 36 KB
    int b = blockIdx.y;
    int tid = threadIdx.x;
    for (int i = tid; i < HEADS * CH; i += 256) us[i] = g_u[b * HEADS * CH + i];
    __syncthreads();
    int wid = tid >> 5, lane = tid & 31;
    int n = blockIdx.x * 8 + wid;
    const float* xr = x + ((size_t)b * SEQ + n) * CH;
    float xv[24];
    #pragma unroll
    for (int i = 0; i < 24; i++) xv[i] = xr[lane + i * 32];
    #pragma unroll
    for (int h = 0; h < HEADS; h++) {
        const float* uh = us + h * CH;
        float s = 0.f;
        #pragma unroll
        for (int i = 0; i < 24; i++) s += xv[i] * uh[lane + i * 32];
        #pragma unroll
        for (int off = 16; off > 0; off >>= 1)
            s += __shfl_down_sync(0xffffffffu, s, off);
        if (lane == 0) g_z[(b * HEADS + h) * SEQ + n] = s;
    }
}

// ---------------- 4: softmax over n per (b,h), fold 1/SEQ --------------------
__global__ void softmax_kernel() {
    __shared__ float red[256];
    int base = blockIdx.x * SEQ;
    int tid = threadIdx.x;
    float v[8];
    float m = -1e30f;
    #pragma unroll
    for (int k = 0; k < 8; k++) {
        v[k] = g_z[base + tid + k * 256];
        m = fmaxf(m, v[k]);
    }
    red[tid] = m; __syncthreads();
    for (int s = 128; s > 0; s >>= 1) {
        if (tid < s) red[tid] = fmaxf(red[tid], red[tid + s]);
        __syncthreads();
    }
    m = red[0]; __syncthreads();
    float sum = 0.f;
    #pragma unroll
    for (int k = 0; k < 8; k++) { v[k] = __expf(v[k] - m); sum += v[k]; }
    red[tid] = sum; __syncthreads();
    for (int s = 128; s > 0; s >>= 1) {
        if (tid < s) red[tid] += red[tid + s];
        __syncthreads();
    }
    float inv = 1.0f / (red[0] * (float)SEQ);
    #pragma unroll
    for (int k = 0; k < 8; k++) g_attn[base + tid + k * 256] = v[k] * inv;
}

// ================= warp-MMA building blocks ==================================
__device__ __forceinline__ void mma16816(float* c, const uint32_t* a, const uint32_t* b) {
    asm volatile(
        "mma.sync.aligned.m16n8k16.row.col.f32.f16.f16.f32 "
        "{%0,%1,%2,%3}, {%4,%5,%6,%7}, {%8,%9}, {%0,%1,%2,%3};\n"
        : "+f"(c[0]), "+f"(c[1]), "+f"(c[2]), "+f"(c[3])
        : "r"(a[0]), "r"(a[1]), "r"(a[2]), "r"(a[3]), "r"(b[0]), "r"(b[1]));
}

__device__ __forceinline__ uint32_t smem_u32(const void* p) {
    uint32_t a;
    asm("{ .reg .u64 t; cvta.to.shared.u64 t, %1; cvt.u32.u64 %0, t; }"
        : "=r"(a) : "l"(p));
    return a;
}

__device__ __forceinline__ void ldmatrix_x4(uint32_t* r, uint32_t addr) {
    asm volatile(
        "ldmatrix.sync.aligned.m8n8.x4.shared.b16 {%0,%1,%2,%3}, [%4];"
        : "=r"(r[0]), "=r"(r[1]), "=r"(r[2]), "=r"(r[3]) : "r"(addr));
}

__device__ __forceinline__ void ldmatrix_x4_trans(uint32_t* r, uint32_t addr) {
    asm volatile(
        "ldmatrix.sync.aligned.m8n8.x4.trans.shared.b16 {%0,%1,%2,%3}, [%4];"
        : "=r"(r[0]), "=r"(r[1]), "=r"(r[2]), "=r"(r[3]) : "r"(addr));
}

__device__ __forceinline__ void cp_async16(uint32_t smem_addr, const void* gptr) {
    asm volatile("cp.async.cg.shared.global [%0], [%1], 16;"
                 :: "r"(smem_addr), "l"(gptr) : "memory");
}
#define CP_COMMIT()  asm volatile("cp.async.commit_group;" ::: "memory")
#define CP_WAIT(N)   asm volatile("cp.async.wait_group %0;" :: "n"(N) : "memory")

// ================= warp-MMA 2-product GEMM (cp.async 3-stage) ================
#define GEMM_STAGE_BYTES 30720
#define GEMM_SMEM_BYTES  (3 * GEMM_STAGE_BYTES)

template <int MODE>
__global__ void __launch_bounds__(256, 2) gemm_mma_kernel(
    const __half* __restrict__ Ahi, const __half* __restrict__ Alo,
    const __half* __restrict__ Bhi,
    const float* __restrict__ bias, float* __restrict__ out,
    __half* __restrict__ outhi, __half* __restrict__ outlo, float outscale)
{
    extern __shared__ uint32_t dsm[];
    uint32_t sbase = smem_u32(dsm);

    int tid = threadIdx.x;
    int m0 = blockIdx.y * 128;
    int n0 = blockIdx.x * 128;
    int w = tid >> 5, lane = tid & 31;
    int wm = w >> 2, wn = w & 3;
    int g = lane >> 2, tig = lane & 3;

    float acc[4][4][4];
    #pragma unroll
    for (int mt = 0; mt < 4; mt++)
        #pragma unroll
        for (int nt = 0; nt < 4; nt++)
            #pragma unroll
            for (int r = 0; r < 4; r++) acc[mt][nt][r] = 0.f;

    int lrow = tid >> 2;
    int q = tid & 3;
    uint32_t sdst0 = (uint32_t)(lrow * 80 + q * 16);
    uint32_t sdst1 = (uint32_t)((lrow + 64) * 80 + q * 16);
    size_t goffA0 = (size_t)(m0 + lrow) * CH + q * 8;
    size_t goffA1 = (size_t)(m0 + lrow + 64) * CH + q * 8;
    size_t goffB0 = (size_t)(n0 + lrow) * CH + q * 8;
    size_t goffB1 = (size_t)(n0 + lrow + 64) * CH + q * 8;

    int sub = lane >> 3, lr = lane & 7;
    int aRow = wm * 64 + ((sub & 1) << 3) + lr;
    int aKs  = sub >> 1;
    uint32_t aOffBase = (uint32_t)(aRow * 80 + aKs * 16);
    int bRow = wn * 32 + (((sub >> 1) & 1) << 3) + lr;
    int bKs  = sub & 1;
    uint32_t bOffBase = (uint32_t)(bRow * 80 + bKs * 16);

    const int NSTAGE = CH / 32;   // 24

    #pragma unroll
    for (int p = 0; p < 2; p++) {
        uint32_t st = sbase + (uint32_t)p * GEMM_STAGE_BYTES;
        size_t ka = (size_t)p * 32;
        cp_async16(st + sdst0,          Ahi + goffA0 + ka);
        cp_async16(st + sdst1,          Ahi + goffA1 + ka);
        cp_async16(st + 10240 + sdst0,  Alo + goffA0 + ka);
        cp_async16(st + 10240 + sdst1,  Alo + goffA1 + ka);
        cp_async16(st + 20480 + sdst0,  Bhi + goffB0 + ka);
        cp_async16(st + 20480 + sdst1,  Bhi + goffB1 + ka);
        CP_COMMIT();
    }

    int sslot = 0;
    for (int s = 0; s < NSTAGE; s++) {
        if (s + 1 < NSTAGE) { CP_WAIT(1); } else { CP_WAIT(0); }
        __syncthreads();

        if (s + 2 < NSTAGE) {
            int tgt = (sslot + 2) % 3;
            uint32_t st2 = sbase + (uint32_t)tgt * GEMM_STAGE_BYTES;
            size_t ka = (size_t)(s + 2) * 32;
            cp_async16(st2 + sdst0,          Ahi + goffA0 + ka);
            cp_async16(st2 + sdst1,          Ahi + goffA1 + ka);
            cp_async16(st2 + 10240 + sdst0,  Alo + goffA0 + ka);
            cp_async16(st2 + 10240 + sdst1,  Alo + goffA1 + ka);
            cp_async16(st2 + 20480 + sdst0,  Bhi + goffB0 + ka);
            cp_async16(st2 + 20480 + sdst1,  Bhi + goffB1 + ka);
            CP_COMMIT();
        }

        uint32_t st = sbase + (uint32_t)sslot * GEMM_STAGE_BYTES;
        uint32_t uAhi = st, uAlo = st + 10240u, uBhi = st + 20480u;

        #pragma unroll
        for (int kk = 0; kk < 2; kk++) {
            uint32_t kadd = (uint32_t)(kk * 32);
            uint32_t bh[4][2];
            #pragma unroll
            for (int np = 0; np < 2; np++) {
                uint32_t r4[4];
                uint32_t boff = bOffBase + kadd + (uint32_t)(np * 16 * 80);
                ldmatrix_x4(r4, uBhi + boff);
                bh[np * 2][0] = r4[0];      bh[np * 2][1] = r4[1];
                bh[np * 2 + 1][0] = r4[2];  bh[np * 2 + 1][1] = r4[3];
            }
            #pragma unroll
            for (int mt = 0; mt < 4; mt++) {
                uint32_t aoff = aOffBase + kadd + (uint32_t)(mt * 16 * 80);
                uint32_t ah[4], al[4];
                ldmatrix_x4(ah, uAhi + aoff);
                ldmatrix_x4(al, uAlo + aoff);
                #pragma unroll
                for (int nt = 0; nt < 4; nt++) {
                    mma16816(acc[mt][nt], ah, bh[nt]);
                    mma16816(acc[mt][nt], al, bh[nt]);
                }
            }
        }
        __syncthreads();
        sslot = (sslot + 1) % 3;
    }

    #pragma unroll
    for (int mt = 0; mt < 4; mt++) {
        int r = m0 + wm * 64 + mt * 16 + g;
        #pragma unroll
        for (int nt = 0; nt < 4; nt++) {
            int c = n0 + wn * 32 + nt * 8 + tig * 2;
            if (MODE == 1) {
                float2 v0, v1;
                v0.x = acc[mt][nt][0] * outscale + bias[c];
                v0.y = acc[mt][nt][1] * outscale + bias[c + 1];
                v1.x = acc[mt][nt][2] * outscale + bias[c];
                v1.y = acc[mt][nt][3] * outscale + bias[c + 1];
                *(float2*)(out + (size_t)r * CH + c)       = v0;
                *(float2*)(out + (size_t)(r + 8) * CH + c) = v1;
            } else {
                #pragma unroll
                for (int hr = 0; hr < 2; hr++) {
                    __half hx = __float2half_rn(acc[mt][nt][hr * 2]);
                    __half hy = __float2half_rn(acc[mt][nt][hr * 2 + 1]);
                    size_t idx = (size_t)(r + hr * 8) * CH + c;
                    *(__half2*)(outhi + idx) = __halves2half2(hx, hy);
                }
            }
        }
    }
}

// ================= circulant attention (1-product, cp.async 3-stage V) =======
// oa[b,i,c] = sum_j attn2[(j-i) mod N] * Vhi[j,c],  attn2 = attn/N * OA_SCALE
// attn hi only (A-side), V hi only (B-side). Single MMA product.
// dyn smem: A arrays 16384 B + 3 V stages x 9216 B = 44032 B.
#define CIRC_STAGE_BYTES 9216
#define CIRC_SMEM_BYTES (16384 + 3 * CIRC_STAGE_BYTES)

__global__ void __launch_bounds__(256, 2) circ_mma_kernel() {
    extern __shared__ __half dsmh[];
    __half* A2hi  = dsmh;
    __half* A2hiS = dsmh + 4096;
    uint32_t sVu32 = smem_u32(dsmh + 8192);

    int tid = threadIdx.x;
    int i0 = blockIdx.x * 128;
    int h  = blockIdx.y;
    int b  = blockIdx.z;
    int c0 = h * HDIM;
    int w = tid >> 5, lane = tid & 31;
    int wm = w >> 2, wn = w & 3;
    int g = lane >> 2, tig = lane & 3;

    const float* arow = g_attn + (size_t)(b * HEADS + h) * SEQ;
    for (int t = tid; t < SEQ; t += 256) {
        __half hi = __float2half_rn(arow[t] * OA_SCALE);
        A2hi[t] = hi;  A2hi[t + SEQ] = hi;
    }
    __syncthreads();
    for (int t = tid; t < 2 * SEQ - 1; t += 256) A2hiS[t] = A2hi[t + 1];
    if (tid == 0) A2hiS[2 * SEQ - 1] = __float2half_rn(0.f);

    int ob = SEQ + 2 * tig - (i0 + wm * 64 + g);
    int par = ob & 1;
    const uint32_t* PhiBase = (const uint32_t*)(par ? A2hiS : A2hi) + ((ob - par) >> 1);

    int vrow = tid >> 3, vcg = tid & 7;
    const __half* gvh = g_vhi + ((size_t)b * SEQ + vrow) * CH + c0 + vcg * 8;
    uint32_t svoA = (uint32_t)((vrow * 72 + vcg * 8) * 2);
    uint32_t svoB = (uint32_t)(((vrow + 32) * 72 + vcg * 8) * 2);

    int mrow = ((lane >> 3) & 1) * 8 + (lane & 7);
    int ncol = wn * 16 + (lane >> 4) * 8;
    uint32_t svAddrPart = (uint32_t)(mrow * 144 + ncol * 2);

    float acc[4][2][4];
    #pragma unroll
    for (int mt = 0; mt < 4; mt++)
        #pragma unroll
        for (int nt = 0; nt < 2; nt++)
            #pragma unroll
            for (int r = 0; r < 4; r++) acc[mt][nt][r] = 0.f;

    #pragma unroll
    for (int p = 0; p < 2; p++) {
        uint32_t st = sVu32 + (uint32_t)p * CIRC_STAGE_BYTES;
        size_t adv = (size_t)p * 64 * CH;
        cp_async16(st + svoA, gvh + adv);
        cp_async16(st + svoB, gvh + adv + 32 * CH);
        CP_COMMIT();
    }
    __syncthreads();

    const int NCHUNK = SEQ / 64;   // 32
    for (int c = 0; c < NCHUNK; c++) {
        if (c + 1 < NCHUNK) { CP_WAIT(1); } else { CP_WAIT(0); }
        __syncthreads();

        if (c + 2 < NCHUNK) {
            uint32_t st = sVu32 + (uint32_t)((c + 2) % 3) * CIRC_STAGE_BYTES;
            size_t adv = (size_t)(c + 2) * 64 * CH;
            cp_async16(st + svoA, gvh + adv);
            cp_async16(st + svoB, gvh + adv + 32 * CH);
            CP_COMMIT();
        }

        const uint32_t* Phi = PhiBase + 32 * c;
        uint32_t ehi[7], fhi[8];
        #pragma unroll
        for (int t = 0; t < 7; t++) ehi[t] = Phi[8 * t - 24];
        #pragma unroll
        for (int t = 0; t < 8; t++) fhi[t] = Phi[8 * t - 28];

        uint32_t sVAddr = sVu32 + (uint32_t)(c % 3) * CIRC_STAGE_BYTES + svAddrPart;

        #pragma unroll
        for (int kk = 0; kk < 4; kk++) {
            uint32_t bh[4];
            ldmatrix_x4_trans(bh, sVAddr + kk * 2304u);
            #pragma unroll
            for (int mt = 0; mt < 4; mt++) {
                int d3 = kk - mt + 3;
                uint32_t ah[4] = {ehi[d3], fhi[d3], fhi[d3 + 1], ehi[d3]};
                mma16816(acc[mt][0], ah, bh);
                uint32_t bh1[2] = {bh[2], bh[3]};
                mma16816(acc[mt][1], ah, bh1);
            }
        }
    }

    #pragma unroll
    for (int mt = 0; mt < 4; mt++) {
        int r = i0 + wm * 64 + mt * 16 + g;
        #pragma unroll
        for (int nt = 0; nt < 2; nt++) {
            int cc = c0 + wn * 16 + nt * 8 + tig * 2;
            #pragma unroll
            for (int hr = 0; hr < 2; hr++) {
                float vx = acc[mt][nt][hr * 2];
                float vy = acc[mt][nt][hr * 2 + 1];
                __half hx = __float2half_rn(vx);
                __half hy = __float2half_rn(vy);
                __half lx = __float2half_rn(vx - __half2float(hx));
                __half ly = __float2half_rn(vy - __half2float(hy));
                size_t idx = (size_t)(b * SEQ + r + hr * 8) * CH + cc;
                *(__half2*)(g_oahi + idx) = __halves2half2(hx, hy);
                *(__half2*)(g_oalo + idx) = __halves2half2(lx, ly);
            }
        }
    }
}

// ---------------- launch ------------------------------------------------------
extern "C" void kernel_launch(void* const* d_in, const int* in_sizes, int n_in,
                              void* d_out, int out_size) {
    const float* x  = (const float*)d_in[0];
    const float* Wq = (const float*)d_in[1];
    const float* Wk = (const float*)d_in[2];
    const float* Wv = (const float*)d_in[3];
    const float* Wp = (const float*)d_in[4];
    const float* bp = (const float*)d_in[5];
    float* out = (float*)d_out;

    __half* dxhi; cudaGetSymbolAddress((void**)&dxhi,  g_xhi);
    __half* dxlo; cudaGetSymbolAddress((void**)&dxlo,  g_xlo);
    __half* dvhi; cudaGetSymbolAddress((void**)&dvhi,  g_wvhi);
    __half* dphi; cudaGetSymbolAddress((void**)&dphi,  g_wphi);
    __half* dVhi; cudaGetSymbolAddress((void**)&dVhi,  g_vhi);
    __half* dohi; cudaGetSymbolAddress((void**)&dohi,  g_oahi);
    __half* dolo; cudaGetSymbolAddress((void**)&dolo,  g_oalo);

    cudaFuncSetAttribute(circ_mma_kernel,
                         cudaFuncAttributeMaxDynamicSharedMemorySize, CIRC_SMEM_BYTES);
    cudaFuncSetAttribute(gemm_mma_kernel<1>,
                         cudaFuncAttributeMaxDynamicSharedMemorySize, GEMM_SMEM_BYTES);
    cudaFuncSetAttribute(gemm_mma_kernel<2>,
                         cudaFuncAttributeMaxDynamicSharedMemorySize, GEMM_SMEM_BYTES);

    int n4x = BATCH * SEQ * CH / 4;
    int n4w = CH * CH / 4;
    // 1-3) splits (x hi/lo, Wv hi, Wp hi)
    split_kernel<<<(n4x + 255) / 256, 256>>>(x,  dxhi, dxlo, n4x);
    hi_kernel<<<(n4w + 255) / 256, 256>>>(Wv, dvhi, n4w);
    hi_kernel<<<(n4w + 255) / 256, 256>>>(Wp, dphi, n4w);
    // 4) V = x @ Wv^T  (4th launch -> ncu captures this one)
    gemm_mma_kernel<2><<<dim3(CH / 128, (BATCH * SEQ) / 128), 256, GEMM_SMEM_BYTES>>>(
        dxhi, dxlo, dvhi, nullptr, nullptr, dVhi, nullptr, 1.0f);
    // 5-6) x mean over n
    xpart_kernel<<<dim3(64, BATCH), CH>>>(x);
    xmean_kernel<<<BATCH, CH>>>();
    // 7) u = SCALE * Wq(head-block)^T @ K_avg
    u_kernel<<<BATCH * HEADS, 256>>>(Wq, Wk);
    // 8) z = x . u
    z_kernel<<<dim3(SEQ / 8, BATCH), 256>>>(x);
    // 9) softmax (+ 1/N fold)
    softmax_kernel<<<BATCH * HEADS, 256>>>();
    // 10) circulant attention -> oa hi/lo (scaled)
    circ_mma_kernel<<<dim3(SEQ / 128, HEADS, BATCH), 256, CIRC_SMEM_BYTES>>>();
    // 11) out = oa @ Wp^T + bp
    gemm_mma_kernel<1><<<dim3(CH / 128, (BATCH * SEQ) / 128), 256, GEMM_SMEM_BYTES>>>(
        dohi, dolo, dphi, bp, out, nullptr, nullptr, OA_INV);
}

// round 12
// speedup vs baseline: 2.5512x; 1.2977x over previous
#include <cuda_runtime.h>
#include <cuda_fp16.h>
#include <cstdint>

#define BATCH 2
#define SEQ   2048
#define CH    768
#define HEADS 12
#define HDIM  64
#define ATT_SCALE 0.125f    // HDIM^-0.5
#define OA_SCALE 4096.0f
#define OA_INV   (1.0f / 4096.0f)

// ---------------- scratch (static device arrays; no cudaMalloc) -------------
__device__ float g_xpart[BATCH * 64 * CH];
__device__ float g_xmean[BATCH * CH];
__device__ float g_u[BATCH * HEADS * CH];
__device__ float g_z[BATCH * HEADS * SEQ];
__device__ float g_attn[BATCH * HEADS * SEQ];

__device__ __half g_xhi[BATCH * SEQ * CH];
__device__ __half g_wvhi[CH * CH];
__device__ __half g_wphi[CH * CH];
__device__ __half g_vhi[BATCH * SEQ * CH];
__device__ __half g_oahi[BATCH * SEQ * CH];

// ---------------- fp32 -> fp16 hi only ---------------------------------------
__global__ void hi_kernel(const float* __restrict__ src,
                          __half* __restrict__ hi, int n4) {
    int i = blockIdx.x * 256 + threadIdx.x;
    if (i >= n4) return;
    float4 v = ((const float4*)src)[i];
    ((__half2*)hi)[i * 2]     = __halves2half2(__float2half_rn(v.x), __float2half_rn(v.y));
    ((__half2*)hi)[i * 2 + 1] = __halves2half2(__float2half_rn(v.z), __float2half_rn(v.w));
}

// ---------------- 1a: partial sums of x over n (64 chunks of 32 rows) -------
__global__ void xpart_kernel(const float* __restrict__ x) {
    int b = blockIdx.y;
    int chunk = blockIdx.x;           // 0..63
    int c = threadIdx.x;              // 768 threads
    const float* xb = x + ((size_t)b * SEQ + (size_t)chunk * 32) * CH + c;
    float s = 0.f;
    #pragma unroll 8
    for (int n = 0; n < 32; n++) s += xb[(size_t)n * CH];
    g_xpart[(b * 64 + chunk) * CH + c] = s;
}

// ---------------- 1b: reduce partials -> mean -------------------------------
__global__ void xmean_kernel() {
    int b = blockIdx.x;
    int c = threadIdx.x;
    float s = 0.f;
    #pragma unroll 16
    for (int k = 0; k < 64; k++) s += g_xpart[(b * 64 + k) * CH + c];
    g_xmean[b * CH + c] = s * (1.0f / SEQ);
}

// ---------------- 2: u[b,h,c] = SCALE * sum_d Wq[h*64+d,c] * K_avg[b,h,d] ---
__global__ void u_kernel(const float* __restrict__ Wq, const float* __restrict__ Wk) {
    int b = blockIdx.x / HEADS;
    int h = blockIdx.x % HEADS;
    __shared__ float xm[CH];
    __shared__ float kavg[HDIM];
    for (int c = threadIdx.x; c < CH; c += 256) xm[c] = g_xmean[b * CH + c];
    __syncthreads();
    if (threadIdx.x < HDIM) {
        const float* wk = Wk + (size_t)(h * HDIM + threadIdx.x) * CH;
        float s = 0.f;
        #pragma unroll 8
        for (int c = 0; c < CH; c++) s += xm[c] * wk[c];
        kavg[threadIdx.x] = s;
    }
    __syncthreads();
    for (int c = threadIdx.x; c < CH; c += 256) {
        float s = 0.f;
        #pragma unroll 8
        for (int d = 0; d < HDIM; d++)
            s += Wq[(size_t)(h * HDIM + d) * CH + c] * kavg[d];
        g_u[(b * HEADS + h) * CH + c] = s * ATT_SCALE;
    }
}

// ---------------- 3: z[b,h,n] = x[b,n,:] . u[b,h,:]  (8 rows/block) ----------
__global__ void __launch_bounds__(256) z_kernel(const float* __restrict__ x) {
    __shared__ float us[HEADS * CH];     // 36 KB
    int b = blockIdx.y;
    int tid = threadIdx.x;
    for (int i = tid; i < HEADS * CH; i += 256) us[i] = g_u[b * HEADS * CH + i];
    __syncthreads();
    int wid = tid >> 5, lane = tid & 31;
    int n = blockIdx.x * 8 + wid;
    const float* xr = x + ((size_t)b * SEQ + n) * CH;
    float xv[24];
    #pragma unroll
    for (int i = 0; i < 24; i++) xv[i] = xr[lane + i * 32];
    #pragma unroll
    for (int h = 0; h < HEADS; h++) {
        const float* uh = us + h * CH;
        float s = 0.f;
        #pragma unroll
        for (int i = 0; i < 24; i++) s += xv[i] * uh[lane + i * 32];
        #pragma unroll
        for (int off = 16; off > 0; off >>= 1)
            s += __shfl_down_sync(0xffffffffu, s, off);
        if (lane == 0) g_z[(b * HEADS + h) * SEQ + n] = s;
    }
}

// ---------------- 4: softmax over n per (b,h), fold 1/SEQ --------------------
__global__ void softmax_kernel() {
    __shared__ float red[256];
    int base = blockIdx.x * SEQ;
    int tid = threadIdx.x;
    float v[8];
    float m = -1e30f;
    #pragma unroll
    for (int k = 0; k < 8; k++) {
        v[k] = g_z[base + tid + k * 256];
        m = fmaxf(m, v[k]);
    }
    red[tid] = m; __syncthreads();
    for (int s = 128; s > 0; s >>= 1) {
        if (tid < s) red[tid] = fmaxf(red[tid], red[tid + s]);
        __syncthreads();
    }
    m = red[0]; __syncthreads();
    float sum = 0.f;
    #pragma unroll
    for (int k = 0; k < 8; k++) { v[k] = __expf(v[k] - m); sum += v[k]; }
    red[tid] = sum; __syncthreads();
    for (int s = 128; s > 0; s >>= 1) {
        if (tid < s) red[tid] += red[tid + s];
        __syncthreads();
    }
    float inv = 1.0f / (red[0] * (float)SEQ);
    #pragma unroll
    for (int k = 0; k < 8; k++) g_attn[base + tid + k * 256] = v[k] * inv;
}

// ================= warp-MMA building blocks ==================================
__device__ __forceinline__ void mma16816(float* c, const uint32_t* a, const uint32_t* b) {
    asm volatile(
        "mma.sync.aligned.m16n8k16.row.col.f32.f16.f16.f32 "
        "{%0,%1,%2,%3}, {%4,%5,%6,%7}, {%8,%9}, {%0,%1,%2,%3};\n"
        : "+f"(c[0]), "+f"(c[1]), "+f"(c[2]), "+f"(c[3])
        : "r"(a[0]), "r"(a[1]), "r"(a[2]), "r"(a[3]), "r"(b[0]), "r"(b[1]));
}

__device__ __forceinline__ uint32_t smem_u32(const void* p) {
    uint32_t a;
    asm("{ .reg .u64 t; cvta.to.shared.u64 t, %1; cvt.u32.u64 %0, t; }"
        : "=r"(a) : "l"(p));
    return a;
}

__device__ __forceinline__ void ldmatrix_x4(uint32_t* r, uint32_t addr) {
    asm volatile(
        "ldmatrix.sync.aligned.m8n8.x4.shared.b16 {%0,%1,%2,%3}, [%4];"
        : "=r"(r[0]), "=r"(r[1]), "=r"(r[2]), "=r"(r[3]) : "r"(addr));
}

__device__ __forceinline__ void ldmatrix_x4_trans(uint32_t* r, uint32_t addr) {
    asm volatile(
        "ldmatrix.sync.aligned.m8n8.x4.trans.shared.b16 {%0,%1,%2,%3}, [%4];"
        : "=r"(r[0]), "=r"(r[1]), "=r"(r[2]), "=r"(r[3]) : "r"(addr));
}

__device__ __forceinline__ void cp_async16(uint32_t smem_addr, const void* gptr) {
    asm volatile("cp.async.cg.shared.global [%0], [%1], 16;"
                 :: "r"(smem_addr), "l"(gptr) : "memory");
}
#define CP_COMMIT()  asm volatile("cp.async.commit_group;" ::: "memory")
#define CP_WAIT(N)   asm volatile("cp.async.wait_group %0;" :: "n"(N) : "memory")

// ================= warp-MMA fp16 GEMM (1-product, cp.async 3-stage) ==========
// out = Ahi[M,768] @ (Bhi[768,768])^T, fp32 accum.
// MODE 1: fp32 out + bias (* outscale). MODE 2: fp16 hi out.
#define GEMM_STAGE_BYTES 20480
#define GEMM_SMEM_BYTES  (3 * GEMM_STAGE_BYTES)

template <int MODE>
__global__ void __launch_bounds__(256, 2) gemm_mma_kernel(
    const __half* __restrict__ Ahi,
    const __half* __restrict__ Bhi,
    const float* __restrict__ bias, float* __restrict__ out,
    __half* __restrict__ outhi, float outscale)
{
    extern __shared__ uint32_t dsm[];
    uint32_t sbase = smem_u32(dsm);
    // within a stage: Ahi @0 (10240 B), Bhi @10240

    int tid = threadIdx.x;
    int m0 = blockIdx.y * 128;
    int n0 = blockIdx.x * 128;
    int w = tid >> 5, lane = tid & 31;
    int wm = w >> 2, wn = w & 3;
    int g = lane >> 2, tig = lane & 3;

    float acc[4][4][4];
    #pragma unroll
    for (int mt = 0; mt < 4; mt++)
        #pragma unroll
        for (int nt = 0; nt < 4; nt++)
            #pragma unroll
            for (int r = 0; r < 4; r++) acc[mt][nt][r] = 0.f;

    int lrow = tid >> 2;
    int q = tid & 3;
    uint32_t sdst0 = (uint32_t)(lrow * 80 + q * 16);
    uint32_t sdst1 = (uint32_t)((lrow + 64) * 80 + q * 16);
    size_t goffA0 = (size_t)(m0 + lrow) * CH + q * 8;
    size_t goffA1 = (size_t)(m0 + lrow + 64) * CH + q * 8;
    size_t goffB0 = (size_t)(n0 + lrow) * CH + q * 8;
    size_t goffB1 = (size_t)(n0 + lrow + 64) * CH + q * 8;

    int sub = lane >> 3, lr = lane & 7;
    int aRow = wm * 64 + ((sub & 1) << 3) + lr;
    int aKs  = sub >> 1;
    uint32_t aOffBase = (uint32_t)(aRow * 80 + aKs * 16);
    int bRow = wn * 32 + (((sub >> 1) & 1) << 3) + lr;
    int bKs  = sub & 1;
    uint32_t bOffBase = (uint32_t)(bRow * 80 + bKs * 16);

    const int NSTAGE = CH / 32;   // 24

    #pragma unroll
    for (int p = 0; p < 2; p++) {
        uint32_t st = sbase + (uint32_t)p * GEMM_STAGE_BYTES;
        size_t ka = (size_t)p * 32;
        cp_async16(st + sdst0,          Ahi + goffA0 + ka);
        cp_async16(st + sdst1,          Ahi + goffA1 + ka);
        cp_async16(st + 10240 + sdst0,  Bhi + goffB0 + ka);
        cp_async16(st + 10240 + sdst1,  Bhi + goffB1 + ka);
        CP_COMMIT();
    }

    int sslot = 0;
    for (int s = 0; s < NSTAGE; s++) {
        if (s + 1 < NSTAGE) { CP_WAIT(1); } else { CP_WAIT(0); }
        __syncthreads();

        if (s + 2 < NSTAGE) {
            int tgt = (sslot + 2) % 3;
            uint32_t st2 = sbase + (uint32_t)tgt * GEMM_STAGE_BYTES;
            size_t ka = (size_t)(s + 2) * 32;
            cp_async16(st2 + sdst0,          Ahi + goffA0 + ka);
            cp_async16(st2 + sdst1,          Ahi + goffA1 + ka);
            cp_async16(st2 + 10240 + sdst0,  Bhi + goffB0 + ka);
            cp_async16(st2 + 10240 + sdst1,  Bhi + goffB1 + ka);
            CP_COMMIT();
        }

        uint32_t st = sbase + (uint32_t)sslot * GEMM_STAGE_BYTES;
        uint32_t uAhi = st, uBhi = st + 10240u;

        #pragma unroll
        for (int kk = 0; kk < 2; kk++) {
            uint32_t kadd = (uint32_t)(kk * 32);
            uint32_t bh[4][2];
            #pragma unroll
            for (int np = 0; np < 2; np++) {
                uint32_t r4[4];
                uint32_t boff = bOffBase + kadd + (uint32_t)(np * 16 * 80);
                ldmatrix_x4(r4, uBhi + boff);
                bh[np * 2][0] = r4[0];      bh[np * 2][1] = r4[1];
                bh[np * 2 + 1][0] = r4[2];  bh[np * 2 + 1][1] = r4[3];
            }
            #pragma unroll
            for (int mt = 0; mt < 4; mt++) {
                uint32_t aoff = aOffBase + kadd + (uint32_t)(mt * 16 * 80);
                uint32_t ah[4];
                ldmatrix_x4(ah, uAhi + aoff);
                #pragma unroll
                for (int nt = 0; nt < 4; nt++)
                    mma16816(acc[mt][nt], ah, bh[nt]);
            }
        }
        __syncthreads();
        sslot = (sslot + 1) % 3;
    }

    #pragma unroll
    for (int mt = 0; mt < 4; mt++) {
        int r = m0 + wm * 64 + mt * 16 + g;
        #pragma unroll
        for (int nt = 0; nt < 4; nt++) {
            int c = n0 + wn * 32 + nt * 8 + tig * 2;
            if (MODE == 1) {
                float2 v0, v1;
                v0.x = acc[mt][nt][0] * outscale + bias[c];
                v0.y = acc[mt][nt][1] * outscale + bias[c + 1];
                v1.x = acc[mt][nt][2] * outscale + bias[c];
                v1.y = acc[mt][nt][3] * outscale + bias[c + 1];
                *(float2*)(out + (size_t)r * CH + c)       = v0;
                *(float2*)(out + (size_t)(r + 8) * CH + c) = v1;
            } else {
                #pragma unroll
                for (int hr = 0; hr < 2; hr++) {
                    __half hx = __float2half_rn(acc[mt][nt][hr * 2]);
                    __half hy = __float2half_rn(acc[mt][nt][hr * 2 + 1]);
                    size_t idx = (size_t)(r + hr * 8) * CH + c;
                    *(__half2*)(outhi + idx) = __halves2half2(hx, hy);
                }
            }
        }
    }
}

// ================= circulant attention (1-product, cp.async 3-stage V) =======
// oa[b,i,c] = sum_j attn2[(j-i) mod N] * Vhi[j,c],  attn2 = attn/N * OA_SCALE
// dyn smem: A arrays 16384 B + 3 V stages x 9216 B = 44032 B.
#define CIRC_STAGE_BYTES 9216
#define CIRC_SMEM_BYTES (16384 + 3 * CIRC_STAGE_BYTES)

__global__ void __launch_bounds__(256, 2) circ_mma_kernel() {
    extern __shared__ __half dsmh[];
    __half* A2hi  = dsmh;
    __half* A2hiS = dsmh + 4096;
    uint32_t sVu32 = smem_u32(dsmh + 8192);

    int tid = threadIdx.x;
    int i0 = blockIdx.x * 128;
    int h  = blockIdx.y;
    int b  = blockIdx.z;
    int c0 = h * HDIM;
    int w = tid >> 5, lane = tid & 31;
    int wm = w >> 2, wn = w & 3;
    int g = lane >> 2, tig = lane & 3;

    const float* arow = g_attn + (size_t)(b * HEADS + h) * SEQ;
    for (int t = tid; t < SEQ; t += 256) {
        __half hi = __float2half_rn(arow[t] * OA_SCALE);
        A2hi[t] = hi;  A2hi[t + SEQ] = hi;
    }
    __syncthreads();
    for (int t = tid; t < 2 * SEQ - 1; t += 256) A2hiS[t] = A2hi[t + 1];
    if (tid == 0) A2hiS[2 * SEQ - 1] = __float2half_rn(0.f);

    int ob = SEQ + 2 * tig - (i0 + wm * 64 + g);
    int par = ob & 1;
    const uint32_t* PhiBase = (const uint32_t*)(par ? A2hiS : A2hi) + ((ob - par) >> 1);

    int vrow = tid >> 3, vcg = tid & 7;
    const __half* gvh = g_vhi + ((size_t)b * SEQ + vrow) * CH + c0 + vcg * 8;
    uint32_t svoA = (uint32_t)((vrow * 72 + vcg * 8) * 2);
    uint32_t svoB = (uint32_t)(((vrow + 32) * 72 + vcg * 8) * 2);

    int mrow = ((lane >> 3) & 1) * 8 + (lane & 7);
    int ncol = wn * 16 + (lane >> 4) * 8;
    uint32_t svAddrPart = (uint32_t)(mrow * 144 + ncol * 2);

    float acc[4][2][4];
    #pragma unroll
    for (int mt = 0; mt < 4; mt++)
        #pragma unroll
        for (int nt = 0; nt < 2; nt++)
            #pragma unroll
            for (int r = 0; r < 4; r++) acc[mt][nt][r] = 0.f;

    #pragma unroll
    for (int p = 0; p < 2; p++) {
        uint32_t st = sVu32 + (uint32_t)p * CIRC_STAGE_BYTES;
        size_t adv = (size_t)p * 64 * CH;
        cp_async16(st + svoA, gvh + adv);
        cp_async16(st + svoB, gvh + adv + 32 * CH);
        CP_COMMIT();
    }
    __syncthreads();

    const int NCHUNK = SEQ / 64;   // 32
    for (int c = 0; c < NCHUNK; c++) {
        if (c + 1 < NCHUNK) { CP_WAIT(1); } else { CP_WAIT(0); }
        __syncthreads();

        if (c + 2 < NCHUNK) {
            uint32_t st = sVu32 + (uint32_t)((c + 2) % 3) * CIRC_STAGE_BYTES;
            size_t adv = (size_t)(c + 2) * 64 * CH;
            cp_async16(st + svoA, gvh + adv);
            cp_async16(st + svoB, gvh + adv + 32 * CH);
            CP_COMMIT();
        }

        const uint32_t* Phi = PhiBase + 32 * c;
        uint32_t ehi[7], fhi[8];
        #pragma unroll
        for (int t = 0; t < 7; t++) ehi[t] = Phi[8 * t - 24];
        #pragma unroll
        for (int t = 0; t < 8; t++) fhi[t] = Phi[8 * t - 28];

        uint32_t sVAddr = sVu32 + (uint32_t)(c % 3) * CIRC_STAGE_BYTES + svAddrPart;

        #pragma unroll
        for (int kk = 0; kk < 4; kk++) {
            uint32_t bh[4];
            ldmatrix_x4_trans(bh, sVAddr + kk * 2304u);
            #pragma unroll
            for (int mt = 0; mt < 4; mt++) {
                int d3 = kk - mt + 3;
                uint32_t ah[4] = {ehi[d3], fhi[d3], fhi[d3 + 1], ehi[d3]};
                mma16816(acc[mt][0], ah, bh);
                uint32_t bh1[2] = {bh[2], bh[3]};
                mma16816(acc[mt][1], ah, bh1);
            }
        }
    }

    // epilogue: oa * OA_SCALE as fp16 hi only
    #pragma unroll
    for (int mt = 0; mt < 4; mt++) {
        int r = i0 + wm * 64 + mt * 16 + g;
        #pragma unroll
        for (int nt = 0; nt < 2; nt++) {
            int cc = c0 + wn * 16 + nt * 8 + tig * 2;
            #pragma unroll
            for (int hr = 0; hr < 2; hr++) {
                __half hx = __float2half_rn(acc[mt][nt][hr * 2]);
                __half hy = __float2half_rn(acc[mt][nt][hr * 2 + 1]);
                size_t idx = (size_t)(b * SEQ + r + hr * 8) * CH + cc;
                *(__half2*)(g_oahi + idx) = __halves2half2(hx, hy);
            }
        }
    }
}

// ---------------- launch ------------------------------------------------------
extern "C" void kernel_launch(void* const* d_in, const int* in_sizes, int n_in,
                              void* d_out, int out_size) {
    const float* x  = (const float*)d_in[0];
    const float* Wq = (const float*)d_in[1];
    const float* Wk = (const float*)d_in[2];
    const float* Wv = (const float*)d_in[3];
    const float* Wp = (const float*)d_in[4];
    const float* bp = (const float*)d_in[5];
    float* out = (float*)d_out;

    __half* dxhi; cudaGetSymbolAddress((void**)&dxhi,  g_xhi);
    __half* dvhi; cudaGetSymbolAddress((void**)&dvhi,  g_wvhi);
    __half* dphi; cudaGetSymbolAddress((void**)&dphi,  g_wphi);
    __half* dVhi; cudaGetSymbolAddress((void**)&dVhi,  g_vhi);
    __half* dohi; cudaGetSymbolAddress((void**)&dohi,  g_oahi);

    cudaFuncSetAttribute(circ_mma_kernel,
                         cudaFuncAttributeMaxDynamicSharedMemorySize, CIRC_SMEM_BYTES);
    cudaFuncSetAttribute(gemm_mma_kernel<1>,
                         cudaFuncAttributeMaxDynamicSharedMemorySize, GEMM_SMEM_BYTES);
    cudaFuncSetAttribute(gemm_mma_kernel<2>,
                         cudaFuncAttributeMaxDynamicSharedMemorySize, GEMM_SMEM_BYTES);

    int n4x = BATCH * SEQ * CH / 4;
    int n4w = CH * CH / 4;
    // 1-3) fp16 hi conversions (x, Wv, Wp)
    hi_kernel<<<(n4x + 255) / 256, 256>>>(x,  dxhi, n4x);
    hi_kernel<<<(n4w + 255) / 256, 256>>>(Wv, dvhi, n4w);
    hi_kernel<<<(n4w + 255) / 256, 256>>>(Wp, dphi, n4w);
    // 4) V = x @ Wv^T  (4th launch -> ncu captures this one)
    gemm_mma_kernel<2><<<dim3(CH / 128, (BATCH * SEQ) / 128), 256, GEMM_SMEM_BYTES>>>(
        dxhi, dvhi, nullptr, nullptr, dVhi, 1.0f);
    // 5-6) x mean over n
    xpart_kernel<<<dim3(64, BATCH), CH>>>(x);
    xmean_kernel<<<BATCH, CH>>>();
    // 7) u = SCALE * Wq(head-block)^T @ K_avg
    u_kernel<<<BATCH * HEADS, 256>>>(Wq, Wk);
    // 8) z = x . u
    z_kernel<<<dim3(SEQ / 8, BATCH), 256>>>(x);
    // 9) softmax (+ 1/N fold)
    softmax_kernel<<<BATCH * HEADS, 256>>>();
    // 10) circulant attention -> oa hi (scaled)
    circ_mma_kernel<<<dim3(SEQ / 128, HEADS, BATCH), 256, CIRC_SMEM_BYTES>>>();
    // 11) out = oa @ Wp^T + bp
    gemm_mma_kernel<1><<<dim3(CH / 128, (BATCH * SEQ) / 128), 256, GEMM_SMEM_BYTES>>>(
        dohi, dphi, bp, out, nullptr, OA_INV);
}

// round 13
// speedup vs baseline: 2.5597x; 1.0033x over previous
#include <cuda_runtime.h>
#include <cuda_fp16.h>
#include <cstdint>

#define BATCH 2
#define SEQ   2048
#define CH    768
#define HEADS 12
#define HDIM  64
#define ATT_SCALE 0.125f    // HDIM^-0.5
#define OA_SCALE 4096.0f
#define OA_INV   (1.0f / 4096.0f)

// ---------------- scratch (static device arrays; no cudaMalloc) -------------
__device__ float g_xpart[BATCH * 64 * CH];
__device__ float g_u[BATCH * HEADS * CH];
__device__ float g_z[BATCH * HEADS * SEQ];
__device__ float g_attn[BATCH * HEADS * SEQ];

__device__ __half g_xhi[BATCH * SEQ * CH];
__device__ __half g_wvhi[CH * CH];
__device__ __half g_wphi[CH * CH];
__device__ __half g_vhi[BATCH * SEQ * CH];
__device__ __half g_oahi[BATCH * SEQ * CH];

// ---------------- fused: x -> fp16 hi + 32-row partial sums -----------------
// grid (64, BATCH), block 768. Thread = one column; 32 rows per block.
__global__ void xhi_part_kernel(const float* __restrict__ x) {
    int b = blockIdx.y;
    int chunk = blockIdx.x;           // 0..63
    int c = threadIdx.x;              // 768 threads
    size_t base = ((size_t)b * SEQ + (size_t)chunk * 32) * CH + c;
    float s = 0.f;
    #pragma unroll 8
    for (int n = 0; n < 32; n++) {
        float v = x[base + (size_t)n * CH];
        s += v;
        g_xhi[base + (size_t)n * CH] = __float2half_rn(v);
    }
    g_xpart[(b * 64 + chunk) * CH + c] = s;
}

// ---------------- fused: Wv and Wp -> fp16 hi --------------------------------
__global__ void wvp_hi_kernel(const float* __restrict__ Wv,
                              const float* __restrict__ Wp, int n4) {
    int i = blockIdx.x * 256 + threadIdx.x;
    if (i >= n4) return;
    const float* src = blockIdx.y ? Wp : Wv;
    __half* dst = blockIdx.y ? g_wphi : g_wvhi;
    float4 v = ((const float4*)src)[i];
    ((__half2*)dst)[i * 2]     = __halves2half2(__float2half_rn(v.x), __float2half_rn(v.y));
    ((__half2*)dst)[i * 2 + 1] = __halves2half2(__float2half_rn(v.z), __float2half_rn(v.w));
}

// ---------------- u[b,h,c] = SCALE * sum_d Wq[h*64+d,c] * K_avg[b,h,d] ------
// xmean folded in: reduce g_xpart inline.
__global__ void u_kernel(const float* __restrict__ Wq, const float* __restrict__ Wk) {
    int b = blockIdx.x / HEADS;
    int h = blockIdx.x % HEADS;
    __shared__ float xm[CH];
    __shared__ float kavg[HDIM];
    for (int c = threadIdx.x; c < CH; c += 256) {
        float s = 0.f;
        #pragma unroll 16
        for (int k = 0; k < 64; k++) s += g_xpart[(b * 64 + k) * CH + c];
        xm[c] = s * (1.0f / SEQ);
    }
    __syncthreads();
    if (threadIdx.x < HDIM) {
        const float* wk = Wk + (size_t)(h * HDIM + threadIdx.x) * CH;
        float s = 0.f;
        #pragma unroll 8
        for (int c = 0; c < CH; c++) s += xm[c] * wk[c];
        kavg[threadIdx.x] = s;
    }
    __syncthreads();
    for (int c = threadIdx.x; c < CH; c += 256) {
        float s = 0.f;
        #pragma unroll 8
        for (int d = 0; d < HDIM; d++)
            s += Wq[(size_t)(h * HDIM + d) * CH + c] * kavg[d];
        g_u[(b * HEADS + h) * CH + c] = s * ATT_SCALE;
    }
}

// ---------------- z[b,h,n] = x[b,n,:] . u[b,h,:]  (8 rows/block) -------------
__global__ void __launch_bounds__(256) z_kernel(const float* __restrict__ x) {
    __shared__ float us[HEADS * CH];     // 36 KB
    int b = blockIdx.y;
    int tid = threadIdx.x;
    for (int i = tid; i < HEADS * CH; i += 256) us[i] = g_u[b * HEADS * CH + i];
    __syncthreads();
    int wid = tid >> 5, lane = tid & 31;
    int n = blockIdx.x * 8 + wid;
    const float* xr = x + ((size_t)b * SEQ + n) * CH;
    float xv[24];
    #pragma unroll
    for (int i = 0; i < 24; i++) xv[i] = xr[lane + i * 32];
    #pragma unroll
    for (int h = 0; h < HEADS; h++) {
        const float* uh = us + h * CH;
        float s = 0.f;
        #pragma unroll
        for (int i = 0; i < 24; i++) s += xv[i] * uh[lane + i * 32];
        #pragma unroll
        for (int off = 16; off > 0; off >>= 1)
            s += __shfl_down_sync(0xffffffffu, s, off);
        if (lane == 0) g_z[(b * HEADS + h) * SEQ + n] = s;
    }
}

// ---------------- softmax over n per (b,h), fold 1/SEQ ------------------------
__global__ void softmax_kernel() {
    __shared__ float red[256];
    int base = blockIdx.x * SEQ;
    int tid = threadIdx.x;
    float v[8];
    float m = -1e30f;
    #pragma unroll
    for (int k = 0; k < 8; k++) {
        v[k] = g_z[base + tid + k * 256];
        m = fmaxf(m, v[k]);
    }
    red[tid] = m; __syncthreads();
    for (int s = 128; s > 0; s >>= 1) {
        if (tid < s) red[tid] = fmaxf(red[tid], red[tid + s]);
        __syncthreads();
    }
    m = red[0]; __syncthreads();
    float sum = 0.f;
    #pragma unroll
    for (int k = 0; k < 8; k++) { v[k] = __expf(v[k] - m); sum += v[k]; }
    red[tid] = sum; __syncthreads();
    for (int s = 128; s > 0; s >>= 1) {
        if (tid < s) red[tid] += red[tid + s];
        __syncthreads();
    }
    float inv = 1.0f / (red[0] * (float)SEQ);
    #pragma unroll
    for (int k = 0; k < 8; k++) g_attn[base + tid + k * 256] = v[k] * inv;
}

// ================= warp-MMA building blocks ==================================
__device__ __forceinline__ void mma16816(float* c, const uint32_t* a, const uint32_t* b) {
    asm volatile(
        "mma.sync.aligned.m16n8k16.row.col.f32.f16.f16.f32 "
        "{%0,%1,%2,%3}, {%4,%5,%6,%7}, {%8,%9}, {%0,%1,%2,%3};\n"
        : "+f"(c[0]), "+f"(c[1]), "+f"(c[2]), "+f"(c[3])
        : "r"(a[0]), "r"(a[1]), "r"(a[2]), "r"(a[3]), "r"(b[0]), "r"(b[1]));
}

__device__ __forceinline__ uint32_t smem_u32(const void* p) {
    uint32_t a;
    asm("{ .reg .u64 t; cvta.to.shared.u64 t, %1; cvt.u32.u64 %0, t; }"
        : "=r"(a) : "l"(p));
    return a;
}

__device__ __forceinline__ void ldmatrix_x4(uint32_t* r, uint32_t addr) {
    asm volatile(
        "ldmatrix.sync.aligned.m8n8.x4.shared.b16 {%0,%1,%2,%3}, [%4];"
        : "=r"(r[0]), "=r"(r[1]), "=r"(r[2]), "=r"(r[3]) : "r"(addr));
}

__device__ __forceinline__ void ldmatrix_x4_trans(uint32_t* r, uint32_t addr) {
    asm volatile(
        "ldmatrix.sync.aligned.m8n8.x4.trans.shared.b16 {%0,%1,%2,%3}, [%4];"
        : "=r"(r[0]), "=r"(r[1]), "=r"(r[2]), "=r"(r[3]) : "r"(addr));
}

__device__ __forceinline__ void cp_async16(uint32_t smem_addr, const void* gptr) {
    asm volatile("cp.async.cg.shared.global [%0], [%1], 16;"
                 :: "r"(smem_addr), "l"(gptr) : "memory");
}
#define CP_COMMIT()  asm volatile("cp.async.commit_group;" ::: "memory")
#define CP_WAIT(N)   asm volatile("cp.async.wait_group %0;" :: "n"(N) : "memory")

// ================= warp-MMA fp16 GEMM (1-product, cp.async 4-stage) ==========
// out = Ahi[M,768] @ (Bhi[768,768])^T, fp32 accum.
// MODE 1: fp32 out + bias (* outscale). MODE 2: fp16 hi out.
// ONE barrier per stage (slot-rotation proof: cp targets slot (s+3)%4, whose
// last reader was compute s-1, which precedes this iteration's barrier).
#define GEMM_STAGE_BYTES 20480
#define GEMM_SMEM_BYTES  (4 * GEMM_STAGE_BYTES)

template <int MODE>
__global__ void __launch_bounds__(256, 2) gemm_mma_kernel(
    const __half* __restrict__ Ahi,
    const __half* __restrict__ Bhi,
    const float* __restrict__ bias, float* __restrict__ out,
    __half* __restrict__ outhi, float outscale)
{
    extern __shared__ uint32_t dsm[];
    uint32_t sbase = smem_u32(dsm);

    int tid = threadIdx.x;
    int m0 = blockIdx.y * 128;
    int n0 = blockIdx.x * 128;
    int w = tid >> 5, lane = tid & 31;
    int wm = w >> 2, wn = w & 3;
    int g = lane >> 2, tig = lane & 3;

    float acc[4][4][4];
    #pragma unroll
    for (int mt = 0; mt < 4; mt++)
        #pragma unroll
        for (int nt = 0; nt < 4; nt++)
            #pragma unroll
            for (int r = 0; r < 4; r++) acc[mt][nt][r] = 0.f;

    int lrow = tid >> 2;
    int q = tid & 3;
    uint32_t sdst0 = (uint32_t)(lrow * 80 + q * 16);
    uint32_t sdst1 = (uint32_t)((lrow + 64) * 80 + q * 16);
    size_t goffA0 = (size_t)(m0 + lrow) * CH + q * 8;
    size_t goffA1 = (size_t)(m0 + lrow + 64) * CH + q * 8;
    size_t goffB0 = (size_t)(n0 + lrow) * CH + q * 8;
    size_t goffB1 = (size_t)(n0 + lrow + 64) * CH + q * 8;

    int sub = lane >> 3, lr = lane & 7;
    int aRow = wm * 64 + ((sub & 1) << 3) + lr;
    int aKs  = sub >> 1;
    uint32_t aOffBase = (uint32_t)(aRow * 80 + aKs * 16);
    int bRow = wn * 32 + (((sub >> 1) & 1) << 3) + lr;
    int bKs  = sub & 1;
    uint32_t bOffBase = (uint32_t)(bRow * 80 + bKs * 16);

    const int NSTAGE = CH / 32;   // 24

    #pragma unroll
    for (int p = 0; p < 3; p++) {
        uint32_t st = sbase + (uint32_t)p * GEMM_STAGE_BYTES;
        size_t ka = (size_t)p * 32;
        cp_async16(st + sdst0,          Ahi + goffA0 + ka);
        cp_async16(st + sdst1,          Ahi + goffA1 + ka);
        cp_async16(st + 10240 + sdst0,  Bhi + goffB0 + ka);
        cp_async16(st + 10240 + sdst1,  Bhi + goffB1 + ka);
        CP_COMMIT();
    }

    for (int s = 0; s < NSTAGE; s++) {
        // wait ladder: leave at most (pending-after-s) groups in flight
        if (s + 2 < NSTAGE)      { CP_WAIT(2); }
        else if (s + 1 < NSTAGE) { CP_WAIT(1); }
        else                     { CP_WAIT(0); }
        __syncthreads();

        if (s + 3 < NSTAGE) {
            uint32_t st2 = sbase + (uint32_t)((s + 3) & 3) * GEMM_STAGE_BYTES;
            size_t ka = (size_t)(s + 3) * 32;
            cp_async16(st2 + sdst0,          Ahi + goffA0 + ka);
            cp_async16(st2 + sdst1,          Ahi + goffA1 + ka);
            cp_async16(st2 + 10240 + sdst0,  Bhi + goffB0 + ka);
            cp_async16(st2 + 10240 + sdst1,  Bhi + goffB1 + ka);
            CP_COMMIT();
        }

        uint32_t st = sbase + (uint32_t)(s & 3) * GEMM_STAGE_BYTES;
        uint32_t uAhi = st, uBhi = st + 10240u;

        #pragma unroll
        for (int kk = 0; kk < 2; kk++) {
            uint32_t kadd = (uint32_t)(kk * 32);
            uint32_t bh[4][2];
            #pragma unroll
            for (int np = 0; np < 2; np++) {
                uint32_t r4[4];
                uint32_t boff = bOffBase + kadd + (uint32_t)(np * 16 * 80);
                ldmatrix_x4(r4, uBhi + boff);
                bh[np * 2][0] = r4[0];      bh[np * 2][1] = r4[1];
                bh[np * 2 + 1][0] = r4[2];  bh[np * 2 + 1][1] = r4[3];
            }
            #pragma unroll
            for (int mt = 0; mt < 4; mt++) {
                uint32_t aoff = aOffBase + kadd + (uint32_t)(mt * 16 * 80);
                uint32_t ah[4];
                ldmatrix_x4(ah, uAhi + aoff);
                #pragma unroll
                for (int nt = 0; nt < 4; nt++)
                    mma16816(acc[mt][nt], ah, bh[nt]);
            }
        }
        // no trailing barrier (see kernel comment)
    }

    #pragma unroll
    for (int mt = 0; mt < 4; mt++) {
        int r = m0 + wm * 64 + mt * 16 + g;
        #pragma unroll
        for (int nt = 0; nt < 4; nt++) {
            int c = n0 + wn * 32 + nt * 8 + tig * 2;
            if (MODE == 1) {
                float2 v0, v1;
                v0.x = acc[mt][nt][0] * outscale + bias[c];
                v0.y = acc[mt][nt][1] * outscale + bias[c + 1];
                v1.x = acc[mt][nt][2] * outscale + bias[c];
                v1.y = acc[mt][nt][3] * outscale + bias[c + 1];
                *(float2*)(out + (size_t)r * CH + c)       = v0;
                *(float2*)(out + (size_t)(r + 8) * CH + c) = v1;
            } else {
                #pragma unroll
                for (int hr = 0; hr < 2; hr++) {
                    __half hx = __float2half_rn(acc[mt][nt][hr * 2]);
                    __half hy = __float2half_rn(acc[mt][nt][hr * 2 + 1]);
                    size_t idx = (size_t)(r + hr * 8) * CH + c;
                    *(__half2*)(outhi + idx) = __halves2half2(hx, hy);
                }
            }
        }
    }
}

// ================= circulant attention (1-product, cp.async 4-stage V) =======
// oa[b,i,c] = sum_j attn2[(j-i) mod N] * Vhi[j,c],  attn2 = attn/N * OA_SCALE
// dyn smem: A arrays 16384 B + 4 V stages x 9216 B = 53248 B.
#define CIRC_STAGE_BYTES 9216
#define CIRC_SMEM_BYTES (16384 + 4 * CIRC_STAGE_BYTES)

__global__ void __launch_bounds__(256, 2) circ_mma_kernel() {
    extern __shared__ __half dsmh[];
    __half* A2hi  = dsmh;
    __half* A2hiS = dsmh + 4096;
    uint32_t sVu32 = smem_u32(dsmh + 8192);

    int tid = threadIdx.x;
    int i0 = blockIdx.x * 128;
    int h  = blockIdx.y;
    int b  = blockIdx.z;
    int c0 = h * HDIM;
    int w = tid >> 5, lane = tid & 31;
    int wm = w >> 2, wn = w & 3;
    int g = lane >> 2, tig = lane & 3;

    const float* arow = g_attn + (size_t)(b * HEADS + h) * SEQ;
    for (int t = tid; t < SEQ; t += 256) {
        __half hi = __float2half_rn(arow[t] * OA_SCALE);
        A2hi[t] = hi;  A2hi[t + SEQ] = hi;
    }
    __syncthreads();
    for (int t = tid; t < 2 * SEQ - 1; t += 256) A2hiS[t] = A2hi[t + 1];
    if (tid == 0) A2hiS[2 * SEQ - 1] = __float2half_rn(0.f);

    int ob = SEQ + 2 * tig - (i0 + wm * 64 + g);
    int par = ob & 1;
    const uint32_t* PhiBase = (const uint32_t*)(par ? A2hiS : A2hi) + ((ob - par) >> 1);

    int vrow = tid >> 3, vcg = tid & 7;
    const __half* gvh = g_vhi + ((size_t)b * SEQ + vrow) * CH + c0 + vcg * 8;
    uint32_t svoA = (uint32_t)((vrow * 72 + vcg * 8) * 2);
    uint32_t svoB = (uint32_t)(((vrow + 32) * 72 + vcg * 8) * 2);

    int mrow = ((lane >> 3) & 1) * 8 + (lane & 7);
    int ncol = wn * 16 + (lane >> 4) * 8;
    uint32_t svAddrPart = (uint32_t)(mrow * 144 + ncol * 2);

    float acc[4][2][4];
    #pragma unroll
    for (int mt = 0; mt < 4; mt++)
        #pragma unroll
        for (int nt = 0; nt < 2; nt++)
            #pragma unroll
            for (int r = 0; r < 4; r++) acc[mt][nt][r] = 0.f;

    #pragma unroll
    for (int p = 0; p < 3; p++) {
        uint32_t st = sVu32 + (uint32_t)p * CIRC_STAGE_BYTES;
        size_t adv = (size_t)p * 64 * CH;
        cp_async16(st + svoA, gvh + adv);
        cp_async16(st + svoB, gvh + adv + 32 * CH);
        CP_COMMIT();
    }
    __syncthreads();   // attn arrays ready

    const int NCHUNK = SEQ / 64;   // 32
    for (int c = 0; c < NCHUNK; c++) {
        if (c + 2 < NCHUNK)      { CP_WAIT(2); }
        else if (c + 1 < NCHUNK) { CP_WAIT(1); }
        else                     { CP_WAIT(0); }
        __syncthreads();

        if (c + 3 < NCHUNK) {
            uint32_t st = sVu32 + (uint32_t)((c + 3) & 3) * CIRC_STAGE_BYTES;
            size_t adv = (size_t)(c + 3) * 64 * CH;
            cp_async16(st + svoA, gvh + adv);
            cp_async16(st + svoB, gvh + adv + 32 * CH);
            CP_COMMIT();
        }

        const uint32_t* Phi = PhiBase + 32 * c;
        uint32_t ehi[7], fhi[8];
        #pragma unroll
        for (int t = 0; t < 7; t++) ehi[t] = Phi[8 * t - 24];
        #pragma unroll
        for (int t = 0; t < 8; t++) fhi[t] = Phi[8 * t - 28];

        uint32_t sVAddr = sVu32 + (uint32_t)(c & 3) * CIRC_STAGE_BYTES + svAddrPart;

        #pragma unroll
        for (int kk = 0; kk < 4; kk++) {
            uint32_t bh[4];
            ldmatrix_x4_trans(bh, sVAddr + kk * 2304u);
            #pragma unroll
            for (int mt = 0; mt < 4; mt++) {
                int d3 = kk - mt + 3;
                uint32_t ah[4] = {ehi[d3], fhi[d3], fhi[d3 + 1], ehi[d3]};
                mma16816(acc[mt][0], ah, bh);
                uint32_t bh1[2] = {bh[2], bh[3]};
                mma16816(acc[mt][1], ah, bh1);
            }
        }
    }

    #pragma unroll
    for (int mt = 0; mt < 4; mt++) {
        int r = i0 + wm * 64 + mt * 16 + g;
        #pragma unroll
        for (int nt = 0; nt < 2; nt++) {
            int cc = c0 + wn * 16 + nt * 8 + tig * 2;
            #pragma unroll
            for (int hr = 0; hr < 2; hr++) {
                __half hx = __float2half_rn(acc[mt][nt][hr * 2]);
                __half hy = __float2half_rn(acc[mt][nt][hr * 2 + 1]);
                size_t idx = (size_t)(b * SEQ + r + hr * 8) * CH + cc;
                *(__half2*)(g_oahi + idx) = __halves2half2(hx, hy);
            }
        }
    }
}

// ---------------- launch ------------------------------------------------------
extern "C" void kernel_launch(void* const* d_in, const int* in_sizes, int n_in,
                              void* d_out, int out_size) {
    const float* x  = (const float*)d_in[0];
    const float* Wq = (const float*)d_in[1];
    const float* Wk = (const float*)d_in[2];
    const float* Wv = (const float*)d_in[3];
    const float* Wp = (const float*)d_in[4];
    const float* bp = (const float*)d_in[5];
    float* out = (float*)d_out;

    __half* dxhi; cudaGetSymbolAddress((void**)&dxhi,  g_xhi);
    __half* dvhi; cudaGetSymbolAddress((void**)&dvhi,  g_wvhi);
    __half* dphi; cudaGetSymbolAddress((void**)&dphi,  g_wphi);
    __half* dVhi; cudaGetSymbolAddress((void**)&dVhi,  g_vhi);
    __half* dohi; cudaGetSymbolAddress((void**)&dohi,  g_oahi);

    cudaFuncSetAttribute(circ_mma_kernel,
                         cudaFuncAttributeMaxDynamicSharedMemorySize, CIRC_SMEM_BYTES);
    cudaFuncSetAttribute(gemm_mma_kernel<1>,
                         cudaFuncAttributeMaxDynamicSharedMemorySize, GEMM_SMEM_BYTES);
    cudaFuncSetAttribute(gemm_mma_kernel<2>,
                         cudaFuncAttributeMaxDynamicSharedMemorySize, GEMM_SMEM_BYTES);

    int n4w = CH * CH / 4;
    // 1) x -> fp16 hi + partial sums (fused)
    xhi_part_kernel<<<dim3(64, BATCH), CH>>>(x);
    // 2) Wv, Wp -> fp16 hi (fused, one launch)
    wvp_hi_kernel<<<dim3((n4w + 255) / 256, 2), 256>>>(Wv, Wp, n4w);
    // 3) u = SCALE * Wq(head-block)^T @ K_avg   (xmean folded in)
    u_kernel<<<BATCH * HEADS, 256>>>(Wq, Wk);
    // 4) V = x @ Wv^T  (4th launch -> ncu captures this one)
    gemm_mma_kernel<2><<<dim3(CH / 128, (BATCH * SEQ) / 128), 256, GEMM_SMEM_BYTES>>>(
        dxhi, dvhi, nullptr, nullptr, dVhi, 1.0f);
    // 5) z = x . u
    z_kernel<<<dim3(SEQ / 8, BATCH), 256>>>(x);
    // 6) softmax (+ 1/N fold)
    softmax_kernel<<<BATCH * HEADS, 256>>>();
    // 7) circulant attention -> oa hi (scaled)
    circ_mma_kernel<<<dim3(SEQ / 128, HEADS, BATCH), 256, CIRC_SMEM_BYTES>>>();
    // 8) out = oa @ Wp^T + bp
    gemm_mma_kernel<1><<<dim3(CH / 128, (BATCH * SEQ) / 128), 256, GEMM_SMEM_BYTES>>>(
        dohi, dphi, bp, out, nullptr, OA_INV);
}

// round 14
// speedup vs baseline: 2.9050x; 1.1349x over previous
#include <cuda_runtime.h>
#include <cuda_fp16.h>
#include <cstdint>

#define BATCH 2
#define SEQ   2048
#define CH    768
#define HEADS 12
#define HDIM  64
#define ATT_SCALE 0.125f    // HDIM^-0.5
#define OA_SCALE 4096.0f
#define OA_INV   (1.0f / 4096.0f)

// ---------------- scratch (static device arrays; no cudaMalloc) -------------
__device__ float g_xpart[BATCH * 128 * CH];
__device__ float g_u[BATCH * HEADS * CH];
__device__ float g_z[BATCH * HEADS * SEQ];
__device__ float g_attn[BATCH * HEADS * SEQ];

__device__ __half g_xhi[BATCH * SEQ * CH];
__device__ __half g_wvhi[CH * CH];
__device__ __half g_wphi[CH * CH];
__device__ __half g_vhi[BATCH * SEQ * CH];
__device__ __half g_oahi[BATCH * SEQ * CH];

// ---------------- fused: x -> fp16 hi + 16-row partial sums -----------------
__global__ void xhi_part_kernel(const float* __restrict__ x) {
    int b = blockIdx.y;
    int chunk = blockIdx.x;           // 0..127
    int c = threadIdx.x;              // 768 threads
    size_t base = ((size_t)b * SEQ + (size_t)chunk * 16) * CH + c;
    float s = 0.f;
    #pragma unroll
    for (int n = 0; n < 16; n++) {
        float v = x[base + (size_t)n * CH];
        s += v;
        g_xhi[base + (size_t)n * CH] = __float2half_rn(v);
    }
    g_xpart[(b * 128 + chunk) * CH + c] = s;
}

// ---------------- fused: Wv and Wp -> fp16 hi --------------------------------
__global__ void wvp_hi_kernel(const float* __restrict__ Wv,
                              const float* __restrict__ Wp, int n4) {
    int i = blockIdx.x * 256 + threadIdx.x;
    if (i >= n4) return;
    const float* src = blockIdx.y ? Wp : Wv;
    __half* dst = blockIdx.y ? g_wphi : g_wvhi;
    float4 v = ((const float4*)src)[i];
    ((__half2*)dst)[i * 2]     = __halves2half2(__float2half_rn(v.x), __float2half_rn(v.y));
    ((__half2*)dst)[i * 2 + 1] = __halves2half2(__float2half_rn(v.z), __float2half_rn(v.w));
}

// ---------------- u[b,h,c] = SCALE * sum_d Wq[h*64+d,c] * K_avg[b,h,d] ------
__global__ void u_kernel(const float* __restrict__ Wq, const float* __restrict__ Wk) {
    int b = blockIdx.x / HEADS;
    int h = blockIdx.x % HEADS;
    __shared__ float xm[CH];
    __shared__ float kavg[HDIM];
    for (int c = threadIdx.x; c < CH; c += 256) {
        float s = 0.f;
        #pragma unroll 16
        for (int k = 0; k < 128; k++) s += g_xpart[(b * 128 + k) * CH + c];
        xm[c] = s * (1.0f / SEQ);
    }
    __syncthreads();
    if (threadIdx.x < HDIM) {
        const float* wk = Wk + (size_t)(h * HDIM + threadIdx.x) * CH;
        float s = 0.f;
        #pragma unroll 8
        for (int c = 0; c < CH; c++) s += xm[c] * wk[c];
        kavg[threadIdx.x] = s;
    }
    __syncthreads();
    for (int c = threadIdx.x; c < CH; c += 256) {
        float s = 0.f;
        #pragma unroll 8
        for (int d = 0; d < HDIM; d++)
            s += Wq[(size_t)(h * HDIM + d) * CH + c] * kavg[d];
        g_u[(b * HEADS + h) * CH + c] = s * ATT_SCALE;
    }
}

// ---------------- z[b,h,n] = x[b,n,:] . u[b,h,:]  (8 rows/block) -------------
__global__ void __launch_bounds__(256) z_kernel(const float* __restrict__ x) {
    __shared__ float us[HEADS * CH];
    int b = blockIdx.y;
    int tid = threadIdx.x;
    for (int i = tid; i < HEADS * CH; i += 256) us[i] = g_u[b * HEADS * CH + i];
    __syncthreads();
    int wid = tid >> 5, lane = tid & 31;
    int n = blockIdx.x * 8 + wid;
    const float* xr = x + ((size_t)b * SEQ + n) * CH;
    float xv[24];
    #pragma unroll
    for (int i = 0; i < 24; i++) xv[i] = xr[lane + i * 32];
    #pragma unroll
    for (int h = 0; h < HEADS; h++) {
        const float* uh = us + h * CH;
        float s = 0.f;
        #pragma unroll
        for (int i = 0; i < 24; i++) s += xv[i] * uh[lane + i * 32];
        #pragma unroll
        for (int off = 16; off > 0; off >>= 1)
            s += __shfl_down_sync(0xffffffffu, s, off);
        if (lane == 0) g_z[(b * HEADS + h) * SEQ + n] = s;
    }
}

// ---------------- softmax over n per (b,h), fold 1/SEQ ------------------------
__global__ void softmax_kernel() {
    __shared__ float red[256];
    int base = blockIdx.x * SEQ;
    int tid = threadIdx.x;
    float v[8];
    float m = -1e30f;
    #pragma unroll
    for (int k = 0; k < 8; k++) {
        v[k] = g_z[base + tid + k * 256];
        m = fmaxf(m, v[k]);
    }
    red[tid] = m; __syncthreads();
    for (int s = 128; s > 0; s >>= 1) {
        if (tid < s) red[tid] = fmaxf(red[tid], red[tid + s]);
        __syncthreads();
    }
    m = red[0]; __syncthreads();
    float sum = 0.f;
    #pragma unroll
    for (int k = 0; k < 8; k++) { v[k] = __expf(v[k] - m); sum += v[k]; }
    red[tid] = sum; __syncthreads();
    for (int s = 128; s > 0; s >>= 1) {
        if (tid < s) red[tid] += red[tid + s];
        __syncthreads();
    }
    float inv = 1.0f / (red[0] * (float)SEQ);
    #pragma unroll
    for (int k = 0; k < 8; k++) g_attn[base + tid + k * 256] = v[k] * inv;
}

// ================= warp-MMA building blocks ==================================
__device__ __forceinline__ void mma16816(float* c, const uint32_t* a, const uint32_t* b) {
    asm volatile(
        "mma.sync.aligned.m16n8k16.row.col.f32.f16.f16.f32 "
        "{%0,%1,%2,%3}, {%4,%5,%6,%7}, {%8,%9}, {%0,%1,%2,%3};\n"
        : "+f"(c[0]), "+f"(c[1]), "+f"(c[2]), "+f"(c[3])
        : "r"(a[0]), "r"(a[1]), "r"(a[2]), "r"(a[3]), "r"(b[0]), "r"(b[1]));
}

__device__ __forceinline__ uint32_t smem_u32(const void* p) {
    uint32_t a;
    asm("{ .reg .u64 t; cvta.to.shared.u64 t, %1; cvt.u32.u64 %0, t; }"
        : "=r"(a) : "l"(p));
    return a;
}

__device__ __forceinline__ void ldmatrix_x4(uint32_t* r, uint32_t addr) {
    asm volatile(
        "ldmatrix.sync.aligned.m8n8.x4.shared.b16 {%0,%1,%2,%3}, [%4];"
        : "=r"(r[0]), "=r"(r[1]), "=r"(r[2]), "=r"(r[3]) : "r"(addr));
}

__device__ __forceinline__ void ldmatrix_x4_trans(uint32_t* r, uint32_t addr) {
    asm volatile(
        "ldmatrix.sync.aligned.m8n8.x4.trans.shared.b16 {%0,%1,%2,%3}, [%4];"
        : "=r"(r[0]), "=r"(r[1]), "=r"(r[2]), "=r"(r[3]) : "r"(addr));
}

__device__ __forceinline__ void cp_async16(uint32_t smem_addr, const void* gptr) {
    asm volatile("cp.async.cg.shared.global [%0], [%1], 16;"
                 :: "r"(smem_addr), "l"(gptr) : "memory");
}
#define CP_COMMIT()  asm volatile("cp.async.commit_group;" ::: "memory")
#define CP_WAIT(N)   asm volatile("cp.async.wait_group %0;" :: "n"(N) : "memory")

// ================= warp-MMA fp16 GEMM: 64x128 tile, 3 CTAs/SM ================
// out = Ahi[M,768] @ (Bhi[768,768])^T, fp32 accum.
// MODE 1: fp32 out + bias (* outscale). MODE 2: fp16 hi out.
// stage: A 64x80B @0 (5120), B 128x80B @5120 (10240) -> 15360 B; 4 stages.
#define GEMM_STAGE_BYTES 15360
#define GEMM_SMEM_BYTES  (4 * GEMM_STAGE_BYTES)

template <int MODE>
__global__ void __launch_bounds__(256, 3) gemm_mma_kernel(
    const __half* __restrict__ Ahi,
    const __half* __restrict__ Bhi,
    const float* __restrict__ bias, float* __restrict__ out,
    __half* __restrict__ outhi, float outscale)
{
    extern __shared__ uint32_t dsm[];
    uint32_t sbase = smem_u32(dsm);

    int tid = threadIdx.x;
    int m0 = blockIdx.y * 64;
    int n0 = blockIdx.x * 128;
    int w = tid >> 5, lane = tid & 31;
    int wm = w >> 2, wn = w & 3;          // 2(M) x 4(N); warp tile 32x32
    int g = lane >> 2, tig = lane & 3;

    float acc[2][4][4];
    #pragma unroll
    for (int mt = 0; mt < 2; mt++)
        #pragma unroll
        for (int nt = 0; nt < 4; nt++)
            #pragma unroll
            for (int r = 0; r < 4; r++) acc[mt][nt][r] = 0.f;

    // loaders: A one chunk (row=t>>2, q=t&3), B two chunks (rows t>>2, +64)
    int lrow = tid >> 2;
    int q = tid & 3;
    uint32_t sdstA  = (uint32_t)(lrow * 80 + q * 16);
    uint32_t sdstB0 = (uint32_t)(5120 + lrow * 80 + q * 16);
    uint32_t sdstB1 = (uint32_t)(5120 + (lrow + 64) * 80 + q * 16);
    size_t goffA  = (size_t)(m0 + lrow) * CH + q * 8;
    size_t goffB0 = (size_t)(n0 + lrow) * CH + q * 8;
    size_t goffB1 = (size_t)(n0 + lrow + 64) * CH + q * 8;

    int sub = lane >> 3, lr = lane & 7;
    int aRow = wm * 32 + ((sub & 1) << 3) + lr;   // + mt*16
    int aKs  = sub >> 1;
    uint32_t aOffBase = (uint32_t)(aRow * 80 + aKs * 16);
    int bRow = wn * 32 + (((sub >> 1) & 1) << 3) + lr;   // + np*16
    int bKs  = sub & 1;
    uint32_t bOffBase = (uint32_t)(5120 + bRow * 80 + bKs * 16);

    const int NSTAGE = CH / 32;   // 24

    #pragma unroll
    for (int p = 0; p < 3; p++) {
        uint32_t st = sbase + (uint32_t)p * GEMM_STAGE_BYTES;
        size_t ka = (size_t)p * 32;
        cp_async16(st + sdstA,  Ahi + goffA + ka);
        cp_async16(st + sdstB0, Bhi + goffB0 + ka);
        cp_async16(st + sdstB1, Bhi + goffB1 + ka);
        CP_COMMIT();
    }

    for (int s = 0; s < NSTAGE; s++) {
        if (s + 2 < NSTAGE)      { CP_WAIT(2); }
        else if (s + 1 < NSTAGE) { CP_WAIT(1); }
        else                     { CP_WAIT(0); }
        __syncthreads();

        if (s + 3 < NSTAGE) {
            uint32_t st2 = sbase + (uint32_t)((s + 3) & 3) * GEMM_STAGE_BYTES;
            size_t ka = (size_t)(s + 3) * 32;
            cp_async16(st2 + sdstA,  Ahi + goffA + ka);
            cp_async16(st2 + sdstB0, Bhi + goffB0 + ka);
            cp_async16(st2 + sdstB1, Bhi + goffB1 + ka);
            CP_COMMIT();
        }

        uint32_t st = sbase + (uint32_t)(s & 3) * GEMM_STAGE_BYTES;

        #pragma unroll
        for (int kk = 0; kk < 2; kk++) {
            uint32_t kadd = (uint32_t)(kk * 32);
            uint32_t bh[4][2];
            #pragma unroll
            for (int np = 0; np < 2; np++) {
                uint32_t r4[4];
                ldmatrix_x4(r4, st + bOffBase + kadd + (uint32_t)(np * 16 * 80));
                bh[np * 2][0] = r4[0];      bh[np * 2][1] = r4[1];
                bh[np * 2 + 1][0] = r4[2];  bh[np * 2 + 1][1] = r4[3];
            }
            #pragma unroll
            for (int mt = 0; mt < 2; mt++) {
                uint32_t ah[4];
                ldmatrix_x4(ah, st + aOffBase + kadd + (uint32_t)(mt * 16 * 80));
                #pragma unroll
                for (int nt = 0; nt < 4; nt++)
                    mma16816(acc[mt][nt], ah, bh[nt]);
            }
        }
        // single barrier per stage (slot-rotation argument)
    }

    #pragma unroll
    for (int mt = 0; mt < 2; mt++) {
        int r = m0 + wm * 32 + mt * 16 + g;
        #pragma unroll
        for (int nt = 0; nt < 4; nt++) {
            int c = n0 + wn * 32 + nt * 8 + tig * 2;
            if (MODE == 1) {
                float2 v0, v1;
                v0.x = acc[mt][nt][0] * outscale + bias[c];
                v0.y = acc[mt][nt][1] * outscale + bias[c + 1];
                v1.x = acc[mt][nt][2] * outscale + bias[c];
                v1.y = acc[mt][nt][3] * outscale + bias[c + 1];
                *(float2*)(out + (size_t)r * CH + c)       = v0;
                *(float2*)(out + (size_t)(r + 8) * CH + c) = v1;
            } else {
                #pragma unroll
                for (int hr = 0; hr < 2; hr++) {
                    __half hx = __float2half_rn(acc[mt][nt][hr * 2]);
                    __half hy = __float2half_rn(acc[mt][nt][hr * 2 + 1]);
                    size_t idx = (size_t)(r + hr * 8) * CH + c;
                    *(__half2*)(outhi + idx) = __halves2half2(hx, hy);
                }
            }
        }
    }
}

// ================= circulant attention (1-product, cp.async 4-stage V) =======
#define CIRC_STAGE_BYTES 9216
#define CIRC_SMEM_BYTES (16384 + 4 * CIRC_STAGE_BYTES)

__global__ void __launch_bounds__(256, 2) circ_mma_kernel() {
    extern __shared__ __half dsmh[];
    __half* A2hi  = dsmh;
    __half* A2hiS = dsmh + 4096;
    uint32_t sVu32 = smem_u32(dsmh + 8192);

    int tid = threadIdx.x;
    int i0 = blockIdx.x * 128;
    int h  = blockIdx.y;
    int b  = blockIdx.z;
    int c0 = h * HDIM;
    int w = tid >> 5, lane = tid & 31;
    int wm = w >> 2, wn = w & 3;
    int g = lane >> 2, tig = lane & 3;

    const float* arow = g_attn + (size_t)(b * HEADS + h) * SEQ;
    for (int t = tid; t < SEQ; t += 256) {
        __half hi = __float2half_rn(arow[t] * OA_SCALE);
        A2hi[t] = hi;  A2hi[t + SEQ] = hi;
    }
    __syncthreads();
    for (int t = tid; t < 2 * SEQ - 1; t += 256) A2hiS[t] = A2hi[t + 1];
    if (tid == 0) A2hiS[2 * SEQ - 1] = __float2half_rn(0.f);

    int ob = SEQ + 2 * tig - (i0 + wm * 64 + g);
    int par = ob & 1;
    const uint32_t* PhiBase = (const uint32_t*)(par ? A2hiS : A2hi) + ((ob - par) >> 1);

    int vrow = tid >> 3, vcg = tid & 7;
    const __half* gvh = g_vhi + ((size_t)b * SEQ + vrow) * CH + c0 + vcg * 8;
    uint32_t svoA = (uint32_t)((vrow * 72 + vcg * 8) * 2);
    uint32_t svoB = (uint32_t)(((vrow + 32) * 72 + vcg * 8) * 2);

    int mrow = ((lane >> 3) & 1) * 8 + (lane & 7);
    int ncol = wn * 16 + (lane >> 4) * 8;
    uint32_t svAddrPart = (uint32_t)(mrow * 144 + ncol * 2);

    float acc[4][2][4];
    #pragma unroll
    for (int mt = 0; mt < 4; mt++)
        #pragma unroll
        for (int nt = 0; nt < 2; nt++)
            #pragma unroll
            for (int r = 0; r < 4; r++) acc[mt][nt][r] = 0.f;

    #pragma unroll
    for (int p = 0; p < 3; p++) {
        uint32_t st = sVu32 + (uint32_t)p * CIRC_STAGE_BYTES;
        size_t adv = (size_t)p * 64 * CH;
        cp_async16(st + svoA, gvh + adv);
        cp_async16(st + svoB, gvh + adv + 32 * CH);
        CP_COMMIT();
    }
    __syncthreads();

    const int NCHUNK = SEQ / 64;   // 32
    for (int c = 0; c < NCHUNK; c++) {
        if (c + 2 < NCHUNK)      { CP_WAIT(2); }
        else if (c + 1 < NCHUNK) { CP_WAIT(1); }
        else                     { CP_WAIT(0); }
        __syncthreads();

        if (c + 3 < NCHUNK) {
            uint32_t st = sVu32 + (uint32_t)((c + 3) & 3) * CIRC_STAGE_BYTES;
            size_t adv = (size_t)(c + 3) * 64 * CH;
            cp_async16(st + svoA, gvh + adv);
            cp_async16(st + svoB, gvh + adv + 32 * CH);
            CP_COMMIT();
        }

        const uint32_t* Phi = PhiBase + 32 * c;
        uint32_t ehi[7], fhi[8];
        #pragma unroll
        for (int t = 0; t < 7; t++) ehi[t] = Phi[8 * t - 24];
        #pragma unroll
        for (int t = 0; t < 8; t++) fhi[t] = Phi[8 * t - 28];

        uint32_t sVAddr = sVu32 + (uint32_t)(c & 3) * CIRC_STAGE_BYTES + svAddrPart;

        #pragma unroll
        for (int kk = 0; kk < 4; kk++) {
            uint32_t bh[4];
            ldmatrix_x4_trans(bh, sVAddr + kk * 2304u);
            #pragma unroll
            for (int mt = 0; mt < 4; mt++) {
                int d3 = kk - mt + 3;
                uint32_t ah[4] = {ehi[d3], fhi[d3], fhi[d3 + 1], ehi[d3]};
                mma16816(acc[mt][0], ah, bh);
                uint32_t bh1[2] = {bh[2], bh[3]};
                mma16816(acc[mt][1], ah, bh1);
            }
        }
    }

    #pragma unroll
    for (int mt = 0; mt < 4; mt++) {
        int r = i0 + wm * 64 + mt * 16 + g;
        #pragma unroll
        for (int nt = 0; nt < 2; nt++) {
            int cc = c0 + wn * 16 + nt * 8 + tig * 2;
            #pragma unroll
            for (int hr = 0; hr < 2; hr++) {
                __half hx = __float2half_rn(acc[mt][nt][hr * 2]);
                __half hy = __float2half_rn(acc[mt][nt][hr * 2 + 1]);
                size_t idx = (size_t)(b * SEQ + r + hr * 8) * CH + cc;
                *(__half2*)(g_oahi + idx) = __halves2half2(hx, hy);
            }
        }
    }
}

// ---------------- launch ------------------------------------------------------
extern "C" void kernel_launch(void* const* d_in, const int* in_sizes, int n_in,
                              void* d_out, int out_size) {
    const float* x  = (const float*)d_in[0];
    const float* Wq = (const float*)d_in[1];
    const float* Wk = (const float*)d_in[2];
    const float* Wv = (const float*)d_in[3];
    const float* Wp = (const float*)d_in[4];
    const float* bp = (const float*)d_in[5];
    float* out = (float*)d_out;

    __half* dxhi; cudaGetSymbolAddress((void**)&dxhi,  g_xhi);
    __half* dvhi; cudaGetSymbolAddress((void**)&dvhi,  g_wvhi);
    __half* dphi; cudaGetSymbolAddress((void**)&dphi,  g_wphi);
    __half* dVhi; cudaGetSymbolAddress((void**)&dVhi,  g_vhi);
    __half* dohi; cudaGetSymbolAddress((void**)&dohi,  g_oahi);

    // one-time resources (no device memory allocation)
    static cudaStream_t s1 = nullptr;
    static cudaEvent_t evA = nullptr, evV = nullptr;
    if (!s1) {
        cudaStreamCreateWithFlags(&s1, cudaStreamNonBlocking);
        cudaEventCreateWithFlags(&evA, cudaEventDisableTiming);
        cudaEventCreateWithFlags(&evV, cudaEventDisableTiming);
        cudaFuncSetAttribute(circ_mma_kernel,
                             cudaFuncAttributeMaxDynamicSharedMemorySize, CIRC_SMEM_BYTES);
        cudaFuncSetAttribute(gemm_mma_kernel<1>,
                             cudaFuncAttributeMaxDynamicSharedMemorySize, GEMM_SMEM_BYTES);
        cudaFuncSetAttribute(gemm_mma_kernel<2>,
                             cudaFuncAttributeMaxDynamicSharedMemorySize, GEMM_SMEM_BYTES);
    }

    int n4w = CH * CH / 4;
    // main stream: conversions
    wvp_hi_kernel<<<dim3((n4w + 255) / 256, 2), 256>>>(Wv, Wp, n4w);
    xhi_part_kernel<<<dim3(128, BATCH), CH>>>(x);
    cudaEventRecord(evA, 0);

    // side stream: V projection (needs xhi + wvhi)
    cudaStreamWaitEvent(s1, evA, 0);
    gemm_mma_kernel<2><<<dim3(CH / 128, (BATCH * SEQ) / 64), 256, GEMM_SMEM_BYTES, s1>>>(
        dxhi, dvhi, nullptr, nullptr, dVhi, 1.0f);
    cudaEventRecord(evV, s1);

    // main stream (concurrent with gemm_V): u -> z -> softmax
    u_kernel<<<BATCH * HEADS, 256>>>(Wq, Wk);
    z_kernel<<<dim3(SEQ / 8, BATCH), 256>>>(x);
    softmax_kernel<<<BATCH * HEADS, 256>>>();

    // join: circ needs V and attn
    cudaStreamWaitEvent(0, evV, 0);
    circ_mma_kernel<<<dim3(SEQ / 128, HEADS, BATCH), 256, CIRC_SMEM_BYTES>>>();
    gemm_mma_kernel<1><<<dim3(CH / 128, (BATCH * SEQ) / 64), 256, GEMM_SMEM_BYTES>>>(
        dohi, dphi, bp, out, nullptr, OA_INV);
}

// round 15
// speedup vs baseline: 3.8236x; 1.3162x over previous
#include <cuda_runtime.h>
#include <cuda_fp16.h>
#include <cstdint>

#define BATCH 2
#define SEQ   2048
#define CH    768
#define HEADS 12
#define HDIM  64
#define ATT_SCALE 0.125f    // HDIM^-0.5
#define OA_SCALE 4096.0f
#define OA_INV   (1.0f / 4096.0f)

// ---------------- scratch (static device arrays; no cudaMalloc) -------------
__device__ float g_xpart[BATCH * 128 * CH];
__device__ float g_xmean[BATCH * CH];
__device__ float g_kavg[BATCH * HEADS * HDIM];
__device__ float g_u[BATCH * HEADS * CH];
__device__ float g_z[BATCH * HEADS * SEQ];
__device__ float g_attn[BATCH * HEADS * SEQ];

__device__ __half g_xhi[BATCH * SEQ * CH];
__device__ __half g_wvhi[CH * CH];
__device__ __half g_wphi[CH * CH];
__device__ __half g_vhi[BATCH * SEQ * CH];
__device__ __half g_oahi[BATCH * SEQ * CH];

// ---------------- fused: x -> fp16 hi + 16-row partial sums -----------------
__global__ void xhi_part_kernel(const float* __restrict__ x) {
    int b = blockIdx.y;
    int chunk = blockIdx.x;           // 0..127
    int c = threadIdx.x;              // 768 threads
    size_t base = ((size_t)b * SEQ + (size_t)chunk * 16) * CH + c;
    float s = 0.f;
    #pragma unroll
    for (int n = 0; n < 16; n++) {
        float v = x[base + (size_t)n * CH];
        s += v;
        g_xhi[base + (size_t)n * CH] = __float2half_rn(v);
    }
    g_xpart[(b * 128 + chunk) * CH + c] = s;
}

// ---------------- fused: Wv and Wp -> fp16 hi --------------------------------
__global__ void wvp_hi_kernel(const float* __restrict__ Wv,
                              const float* __restrict__ Wp, int n4) {
    int i = blockIdx.x * 256 + threadIdx.x;
    if (i >= n4) return;
    const float* src = blockIdx.y ? Wp : Wv;
    __half* dst = blockIdx.y ? g_wphi : g_wvhi;
    float4 v = ((const float4*)src)[i];
    ((__half2*)dst)[i * 2]     = __halves2half2(__float2half_rn(v.x), __float2half_rn(v.y));
    ((__half2*)dst)[i * 2 + 1] = __halves2half2(__float2half_rn(v.z), __float2half_rn(v.w));
}

// ---------------- xmean: reduce 128 partials (once) --------------------------
__global__ void xmean_kernel() {
    int b = blockIdx.x;
    int c = threadIdx.x;              // 768 threads
    float s = 0.f;
    #pragma unroll 16
    for (int k = 0; k < 128; k++) s += g_xpart[(b * 128 + k) * CH + c];
    g_xmean[b * CH + c] = s * (1.0f / SEQ);
}

// ---------------- kavg[b,h,d] = xmean[b,:] . Wk[h*64+d,:] --------------------
// grid BATCH*HEADS, block 256: 4 threads per d, shfl-reduce within quads.
__global__ void kavg_kernel(const float* __restrict__ Wk) {
    int b = blockIdx.x / HEADS;
    int h = blockIdx.x % HEADS;
    int d = threadIdx.x >> 2;
    int sub = threadIdx.x & 3;
    const float* wk = Wk + (size_t)(h * HDIM + d) * CH;
    const float* xm = g_xmean + b * CH;
    float s = 0.f;
    #pragma unroll 8
    for (int c = sub; c < CH; c += 4) s += xm[c] * wk[c];
    s += __shfl_down_sync(0xffffffffu, s, 2);
    s += __shfl_down_sync(0xffffffffu, s, 1);
    if (sub == 0) g_kavg[(b * HEADS + h) * HDIM + d] = s;
}

// ---------------- u[b,h,c] = SCALE * sum_d Wq[h*64+d,c] * kavg[b,h,d] -------
// grid (3, BATCH*HEADS), block 256: one output per thread, coalesced Wq reads.
__global__ void u2_kernel(const float* __restrict__ Wq) {
    int bh = blockIdx.y;
    int h = bh % HEADS;
    int c = blockIdx.x * 256 + threadIdx.x;
    __shared__ float ka[HDIM];
    if (threadIdx.x < HDIM) ka[threadIdx.x] = g_kavg[bh * HDIM + threadIdx.x];
    __syncthreads();
    const float* wq = Wq + (size_t)(h * HDIM) * CH + c;
    float s = 0.f;
    #pragma unroll 16
    for (int d = 0; d < HDIM; d++) s += wq[(size_t)d * CH] * ka[d];
    g_u[bh * CH + c] = s * ATT_SCALE;
}

// ---------------- z[b,h,n] = x[b,n,:] . u[b,h,:]  (8 rows/block) -------------
__global__ void __launch_bounds__(256) z_kernel(const float* __restrict__ x) {
    __shared__ float us[HEADS * CH];
    int b = blockIdx.y;
    int tid = threadIdx.x;
    for (int i = tid; i < HEADS * CH; i += 256) us[i] = g_u[b * HEADS * CH + i];
    __syncthreads();
    int wid = tid >> 5, lane = tid & 31;
    int n = blockIdx.x * 8 + wid;
    const float* xr = x + ((size_t)b * SEQ + n) * CH;
    float xv[24];
    #pragma unroll
    for (int i = 0; i < 24; i++) xv[i] = xr[lane + i * 32];
    #pragma unroll
    for (int h = 0; h < HEADS; h++) {
        const float* uh = us + h * CH;
        float s = 0.f;
        #pragma unroll
        for (int i = 0; i < 24; i++) s += xv[i] * uh[lane + i * 32];
        #pragma unroll
        for (int off = 16; off > 0; off >>= 1)
            s += __shfl_down_sync(0xffffffffu, s, off);
        if (lane == 0) g_z[(b * HEADS + h) * SEQ + n] = s;
    }
}

// ---------------- softmax over n per (b,h), fold 1/SEQ ------------------------
__global__ void softmax_kernel() {
    __shared__ float red[256];
    int base = blockIdx.x * SEQ;
    int tid = threadIdx.x;
    float v[8];
    float m = -1e30f;
    #pragma unroll
    for (int k = 0; k < 8; k++) {
        v[k] = g_z[base + tid + k * 256];
        m = fmaxf(m, v[k]);
    }
    red[tid] = m; __syncthreads();
    for (int s = 128; s > 0; s >>= 1) {
        if (tid < s) red[tid] = fmaxf(red[tid], red[tid + s]);
        __syncthreads();
    }
    m = red[0]; __syncthreads();
    float sum = 0.f;
    #pragma unroll
    for (int k = 0; k < 8; k++) { v[k] = __expf(v[k] - m); sum += v[k]; }
    red[tid] = sum; __syncthreads();
    for (int s = 128; s > 0; s >>= 1) {
        if (tid < s) red[tid] += red[tid + s];
        __syncthreads();
    }
    float inv = 1.0f / (red[0] * (float)SEQ);
    #pragma unroll
    for (int k = 0; k < 8; k++) g_attn[base + tid + k * 256] = v[k] * inv;
}

// ================= warp-MMA building blocks ==================================
__device__ __forceinline__ void mma16816(float* c, const uint32_t* a, const uint32_t* b) {
    asm volatile(
        "mma.sync.aligned.m16n8k16.row.col.f32.f16.f16.f32 "
        "{%0,%1,%2,%3}, {%4,%5,%6,%7}, {%8,%9}, {%0,%1,%2,%3};\n"
        : "+f"(c[0]), "+f"(c[1]), "+f"(c[2]), "+f"(c[3])
        : "r"(a[0]), "r"(a[1]), "r"(a[2]), "r"(a[3]), "r"(b[0]), "r"(b[1]));
}

__device__ __forceinline__ uint32_t smem_u32(const void* p) {
    uint32_t a;
    asm("{ .reg .u64 t; cvta.to.shared.u64 t, %1; cvt.u32.u64 %0, t; }"
        : "=r"(a) : "l"(p));
    return a;
}

__device__ __forceinline__ void ldmatrix_x4(uint32_t* r, uint32_t addr) {
    asm volatile(
        "ldmatrix.sync.aligned.m8n8.x4.shared.b16 {%0,%1,%2,%3}, [%4];"
        : "=r"(r[0]), "=r"(r[1]), "=r"(r[2]), "=r"(r[3]) : "r"(addr));
}

__device__ __forceinline__ void ldmatrix_x4_trans(uint32_t* r, uint32_t addr) {
    asm volatile(
        "ldmatrix.sync.aligned.m8n8.x4.trans.shared.b16 {%0,%1,%2,%3}, [%4];"
        : "=r"(r[0]), "=r"(r[1]), "=r"(r[2]), "=r"(r[3]) : "r"(addr));
}

__device__ __forceinline__ void cp_async16(uint32_t smem_addr, const void* gptr) {
    asm volatile("cp.async.cg.shared.global [%0], [%1], 16;"
                 :: "r"(smem_addr), "l"(gptr) : "memory");
}
#define CP_COMMIT()  asm volatile("cp.async.commit_group;" ::: "memory")
#define CP_WAIT(N)   asm volatile("cp.async.wait_group %0;" :: "n"(N) : "memory")

// ================= warp-MMA fp16 GEMM: 64x128 tile, 3 CTAs/SM ================
#define GEMM_STAGE_BYTES 15360
#define GEMM_SMEM_BYTES  (4 * GEMM_STAGE_BYTES)

template <int MODE>
__global__ void __launch_bounds__(256, 3) gemm_mma_kernel(
    const __half* __restrict__ Ahi,
    const __half* __restrict__ Bhi,
    const float* __restrict__ bias, float* __restrict__ out,
    __half* __restrict__ outhi, float outscale)
{
    extern __shared__ uint32_t dsm[];
    uint32_t sbase = smem_u32(dsm);

    int tid = threadIdx.x;
    int m0 = blockIdx.y * 64;
    int n0 = blockIdx.x * 128;
    int w = tid >> 5, lane = tid & 31;
    int wm = w >> 2, wn = w & 3;
    int g = lane >> 2, tig = lane & 3;

    float acc[2][4][4];
    #pragma unroll
    for (int mt = 0; mt < 2; mt++)
        #pragma unroll
        for (int nt = 0; nt < 4; nt++)
            #pragma unroll
            for (int r = 0; r < 4; r++) acc[mt][nt][r] = 0.f;

    int lrow = tid >> 2;
    int q = tid & 3;
    uint32_t sdstA  = (uint32_t)(lrow * 80 + q * 16);
    uint32_t sdstB0 = (uint32_t)(5120 + lrow * 80 + q * 16);
    uint32_t sdstB1 = (uint32_t)(5120 + (lrow + 64) * 80 + q * 16);
    size_t goffA  = (size_t)(m0 + lrow) * CH + q * 8;
    size_t goffB0 = (size_t)(n0 + lrow) * CH + q * 8;
    size_t goffB1 = (size_t)(n0 + lrow + 64) * CH + q * 8;

    int sub = lane >> 3, lr = lane & 7;
    int aRow = wm * 32 + ((sub & 1) << 3) + lr;
    int aKs  = sub >> 1;
    uint32_t aOffBase = (uint32_t)(aRow * 80 + aKs * 16);
    int bRow = wn * 32 + (((sub >> 1) & 1) << 3) + lr;
    int bKs  = sub & 1;
    uint32_t bOffBase = (uint32_t)(5120 + bRow * 80 + bKs * 16);

    const int NSTAGE = CH / 32;   // 24

    #pragma unroll
    for (int p = 0; p < 3; p++) {
        uint32_t st = sbase + (uint32_t)p * GEMM_STAGE_BYTES;
        size_t ka = (size_t)p * 32;
        cp_async16(st + sdstA,  Ahi + goffA + ka);
        cp_async16(st + sdstB0, Bhi + goffB0 + ka);
        cp_async16(st + sdstB1, Bhi + goffB1 + ka);
        CP_COMMIT();
    }

    for (int s = 0; s < NSTAGE; s++) {
        if (s + 2 < NSTAGE)      { CP_WAIT(2); }
        else if (s + 1 < NSTAGE) { CP_WAIT(1); }
        else                     { CP_WAIT(0); }
        __syncthreads();

        if (s + 3 < NSTAGE) {
            uint32_t st2 = sbase + (uint32_t)((s + 3) & 3) * GEMM_STAGE_BYTES;
            size_t ka = (size_t)(s + 3) * 32;
            cp_async16(st2 + sdstA,  Ahi + goffA + ka);
            cp_async16(st2 + sdstB0, Bhi + goffB0 + ka);
            cp_async16(st2 + sdstB1, Bhi + goffB1 + ka);
            CP_COMMIT();
        }

        uint32_t st = sbase + (uint32_t)(s & 3) * GEMM_STAGE_BYTES;

        #pragma unroll
        for (int kk = 0; kk < 2; kk++) {
            uint32_t kadd = (uint32_t)(kk * 32);
            uint32_t bh[4][2];
            #pragma unroll
            for (int np = 0; np < 2; np++) {
                uint32_t r4[4];
                ldmatrix_x4(r4, st + bOffBase + kadd + (uint32_t)(np * 16 * 80));
                bh[np * 2][0] = r4[0];      bh[np * 2][1] = r4[1];
                bh[np * 2 + 1][0] = r4[2];  bh[np * 2 + 1][1] = r4[3];
            }
            #pragma unroll
            for (int mt = 0; mt < 2; mt++) {
                uint32_t ah[4];
                ldmatrix_x4(ah, st + aOffBase + kadd + (uint32_t)(mt * 16 * 80));
                #pragma unroll
                for (int nt = 0; nt < 4; nt++)
                    mma16816(acc[mt][nt], ah, bh[nt]);
            }
        }
    }

    #pragma unroll
    for (int mt = 0; mt < 2; mt++) {
        int r = m0 + wm * 32 + mt * 16 + g;
        #pragma unroll
        for (int nt = 0; nt < 4; nt++) {
            int c = n0 + wn * 32 + nt * 8 + tig * 2;
            if (MODE == 1) {
                float2 v0, v1;
                v0.x = acc[mt][nt][0] * outscale + bias[c];
                v0.y = acc[mt][nt][1] * outscale + bias[c + 1];
                v1.x = acc[mt][nt][2] * outscale + bias[c];
                v1.y = acc[mt][nt][3] * outscale + bias[c + 1];
                *(float2*)(out + (size_t)r * CH + c)       = v0;
                *(float2*)(out + (size_t)(r + 8) * CH + c) = v1;
            } else {
                #pragma unroll
                for (int hr = 0; hr < 2; hr++) {
                    __half hx = __float2half_rn(acc[mt][nt][hr * 2]);
                    __half hy = __float2half_rn(acc[mt][nt][hr * 2 + 1]);
                    size_t idx = (size_t)(r + hr * 8) * CH + c;
                    *(__half2*)(outhi + idx) = __halves2half2(hx, hy);
                }
            }
        }
    }
}

// ================= circulant attention (1-product, cp.async 4-stage V) =======
#define CIRC_STAGE_BYTES 9216
#define CIRC_SMEM_BYTES (16384 + 4 * CIRC_STAGE_BYTES)

__global__ void __launch_bounds__(256, 2) circ_mma_kernel() {
    extern __shared__ __half dsmh[];
    __half* A2hi  = dsmh;
    __half* A2hiS = dsmh + 4096;
    uint32_t sVu32 = smem_u32(dsmh + 8192);

    int tid = threadIdx.x;
    int i0 = blockIdx.x * 128;
    int h  = blockIdx.y;
    int b  = blockIdx.z;
    int c0 = h * HDIM;
    int w = tid >> 5, lane = tid & 31;
    int wm = w >> 2, wn = w & 3;
    int g = lane >> 2, tig = lane & 3;

    const float* arow = g_attn + (size_t)(b * HEADS + h) * SEQ;
    for (int t = tid; t < SEQ; t += 256) {
        __half hi = __float2half_rn(arow[t] * OA_SCALE);
        A2hi[t] = hi;  A2hi[t + SEQ] = hi;
    }
    __syncthreads();
    for (int t = tid; t < 2 * SEQ - 1; t += 256) A2hiS[t] = A2hi[t + 1];
    if (tid == 0) A2hiS[2 * SEQ - 1] = __float2half_rn(0.f);

    int ob = SEQ + 2 * tig - (i0 + wm * 64 + g);
    int par = ob & 1;
    const uint32_t* PhiBase = (const uint32_t*)(par ? A2hiS : A2hi) + ((ob - par) >> 1);

    int vrow = tid >> 3, vcg = tid & 7;
    const __half* gvh = g_vhi + ((size_t)b * SEQ + vrow) * CH + c0 + vcg * 8;
    uint32_t svoA = (uint32_t)((vrow * 72 + vcg * 8) * 2);
    uint32_t svoB = (uint32_t)(((vrow + 32) * 72 + vcg * 8) * 2);

    int mrow = ((lane >> 3) & 1) * 8 + (lane & 7);
    int ncol = wn * 16 + (lane >> 4) * 8;
    uint32_t svAddrPart = (uint32_t)(mrow * 144 + ncol * 2);

    float acc[4][2][4];
    #pragma unroll
    for (int mt = 0; mt < 4; mt++)
        #pragma unroll
        for (int nt = 0; nt < 2; nt++)
            #pragma unroll
            for (int r = 0; r < 4; r++) acc[mt][nt][r] = 0.f;

    #pragma unroll
    for (int p = 0; p < 3; p++) {
        uint32_t st = sVu32 + (uint32_t)p * CIRC_STAGE_BYTES;
        size_t adv = (size_t)p * 64 * CH;
        cp_async16(st + svoA, gvh + adv);
        cp_async16(st + svoB, gvh + adv + 32 * CH);
        CP_COMMIT();
    }
    __syncthreads();

    const int NCHUNK = SEQ / 64;   // 32
    for (int c = 0; c < NCHUNK; c++) {
        if (c + 2 < NCHUNK)      { CP_WAIT(2); }
        else if (c + 1 < NCHUNK) { CP_WAIT(1); }
        else                     { CP_WAIT(0); }
        __syncthreads();

        if (c + 3 < NCHUNK) {
            uint32_t st = sVu32 + (uint32_t)((c + 3) & 3) * CIRC_STAGE_BYTES;
            size_t adv = (size_t)(c + 3) * 64 * CH;
            cp_async16(st + svoA, gvh + adv);
            cp_async16(st + svoB, gvh + adv + 32 * CH);
            CP_COMMIT();
        }

        const uint32_t* Phi = PhiBase + 32 * c;
        uint32_t ehi[7], fhi[8];
        #pragma unroll
        for (int t = 0; t < 7; t++) ehi[t] = Phi[8 * t - 24];
        #pragma unroll
        for (int t = 0; t < 8; t++) fhi[t] = Phi[8 * t - 28];

        uint32_t sVAddr = sVu32 + (uint32_t)(c & 3) * CIRC_STAGE_BYTES + svAddrPart;

        #pragma unroll
        for (int kk = 0; kk < 4; kk++) {
            uint32_t bh[4];
            ldmatrix_x4_trans(bh, sVAddr + kk * 2304u);
            #pragma unroll
            for (int mt = 0; mt < 4; mt++) {
                int d3 = kk - mt + 3;
                uint32_t ah[4] = {ehi[d3], fhi[d3], fhi[d3 + 1], ehi[d3]};
                mma16816(acc[mt][0], ah, bh);
                uint32_t bh1[2] = {bh[2], bh[3]};
                mma16816(acc[mt][1], ah, bh1);
            }
        }
    }

    #pragma unroll
    for (int mt = 0; mt < 4; mt++) {
        int r = i0 + wm * 64 + mt * 16 + g;
        #pragma unroll
        for (int nt = 0; nt < 2; nt++) {
            int cc = c0 + wn * 16 + nt * 8 + tig * 2;
            #pragma unroll
            for (int hr = 0; hr < 2; hr++) {
                __half hx = __float2half_rn(acc[mt][nt][hr * 2]);
                __half hy = __float2half_rn(acc[mt][nt][hr * 2 + 1]);
                size_t idx = (size_t)(b * SEQ + r + hr * 8) * CH + cc;
                *(__half2*)(g_oahi + idx) = __halves2half2(hx, hy);
            }
        }
    }
}

// ---------------- launch ------------------------------------------------------
extern "C" void kernel_launch(void* const* d_in, const int* in_sizes, int n_in,
                              void* d_out, int out_size) {
    const float* x  = (const float*)d_in[0];
    const float* Wq = (const float*)d_in[1];
    const float* Wk = (const float*)d_in[2];
    const float* Wv = (const float*)d_in[3];
    const float* Wp = (const float*)d_in[4];
    const float* bp = (const float*)d_in[5];
    float* out = (float*)d_out;

    __half* dxhi; cudaGetSymbolAddress((void**)&dxhi,  g_xhi);
    __half* dvhi; cudaGetSymbolAddress((void**)&dvhi,  g_wvhi);
    __half* dphi; cudaGetSymbolAddress((void**)&dphi,  g_wphi);
    __half* dVhi; cudaGetSymbolAddress((void**)&dVhi,  g_vhi);
    __half* dohi; cudaGetSymbolAddress((void**)&dohi,  g_oahi);

    static cudaStream_t s1 = nullptr;
    static cudaEvent_t evA = nullptr, evV = nullptr;
    if (!s1) {
        cudaStreamCreateWithFlags(&s1, cudaStreamNonBlocking);
        cudaEventCreateWithFlags(&evA, cudaEventDisableTiming);
        cudaEventCreateWithFlags(&evV, cudaEventDisableTiming);
        cudaFuncSetAttribute(circ_mma_kernel,
                             cudaFuncAttributeMaxDynamicSharedMemorySize, CIRC_SMEM_BYTES);
        cudaFuncSetAttribute(gemm_mma_kernel<1>,
                             cudaFuncAttributeMaxDynamicSharedMemorySize, GEMM_SMEM_BYTES);
        cudaFuncSetAttribute(gemm_mma_kernel<2>,
                             cudaFuncAttributeMaxDynamicSharedMemorySize, GEMM_SMEM_BYTES);
    }

    int n4w = CH * CH / 4;
    // main stream: conversions
    wvp_hi_kernel<<<dim3((n4w + 255) / 256, 2), 256>>>(Wv, Wp, n4w);
    xhi_part_kernel<<<dim3(128, BATCH), CH>>>(x);
    cudaEventRecord(evA, 0);

    // side stream: V projection (needs xhi + wvhi)
    cudaStreamWaitEvent(s1, evA, 0);
    gemm_mma_kernel<2><<<dim3(CH / 128, (BATCH * SEQ) / 64), 256, GEMM_SMEM_BYTES, s1>>>(
        dxhi, dvhi, nullptr, nullptr, dVhi, 1.0f);
    cudaEventRecord(evV, s1);

    // main stream (concurrent with gemm_V): xmean -> kavg -> u -> z -> softmax
    xmean_kernel<<<BATCH, CH>>>();
    kavg_kernel<<<BATCH * HEADS, 256>>>(Wk);
    u2_kernel<<<dim3(CH / 256, BATCH * HEADS), 256>>>(Wq);
    z_kernel<<<dim3(SEQ / 8, BATCH), 256>>>(x);
    softmax_kernel<<<BATCH * HEADS, 256>>>();

    // join: circ needs V and attn
    cudaStreamWaitEvent(0, evV, 0);
    circ_mma_kernel<<<dim3(SEQ / 128, HEADS, BATCH), 256, CIRC_SMEM_BYTES>>>();
    gemm_mma_kernel<1><<<dim3(CH / 128, (BATCH * SEQ) / 64), 256, GEMM_SMEM_BYTES>>>(
        dohi, dphi, bp, out, nullptr, OA_INV);
}

// round 16
// speedup vs baseline: 4.1662x; 1.0896x over previous
#include <cuda_runtime.h>
#include <cuda_fp16.h>
#include <cstdint>

#define BATCH 2
#define SEQ   2048
#define CH    768
#define HEADS 12
#define HDIM  64
#define ATT_SCALE 0.125f    // HDIM^-0.5
#define OA_SCALE 4096.0f
#define OA_INV   (1.0f / 4096.0f)

// ---------------- scratch (static device arrays; no cudaMalloc) -------------
__device__ float g_xpart[BATCH * 128 * CH];
__device__ float g_xmean2[BATCH * 8 * CH];
__device__ float g_kavg[BATCH * HEADS * HDIM];
__device__ float g_u[BATCH * HEADS * CH];
__device__ float g_z[BATCH * HEADS * SEQ];
__device__ float g_attn[BATCH * HEADS * SEQ];

__device__ __half g_xhi[BATCH * SEQ * CH];
__device__ __half g_wvhi[CH * CH];
__device__ __half g_wphi[CH * CH];
__device__ __half g_vhi[BATCH * SEQ * CH];
__device__ __half g_oahi[BATCH * SEQ * CH];

// ---------------- fused: x -> fp16 hi + 16-row partial sums -----------------
__global__ void xhi_part_kernel(const float* __restrict__ x) {
    int b = blockIdx.y;
    int chunk = blockIdx.x;           // 0..127
    int c = threadIdx.x;              // 768 threads
    size_t base = ((size_t)b * SEQ + (size_t)chunk * 16) * CH + c;
    float s = 0.f;
    #pragma unroll
    for (int n = 0; n < 16; n++) {
        float v = x[base + (size_t)n * CH];
        s += v;
        g_xhi[base + (size_t)n * CH] = __float2half_rn(v);
    }
    g_xpart[(b * 128 + chunk) * CH + c] = s;
}

// ---------------- fused: Wv and Wp -> fp16 hi --------------------------------
__global__ void wvp_hi_kernel(const float* __restrict__ Wv,
                              const float* __restrict__ Wp, int n4) {
    int i = blockIdx.x * 256 + threadIdx.x;
    if (i >= n4) return;
    const float* src = blockIdx.y ? Wp : Wv;
    __half* dst = blockIdx.y ? g_wphi : g_wvhi;
    float4 v = ((const float4*)src)[i];
    ((__half2*)dst)[i * 2]     = __halves2half2(__float2half_rn(v.x), __float2half_rn(v.y));
    ((__half2*)dst)[i * 2 + 1] = __halves2half2(__float2half_rn(v.z), __float2half_rn(v.w));
}

// ---------------- xmean stage 2: 16 partials -> 1 sub-partial ---------------
// grid (8, BATCH), block 768.
__global__ void xmean2_kernel() {
    int b = blockIdx.y;
    int grp = blockIdx.x;             // 0..7
    int c = threadIdx.x;
    float s = 0.f;
    #pragma unroll
    for (int k = 0; k < 16; k++)
        s += g_xpart[(b * 128 + grp * 16 + k) * CH + c];
    g_xmean2[(b * 8 + grp) * CH + c] = s;
}

// ---------------- kavg[b,h,d] = xmean[b,:] . Wk[h*64+d,:] --------------------
// final 8-way xmean combine done cooperatively into smem.
__global__ void kavg_kernel(const float* __restrict__ Wk) {
    int b = blockIdx.x / HEADS;
    int h = blockIdx.x % HEADS;
    __shared__ float xm[CH];
    for (int c = threadIdx.x; c < CH; c += 256) {
        float s = 0.f;
        #pragma unroll
        for (int grp = 0; grp < 8; grp++)
            s += g_xmean2[(b * 8 + grp) * CH + c];
        xm[c] = s * (1.0f / SEQ);
    }
    __syncthreads();
    int d = threadIdx.x >> 2;
    int sub = threadIdx.x & 3;
    const float* wk = Wk + (size_t)(h * HDIM + d) * CH;
    float s = 0.f;
    #pragma unroll 8
    for (int c = sub; c < CH; c += 4) s += xm[c] * wk[c];
    s += __shfl_down_sync(0xffffffffu, s, 2);
    s += __shfl_down_sync(0xffffffffu, s, 1);
    if (sub == 0) g_kavg[(b * HEADS + h) * HDIM + d] = s;
}

// ---------------- u[b,h,c] = SCALE * sum_d Wq[h*64+d,c] * kavg[b,h,d] -------
__global__ void u2_kernel(const float* __restrict__ Wq) {
    int bh = blockIdx.y;
    int h = bh % HEADS;
    int c = blockIdx.x * 256 + threadIdx.x;
    __shared__ float ka[HDIM];
    if (threadIdx.x < HDIM) ka[threadIdx.x] = g_kavg[bh * HDIM + threadIdx.x];
    __syncthreads();
    const float* wq = Wq + (size_t)(h * HDIM) * CH + c;
    float s = 0.f;
    #pragma unroll 16
    for (int d = 0; d < HDIM; d++) s += wq[(size_t)d * CH] * ka[d];
    g_u[bh * CH + c] = s * ATT_SCALE;
}

// ---------------- z[b,h,n] = x[b,n,:] . u[b,h,:]  (8 rows/block) -------------
__global__ void __launch_bounds__(256) z_kernel(const float* __restrict__ x) {
    __shared__ float us[HEADS * CH];
    int b = blockIdx.y;
    int tid = threadIdx.x;
    for (int i = tid; i < HEADS * CH; i += 256) us[i] = g_u[b * HEADS * CH + i];
    __syncthreads();
    int wid = tid >> 5, lane = tid & 31;
    int n = blockIdx.x * 8 + wid;
    const float* xr = x + ((size_t)b * SEQ + n) * CH;
    float xv[24];
    #pragma unroll
    for (int i = 0; i < 24; i++) xv[i] = xr[lane + i * 32];
    #pragma unroll
    for (int h = 0; h < HEADS; h++) {
        const float* uh = us + h * CH;
        float s = 0.f;
        #pragma unroll
        for (int i = 0; i < 24; i++) s += xv[i] * uh[lane + i * 32];
        #pragma unroll
        for (int off = 16; off > 0; off >>= 1)
            s += __shfl_down_sync(0xffffffffu, s, off);
        if (lane == 0) g_z[(b * HEADS + h) * SEQ + n] = s;
    }
}

// ---------------- softmax over n per (b,h), fold 1/SEQ ------------------------
__global__ void softmax_kernel() {
    __shared__ float red[256];
    int base = blockIdx.x * SEQ;
    int tid = threadIdx.x;
    float v[8];
    float m = -1e30f;
    #pragma unroll
    for (int k = 0; k < 8; k++) {
        v[k] = g_z[base + tid + k * 256];
        m = fmaxf(m, v[k]);
    }
    red[tid] = m; __syncthreads();
    for (int s = 128; s > 0; s >>= 1) {
        if (tid < s) red[tid] = fmaxf(red[tid], red[tid + s]);
        __syncthreads();
    }
    m = red[0]; __syncthreads();
    float sum = 0.f;
    #pragma unroll
    for (int k = 0; k < 8; k++) { v[k] = __expf(v[k] - m); sum += v[k]; }
    red[tid] = sum; __syncthreads();
    for (int s = 128; s > 0; s >>= 1) {
        if (tid < s) red[tid] += red[tid + s];
        __syncthreads();
    }
    float inv = 1.0f / (red[0] * (float)SEQ);
    #pragma unroll
    for (int k = 0; k < 8; k++) g_attn[base + tid + k * 256] = v[k] * inv;
}

// ================= warp-MMA building blocks ==================================
__device__ __forceinline__ void mma16816(float* c, const uint32_t* a, const uint32_t* b) {
    asm volatile(
        "mma.sync.aligned.m16n8k16.row.col.f32.f16.f16.f32 "
        "{%0,%1,%2,%3}, {%4,%5,%6,%7}, {%8,%9}, {%0,%1,%2,%3};\n"
        : "+f"(c[0]), "+f"(c[1]), "+f"(c[2]), "+f"(c[3])
        : "r"(a[0]), "r"(a[1]), "r"(a[2]), "r"(a[3]), "r"(b[0]), "r"(b[1]));
}

__device__ __forceinline__ uint32_t smem_u32(const void* p) {
    uint32_t a;
    asm("{ .reg .u64 t; cvta.to.shared.u64 t, %1; cvt.u32.u64 %0, t; }"
        : "=r"(a) : "l"(p));
    return a;
}

__device__ __forceinline__ void ldmatrix_x4(uint32_t* r, uint32_t addr) {
    asm volatile(
        "ldmatrix.sync.aligned.m8n8.x4.shared.b16 {%0,%1,%2,%3}, [%4];"
        : "=r"(r[0]), "=r"(r[1]), "=r"(r[2]), "=r"(r[3]) : "r"(addr));
}

__device__ __forceinline__ void ldmatrix_x4_trans(uint32_t* r, uint32_t addr) {
    asm volatile(
        "ldmatrix.sync.aligned.m8n8.x4.trans.shared.b16 {%0,%1,%2,%3}, [%4];"
        : "=r"(r[0]), "=r"(r[1]), "=r"(r[2]), "=r"(r[3]) : "r"(addr));
}

__device__ __forceinline__ void cp_async16(uint32_t smem_addr, const void* gptr) {
    asm volatile("cp.async.cg.shared.global [%0], [%1], 16;"
                 :: "r"(smem_addr), "l"(gptr) : "memory");
}
#define CP_COMMIT()  asm volatile("cp.async.commit_group;" ::: "memory")
#define CP_WAIT(N)   asm volatile("cp.async.wait_group %0;" :: "n"(N) : "memory")

// ================= warp-MMA fp16 GEMM: 64x128 tile, 3 CTAs/SM ================
#define GEMM_STAGE_BYTES 15360
#define GEMM_SMEM_BYTES  (4 * GEMM_STAGE_BYTES)

template <int MODE>
__global__ void __launch_bounds__(256, 3) gemm_mma_kernel(
    const __half* __restrict__ Ahi,
    const __half* __restrict__ Bhi,
    const float* __restrict__ bias, float* __restrict__ out,
    __half* __restrict__ outhi, float outscale)
{
    extern __shared__ uint32_t dsm[];
    uint32_t sbase = smem_u32(dsm);

    int tid = threadIdx.x;
    int m0 = blockIdx.y * 64;
    int n0 = blockIdx.x * 128;
    int w = tid >> 5, lane = tid & 31;
    int wm = w >> 2, wn = w & 3;
    int g = lane >> 2, tig = lane & 3;

    float acc[2][4][4];
    #pragma unroll
    for (int mt = 0; mt < 2; mt++)
        #pragma unroll
        for (int nt = 0; nt < 4; nt++)
            #pragma unroll
            for (int r = 0; r < 4; r++) acc[mt][nt][r] = 0.f;

    int lrow = tid >> 2;
    int q = tid & 3;
    uint32_t sdstA  = (uint32_t)(lrow * 80 + q * 16);
    uint32_t sdstB0 = (uint32_t)(5120 + lrow * 80 + q * 16);
    uint32_t sdstB1 = (uint32_t)(5120 + (lrow + 64) * 80 + q * 16);
    size_t goffA  = (size_t)(m0 + lrow) * CH + q * 8;
    size_t goffB0 = (size_t)(n0 + lrow) * CH + q * 8;
    size_t goffB1 = (size_t)(n0 + lrow + 64) * CH + q * 8;

    int sub = lane >> 3, lr = lane & 7;
    int aRow = wm * 32 + ((sub & 1) << 3) + lr;
    int aKs  = sub >> 1;
    uint32_t aOffBase = (uint32_t)(aRow * 80 + aKs * 16);
    int bRow = wn * 32 + (((sub >> 1) & 1) << 3) + lr;
    int bKs  = sub & 1;
    uint32_t bOffBase = (uint32_t)(5120 + bRow * 80 + bKs * 16);

    const int NSTAGE = CH / 32;   // 24

    #pragma unroll
    for (int p = 0; p < 3; p++) {
        uint32_t st = sbase + (uint32_t)p * GEMM_STAGE_BYTES;
        size_t ka = (size_t)p * 32;
        cp_async16(st + sdstA,  Ahi + goffA + ka);
        cp_async16(st + sdstB0, Bhi + goffB0 + ka);
        cp_async16(st + sdstB1, Bhi + goffB1 + ka);
        CP_COMMIT();
    }

    for (int s = 0; s < NSTAGE; s++) {
        if (s + 2 < NSTAGE)      { CP_WAIT(2); }
        else if (s + 1 < NSTAGE) { CP_WAIT(1); }
        else                     { CP_WAIT(0); }
        __syncthreads();

        if (s + 3 < NSTAGE) {
            uint32_t st2 = sbase + (uint32_t)((s + 3) & 3) * GEMM_STAGE_BYTES;
            size_t ka = (size_t)(s + 3) * 32;
            cp_async16(st2 + sdstA,  Ahi + goffA + ka);
            cp_async16(st2 + sdstB0, Bhi + goffB0 + ka);
            cp_async16(st2 + sdstB1, Bhi + goffB1 + ka);
            CP_COMMIT();
        }

        uint32_t st = sbase + (uint32_t)(s & 3) * GEMM_STAGE_BYTES;

        #pragma unroll
        for (int kk = 0; kk < 2; kk++) {
            uint32_t kadd = (uint32_t)(kk * 32);
            uint32_t bh[4][2];
            #pragma unroll
            for (int np = 0; np < 2; np++) {
                uint32_t r4[4];
                ldmatrix_x4(r4, st + bOffBase + kadd + (uint32_t)(np * 16 * 80));
                bh[np * 2][0] = r4[0];      bh[np * 2][1] = r4[1];
                bh[np * 2 + 1][0] = r4[2];  bh[np * 2 + 1][1] = r4[3];
            }
            #pragma unroll
            for (int mt = 0; mt < 2; mt++) {
                uint32_t ah[4];
                ldmatrix_x4(ah, st + aOffBase + kadd + (uint32_t)(mt * 16 * 80));
                #pragma unroll
                for (int nt = 0; nt < 4; nt++)
                    mma16816(acc[mt][nt], ah, bh[nt]);
            }
        }
    }

    #pragma unroll
    for (int mt = 0; mt < 2; mt++) {
        int r = m0 + wm * 32 + mt * 16 + g;
        #pragma unroll
        for (int nt = 0; nt < 4; nt++) {
            int c = n0 + wn * 32 + nt * 8 + tig * 2;
            if (MODE == 1) {
                float2 v0, v1;
                v0.x = acc[mt][nt][0] * outscale + bias[c];
                v0.y = acc[mt][nt][1] * outscale + bias[c + 1];
                v1.x = acc[mt][nt][2] * outscale + bias[c];
                v1.y = acc[mt][nt][3] * outscale + bias[c + 1];
                *(float2*)(out + (size_t)r * CH + c)       = v0;
                *(float2*)(out + (size_t)(r + 8) * CH + c) = v1;
            } else {
                #pragma unroll
                for (int hr = 0; hr < 2; hr++) {
                    __half hx = __float2half_rn(acc[mt][nt][hr * 2]);
                    __half hy = __float2half_rn(acc[mt][nt][hr * 2 + 1]);
                    size_t idx = (size_t)(r + hr * 8) * CH + c;
                    *(__half2*)(outhi + idx) = __halves2half2(hx, hy);
                }
            }
        }
    }
}

// ================= circulant attention (1-product, cp.async 4-stage V) =======
#define CIRC_STAGE_BYTES 9216
#define CIRC_SMEM_BYTES (16384 + 4 * CIRC_STAGE_BYTES)

__global__ void __launch_bounds__(256, 2) circ_mma_kernel() {
    extern __shared__ __half dsmh[];
    __half* A2hi  = dsmh;
    __half* A2hiS = dsmh + 4096;
    uint32_t sVu32 = smem_u32(dsmh + 8192);

    int tid = threadIdx.x;
    int i0 = blockIdx.x * 128;
    int h  = blockIdx.y;
    int b  = blockIdx.z;
    int c0 = h * HDIM;
    int w = tid >> 5, lane = tid & 31;
    int wm = w >> 2, wn = w & 3;
    int g = lane >> 2, tig = lane & 3;

    const float* arow = g_attn + (size_t)(b * HEADS + h) * SEQ;
    for (int t = tid; t < SEQ; t += 256) {
        __half hi = __float2half_rn(arow[t] * OA_SCALE);
        A2hi[t] = hi;  A2hi[t + SEQ] = hi;
    }
    __syncthreads();
    for (int t = tid; t < 2 * SEQ - 1; t += 256) A2hiS[t] = A2hi[t + 1];
    if (tid == 0) A2hiS[2 * SEQ - 1] = __float2half_rn(0.f);

    int ob = SEQ + 2 * tig - (i0 + wm * 64 + g);
    int par = ob & 1;
    const uint32_t* PhiBase = (const uint32_t*)(par ? A2hiS : A2hi) + ((ob - par) >> 1);

    int vrow = tid >> 3, vcg = tid & 7;
    const __half* gvh = g_vhi + ((size_t)b * SEQ + vrow) * CH + c0 + vcg * 8;
    uint32_t svoA = (uint32_t)((vrow * 72 + vcg * 8) * 2);
    uint32_t svoB = (uint32_t)(((vrow + 32) * 72 + vcg * 8) * 2);

    int mrow = ((lane >> 3) & 1) * 8 + (lane & 7);
    int ncol = wn * 16 + (lane >> 4) * 8;
    uint32_t svAddrPart = (uint32_t)(mrow * 144 + ncol * 2);

    float acc[4][2][4];
    #pragma unroll
    for (int mt = 0; mt < 4; mt++)
        #pragma unroll
        for (int nt = 0; nt < 2; nt++)
            #pragma unroll
            for (int r = 0; r < 4; r++) acc[mt][nt][r] = 0.f;

    #pragma unroll
    for (int p = 0; p < 3; p++) {
        uint32_t st = sVu32 + (uint32_t)p * CIRC_STAGE_BYTES;
        size_t adv = (size_t)p * 64 * CH;
        cp_async16(st + svoA, gvh + adv);
        cp_async16(st + svoB, gvh + adv + 32 * CH);
        CP_COMMIT();
    }
    __syncthreads();

    const int NCHUNK = SEQ / 64;   // 32
    for (int c = 0; c < NCHUNK; c++) {
        if (c + 2 < NCHUNK)      { CP_WAIT(2); }
        else if (c + 1 < NCHUNK) { CP_WAIT(1); }
        else                     { CP_WAIT(0); }
        __syncthreads();

        if (c + 3 < NCHUNK) {
            uint32_t st = sVu32 + (uint32_t)((c + 3) & 3) * CIRC_STAGE_BYTES;
            size_t adv = (size_t)(c + 3) * 64 * CH;
            cp_async16(st + svoA, gvh + adv);
            cp_async16(st + svoB, gvh + adv + 32 * CH);
            CP_COMMIT();
        }

        const uint32_t* Phi = PhiBase + 32 * c;
        uint32_t ehi[7], fhi[8];
        #pragma unroll
        for (int t = 0; t < 7; t++) ehi[t] = Phi[8 * t - 24];
        #pragma unroll
        for (int t = 0; t < 8; t++) fhi[t] = Phi[8 * t - 28];

        uint32_t sVAddr = sVu32 + (uint32_t)(c & 3) * CIRC_STAGE_BYTES + svAddrPart;

        #pragma unroll
        for (int kk = 0; kk < 4; kk++) {
            uint32_t bh[4];
            ldmatrix_x4_trans(bh, sVAddr + kk * 2304u);
            #pragma unroll
            for (int mt = 0; mt < 4; mt++) {
                int d3 = kk - mt + 3;
                uint32_t ah[4] = {ehi[d3], fhi[d3], fhi[d3 + 1], ehi[d3]};
                mma16816(acc[mt][0], ah, bh);
                uint32_t bh1[2] = {bh[2], bh[3]};
                mma16816(acc[mt][1], ah, bh1);
            }
        }
    }

    #pragma unroll
    for (int mt = 0; mt < 4; mt++) {
        int r = i0 + wm * 64 + mt * 16 + g;
        #pragma unroll
        for (int nt = 0; nt < 2; nt++) {
            int cc = c0 + wn * 16 + nt * 8 + tig * 2;
            #pragma unroll
            for (int hr = 0; hr < 2; hr++) {
                __half hx = __float2half_rn(acc[mt][nt][hr * 2]);
                __half hy = __float2half_rn(acc[mt][nt][hr * 2 + 1]);
                size_t idx = (size_t)(b * SEQ + r + hr * 8) * CH + cc;
                *(__half2*)(g_oahi + idx) = __halves2half2(hx, hy);
            }
        }
    }
}

// ---------------- launch ------------------------------------------------------
extern "C" void kernel_launch(void* const* d_in, const int* in_sizes, int n_in,
                              void* d_out, int out_size) {
    const float* x  = (const float*)d_in[0];
    const float* Wq = (const float*)d_in[1];
    const float* Wk = (const float*)d_in[2];
    const float* Wv = (const float*)d_in[3];
    const float* Wp = (const float*)d_in[4];
    const float* bp = (const float*)d_in[5];
    float* out = (float*)d_out;

    __half* dxhi; cudaGetSymbolAddress((void**)&dxhi,  g_xhi);
    __half* dvhi; cudaGetSymbolAddress((void**)&dvhi,  g_wvhi);
    __half* dphi; cudaGetSymbolAddress((void**)&dphi,  g_wphi);
    __half* dVhi; cudaGetSymbolAddress((void**)&dVhi,  g_vhi);
    __half* dohi; cudaGetSymbolAddress((void**)&dohi,  g_oahi);

    static cudaStream_t s1 = nullptr;
    static cudaEvent_t evX = nullptr, evV = nullptr;
    if (!s1) {
        cudaStreamCreateWithFlags(&s1, cudaStreamNonBlocking);
        cudaEventCreateWithFlags(&evX, cudaEventDisableTiming);
        cudaEventCreateWithFlags(&evV, cudaEventDisableTiming);
        cudaFuncSetAttribute(circ_mma_kernel,
                             cudaFuncAttributeMaxDynamicSharedMemorySize, CIRC_SMEM_BYTES);
        cudaFuncSetAttribute(gemm_mma_kernel<1>,
                             cudaFuncAttributeMaxDynamicSharedMemorySize, GEMM_SMEM_BYTES);
        cudaFuncSetAttribute(gemm_mma_kernel<2>,
                             cudaFuncAttributeMaxDynamicSharedMemorySize, GEMM_SMEM_BYTES);
    }

    int n4w = CH * CH / 4;
    // side stream: weight conversions (concurrent with xhi_part)
    wvp_hi_kernel<<<dim3((n4w + 255) / 256, 2), 256, 0, s1>>>(Wv, Wp, n4w);
    // main stream: x conversion + partials
    xhi_part_kernel<<<dim3(128, BATCH), CH>>>(x);
    cudaEventRecord(evX, 0);

    // side stream: V projection after both conversions
    cudaStreamWaitEvent(s1, evX, 0);
    gemm_mma_kernel<2><<<dim3(CH / 128, (BATCH * SEQ) / 64), 256, GEMM_SMEM_BYTES, s1>>>(
        dxhi, dvhi, nullptr, nullptr, dVhi, 1.0f);
    cudaEventRecord(evV, s1);

    // main stream (concurrent with gemm_V): u-chain
    xmean2_kernel<<<dim3(8, BATCH), CH>>>();
    kavg_kernel<<<BATCH * HEADS, 256>>>(Wk);
    u2_kernel<<<dim3(CH / 256, BATCH * HEADS), 256>>>(Wq);
    z_kernel<<<dim3(SEQ / 8, BATCH), 256>>>(x);
    softmax_kernel<<<BATCH * HEADS, 256>>>();

    // join: circ needs V and attn
    cudaStreamWaitEvent(0, evV, 0);
    circ_mma_kernel<<<dim3(SEQ / 128, HEADS, BATCH), 256, CIRC_SMEM_BYTES>>>();
    gemm_mma_kernel<1><<<dim3(CH / 128, (BATCH * SEQ) / 64), 256, GEMM_SMEM_BYTES>>>(
        dohi, dphi, bp, out, nullptr, OA_INV);
}